// round 5
// baseline (speedup 1.0000x reference)
#include <cuda_runtime.h>
#include <cuda_bf16.h>
#include <cstdint>
#include <math.h>

typedef __nv_bfloat16 bf16;

// ---------------- dims ----------------
static const int cB  = 8;
static const int cL  = 1152;      // T*W
static const int cD  = 512;
static const int cDI = 1024;
static const int cS  = 64;
static const int cDFF= 2048;
static const int cM  = 9216;      // B*L

// ---------------- fp32 workspaces ----------------
__device__ float g_q   [cM*cD];
__device__ float g_kk  [cM*cD];
__device__ float g_vv  [cM*cD];
__device__ float g_ao  [cM*cD];
__device__ float g_attn[cM*cD];
__device__ float g_xz  [cM*2*cDI];
__device__ float g_u   [cM*cDI];
__device__ float g_xdbc[cM*160];
__device__ float g_dlt [cM*cDI];
__device__ float g_y   [cM*cDI];
__device__ float g_mmb [cM*cD];
__device__ float g_h   [cM*cD];
__device__ float g_hn  [cM*cD];
__device__ float g_ff1 [cM*cDFF];

// ---------------- bf16 split-3 buffers (activations) ----------------
__device__ bf16 gx3   [cM*1536];
__device__ bf16 gao3  [cM*1536];
__device__ bf16 gu3   [cM*3072];
__device__ bf16 gxdbc3[cM*128];
__device__ bf16 gy3   [cM*3072];
__device__ bf16 ghn3  [cM*1536];
__device__ bf16 gff13 [cM*6144];

// ---------------- bf16 split-3 weights ----------------
__device__ bf16 wq3  [512*1536];
__device__ bf16 wk3  [512*1536];
__device__ bf16 wv3  [512*1536];
__device__ bf16 wo3  [512*1536];
__device__ bf16 win3 [2048*1536];
__device__ bf16 wxp3 [160*3072];
__device__ bf16 wdt3 [1024*128];
__device__ bf16 wout3[512*3072];
__device__ bf16 wff13[2048*1536];
__device__ bf16 wff23[512*6144];

// ---------------- f32x2 helpers ----------------
__device__ __forceinline__ void fma2(unsigned long long &d, unsigned long long a, unsigned long long b){
    asm("fma.rn.f32x2 %0, %1, %2, %0;" : "+l"(d) : "l"(a), "l"(b));
}
union F4U { float4 f4; unsigned long long l[2]; float f[4]; };

// ---------------- epilogue math ----------------
__device__ __forceinline__ float softplus_f(float v){
    return fmaxf(v, 0.0f) + log1pf(__expf(-fabsf(v)));
}
__device__ __forceinline__ float gelu_f(float v){
    return 0.5f * v * (1.0f + erff(v * 0.70710678118654752f));
}

// ---------------- PTX helpers ----------------
__device__ __forceinline__ uint32_t smem_u32(const void* p){
    uint32_t a;
    asm("{ .reg .u64 t; cvta.to.shared.u64 t, %1; cvt.u32.u64 %0, t; }" : "=r"(a) : "l"(p));
    return a;
}
__device__ __forceinline__ void cp16(uint32_t dst, const void* src){
    asm volatile("cp.async.cg.shared.global [%0], [%1], 16;" :: "r"(dst), "l"(src));
}
__device__ __forceinline__ void ldsm4(uint32_t &r0, uint32_t &r1, uint32_t &r2, uint32_t &r3, uint32_t addr){
    asm volatile("ldmatrix.sync.aligned.m8n8.x4.shared.b16 {%0,%1,%2,%3}, [%4];"
        : "=r"(r0), "=r"(r1), "=r"(r2), "=r"(r3) : "r"(addr));
}
__device__ __forceinline__ void mma16816(float* c, uint32_t a0, uint32_t a1, uint32_t a2, uint32_t a3,
                                         uint32_t b0, uint32_t b1){
    asm volatile("mma.sync.aligned.m16n8k16.row.col.f32.bf16.bf16.f32 "
        "{%0,%1,%2,%3}, {%4,%5,%6,%7}, {%8,%9}, {%0,%1,%2,%3};"
        : "+f"(c[0]), "+f"(c[1]), "+f"(c[2]), "+f"(c[3])
        : "r"(a0), "r"(a1), "r"(a2), "r"(a3), "r"(b0), "r"(b1));
}

// =====================================================================
// split3: fp32 -> bf16 triple-block along K.
//   activations: [hi | lo | hi] ; weights: [hi | hi | lo]
//   so A3 . W3 = ah*wh + al*wh + ah*wl  per original k.
// =====================================================================
__global__ void split3_act(const float* __restrict__ in, int lda, int K,
                           bf16* __restrict__ out, int k3p)
{
    const int row = blockIdx.y;
    const int kp = blockIdx.x * 64 + threadIdx.x;
    const float* src = in + (size_t)row * lda;
    bf16 v;
    if (kp < K) v = __float2bfloat16(src[kp]);
    else if (kp < 2*K){
        float a = src[kp - K];
        bf16 hh = __float2bfloat16(a);
        v = __float2bfloat16(a - __bfloat162float(hh));
    } else if (kp < 3*K) v = __float2bfloat16(src[kp - 2*K]);
    else v = __float2bfloat16(0.0f);
    out[(size_t)row * k3p + kp] = v;
}
__global__ void split3_wgt(const float* __restrict__ in, int lda, int K,
                           bf16* __restrict__ out, int k3p)
{
    const int row = blockIdx.y;
    const int kp = blockIdx.x * 64 + threadIdx.x;
    const float* src = in + (size_t)row * lda;
    bf16 v;
    if (kp < 2*K){
        int k = (kp < K) ? kp : kp - K;
        v = __float2bfloat16(src[k]);
    } else if (kp < 3*K){
        float a = src[kp - 2*K];
        bf16 hh = __float2bfloat16(a);
        v = __float2bfloat16(a - __bfloat162float(hh));
    } else v = __float2bfloat16(0.0f);
    out[(size_t)row * k3p + kp] = v;
}

// =====================================================================
// HMMA GEMM: C[m][n] = sum_k A3[m][k] * W3[n][k]  (bf16 in, fp32 out)
// CTA tile 128M x 128N, BK=32, cp.async double buffer.
// smem rows padded to 80 B (40 bf16): conflict-free LDGSTS + ldmatrix.
// 8 warps: wm = wid&1 (64 rows), wn = wid>>1 (32 cols).
// EPI: 0=none 1=bias 2=bias+softplus 3=bias+gelu 4=bias+residual
// =====================================================================
#define TILE_BYTES (256 * 80)          // A(128x80) + B(128x80)
template<int EPI>
__global__ __launch_bounds__(256, 2) void hmma_gemm(
    const bf16* __restrict__ A3, int lda3,
    const bf16* __restrict__ W3, int k3p,
    const float* __restrict__ bias, const float* __restrict__ res,
    float* __restrict__ C, int N)
{
    __shared__ char smem[2 * TILE_BYTES];
    const uint32_t sb = smem_u32(smem);
    const int tid = threadIdx.x;
    const int wid = tid >> 5, lane = tid & 31;
    const int bm = blockIdx.y * 128;
    const int bn = blockIdx.x * 128;
    const int wm = wid & 1, wn = wid >> 1;

    float acc[4][4][4];
#pragma unroll
    for (int i = 0; i < 4; i++)
#pragma unroll
        for (int j = 0; j < 4; j++)
#pragma unroll
            for (int e = 0; e < 4; e++) acc[i][j][e] = 0.f;

    const int NC = k3p >> 5;

    // loader lambda-ish: 1024 16B chunks per tile, 4 per thread
    const int c0 = tid;                  // chunks c0, c0+256, +512, +768
    // precompute per-thread chunk decode
    // chunk c: c<512 -> A row=c>>2 ch=c&3 ; else B
    auto load_tile = [&](int ci, uint32_t sbase){
#pragma unroll
        for (int cc = 0; cc < 4; cc++){
            const int c = c0 + cc * 256;
            if (c < 512){
                const int row = c >> 2, ch = c & 3;
                cp16(sbase + row * 80 + ch * 16,
                     &A3[(size_t)(bm + row) * lda3 + ci * 32 + ch * 8]);
            } else {
                const int c2 = c - 512;
                const int row = c2 >> 2, ch = c2 & 3;
                int br = bn + row; if (br >= N) br = N - 1;
                cp16(sbase + 128 * 80 + row * 80 + ch * 16,
                     &W3[(size_t)br * k3p + ci * 32 + ch * 8]);
            }
        }
        asm volatile("cp.async.commit_group;" ::: "memory");
    };

    load_tile(0, sb);

    // per-lane ldmatrix base offsets (within a tile buffer)
    const uint32_t aOff = (uint32_t)((wm * 64 + (lane & 15)) * 80 + (lane >> 4) * 16);
    const uint32_t bOff = (uint32_t)(128 * 80 +
                          (wn * 32 + (lane & 7) + ((lane & 16) ? 8 : 0)) * 80 +
                          ((lane >> 3) & 1) * 16);

    for (int ci = 0; ci < NC; ci++){
        const uint32_t cur = sb + (uint32_t)(ci & 1) * TILE_BYTES;
        if (ci + 1 < NC){
            load_tile(ci + 1, sb + (uint32_t)((ci + 1) & 1) * TILE_BYTES);
            asm volatile("cp.async.wait_group 1;" ::: "memory");
        } else {
            asm volatile("cp.async.wait_group 0;" ::: "memory");
        }
        __syncthreads();

#pragma unroll
        for (int s = 0; s < 2; s++){
            uint32_t a[4][4];
#pragma unroll
            for (int i = 0; i < 4; i++)
                ldsm4(a[i][0], a[i][1], a[i][2], a[i][3], cur + aOff + i * (16 * 80) + s * 32);
            uint32_t b0, b1, b2, b3, b4, b5, b6, b7;
            ldsm4(b0, b1, b2, b3, cur + bOff + s * 32);
            ldsm4(b4, b5, b6, b7, cur + bOff + 16 * 80 + s * 32);
#pragma unroll
            for (int i = 0; i < 4; i++){
                mma16816(acc[i][0], a[i][0], a[i][1], a[i][2], a[i][3], b0, b1);
                mma16816(acc[i][1], a[i][0], a[i][1], a[i][2], a[i][3], b2, b3);
                mma16816(acc[i][2], a[i][0], a[i][1], a[i][2], a[i][3], b4, b5);
                mma16816(acc[i][3], a[i][0], a[i][1], a[i][2], a[i][3], b6, b7);
            }
        }
        __syncthreads();
    }

    // epilogue: tile (i,j): thread holds (row = i*16 + lane/4 [,+8], col = j*8 + 2*(lane%4))
    const int t4 = lane >> 2, tp = (lane & 3) * 2;
#pragma unroll
    for (int i = 0; i < 4; i++){
#pragma unroll
        for (int j = 0; j < 4; j++){
            const int col = bn + wn * 32 + j * 8 + tp;
            if (col >= N) continue;
            const int row0 = bm + wm * 64 + i * 16 + t4;
            float v0 = acc[i][j][0], v1 = acc[i][j][1];
            float v2 = acc[i][j][2], v3 = acc[i][j][3];
            if (EPI >= 1){
                const float bb0 = bias[col], bb1 = bias[col + 1];
                v0 += bb0; v1 += bb1; v2 += bb0; v3 += bb1;
            }
            if (EPI == 2){ v0 = softplus_f(v0); v1 = softplus_f(v1); v2 = softplus_f(v2); v3 = softplus_f(v3); }
            if (EPI == 3){ v0 = gelu_f(v0); v1 = gelu_f(v1); v2 = gelu_f(v2); v3 = gelu_f(v3); }
            if (EPI == 4){
                v0 += res[(size_t)row0 * N + col];
                v1 += res[(size_t)row0 * N + col + 1];
                v2 += res[(size_t)(row0 + 8) * N + col];
                v3 += res[(size_t)(row0 + 8) * N + col + 1];
            }
            *(float2*)&C[(size_t)row0 * N + col]       = make_float2(v0, v1);
            *(float2*)&C[(size_t)(row0 + 8) * N + col] = make_float2(v2, v3);
        }
    }
}

// =====================================================================
// Flash attention (fp32, QK^T with f32x2)
// =====================================================================
__global__ __launch_bounds__(256) void flash_attn(
    const float* __restrict__ Q, const float* __restrict__ K, const float* __restrict__ V,
    const unsigned char* __restrict__ mask, float* __restrict__ O)
{
    extern __shared__ float smx[];
    float* Qs = smx;                 // 64*68
    float* Ks = Qs + 64 * 68;
    float* Vs = Ks + 64 * 68;
    float* Ps = Vs + 64 * 68;
    float* msk = Ps + 64 * 68;       // 64

    const int tid = threadIdx.x, tx = tid & 15, ty = tid >> 4;
    const int bh = blockIdx.y;
    const int b = bh >> 3, h = bh & 7;
    const int q0 = blockIdx.x * 64;
    const size_t basebl = (size_t)b * cL;

    for (int i = tid; i < 1024; i += 256){
        const int r = i >> 4, c = (i & 15) * 4;
        *(float4*)&Qs[r * 68 + c] = *(const float4*)&Q[(basebl + q0 + r) * cD + h * 64 + c];
    }

    float o[4][4], mrow[4], lrow[4];
#pragma unroll
    for (int i = 0; i < 4; i++){
        mrow[i] = -1e30f; lrow[i] = 0.f;
#pragma unroll
        for (int j = 0; j < 4; j++) o[i][j] = 0.f;
    }

    for (int jt = 0; jt < cL / 64; jt++){
        __syncthreads();
        const int k0 = jt * 64;
        for (int i = tid; i < 1024; i += 256){
            const int r = i >> 4, c = (i & 15) * 4;
            *(float4*)&Ks[r * 68 + c] = *(const float4*)&K[(basebl + k0 + r) * cD + h * 64 + c];
            *(float4*)&Vs[r * 68 + c] = *(const float4*)&V[(basebl + k0 + r) * cD + h * 64 + c];
        }
        if (tid < 64) msk[tid] = mask[b * cL + k0 + tid] ? -1e30f : 0.0f;
        __syncthreads();

        unsigned long long s2[4][4];
#pragma unroll
        for (int i = 0; i < 4; i++)
#pragma unroll
            for (int j = 0; j < 4; j++) s2[i][j] = 0ULL;

#pragma unroll 4
        for (int k = 0; k < 64; k += 4){
            F4U qv[4], kv[4];
#pragma unroll
            for (int i = 0; i < 4; i++) qv[i].f4 = *(const float4*)&Qs[(ty * 4 + i) * 68 + k];
#pragma unroll
            for (int j = 0; j < 4; j++) kv[j].f4 = *(const float4*)&Ks[(tx * 4 + j) * 68 + k];
#pragma unroll
            for (int i = 0; i < 4; i++)
#pragma unroll
                for (int j = 0; j < 4; j++){
                    fma2(s2[i][j], qv[i].l[0], kv[j].l[0]);
                    fma2(s2[i][j], qv[i].l[1], kv[j].l[1]);
                }
        }

#pragma unroll
        for (int i = 0; i < 4; i++){
            float sv[4];
#pragma unroll
            for (int j = 0; j < 4; j++){
                const unsigned long long t = s2[i][j];
                const float slo = __uint_as_float((unsigned)(t & 0xffffffffULL));
                const float shi = __uint_as_float((unsigned)(t >> 32));
                sv[j] = (slo + shi) * 0.125f + msk[tx * 4 + j];
            }
            float rm = fmaxf(fmaxf(sv[0], sv[1]), fmaxf(sv[2], sv[3]));
#pragma unroll
            for (int off = 1; off < 16; off <<= 1)
                rm = fmaxf(rm, __shfl_xor_sync(0xffffffffu, rm, off));
            const float mnew = fmaxf(mrow[i], rm);
            const float fac = __expf(mrow[i] - mnew);
            float rs = 0.f;
#pragma unroll
            for (int j = 0; j < 4; j++){
                const float p = __expf(sv[j] - mnew);
                rs += p;
                Ps[(ty * 4 + i) * 68 + tx * 4 + j] = p;
            }
#pragma unroll
            for (int off = 1; off < 16; off <<= 1)
                rs += __shfl_xor_sync(0xffffffffu, rs, off);
            lrow[i] = lrow[i] * fac + rs;
            mrow[i] = mnew;
#pragma unroll
            for (int j = 0; j < 4; j++) o[i][j] *= fac;
        }
        __syncthreads();

#pragma unroll 4
        for (int n = 0; n < 64; n += 4){
            F4U pv[4], vr[4];
#pragma unroll
            for (int i = 0; i < 4; i++) pv[i].f4 = *(const float4*)&Ps[(ty * 4 + i) * 68 + n];
#pragma unroll
            for (int jj = 0; jj < 4; jj++) vr[jj].f4 = *(const float4*)&Vs[(n + jj) * 68 + tx * 4];
#pragma unroll
            for (int i = 0; i < 4; i++)
#pragma unroll
                for (int e = 0; e < 4; e++)
                    o[i][e] += pv[i].f[0]*vr[0].f[e] + pv[i].f[1]*vr[1].f[e]
                             + pv[i].f[2]*vr[2].f[e] + pv[i].f[3]*vr[3].f[e];
        }
    }

#pragma unroll
    for (int i = 0; i < 4; i++){
        const float inv = 1.0f / lrow[i];
#pragma unroll
        for (int e = 0; e < 4; e++)
            O[(basebl + q0 + ty * 4 + i) * cD + h * 64 + tx * 4 + e] = o[i][e] * inv;
    }
}

// =====================================================================
// Depthwise causal conv (KC=4) + SiLU
// =====================================================================
__global__ __launch_bounds__(256) void conv_silu(
    const float* __restrict__ xz, const float* __restrict__ cw,
    const float* __restrict__ cb, float* __restrict__ u)
{
    const long idx = (long)blockIdx.x * 256 + threadIdx.x;
    const int c = (int)(idx & (cDI - 1));
    const int m = (int)(idx >> 10);
    const int b = m / cL, l = m % cL;
    float acc = cb[c];
#pragma unroll
    for (int k = 0; k < 4; k++){
        const int ls = l + k - 3;
        if (ls >= 0)
            acc += xz[((size_t)(b * cL + ls)) * (2 * cDI) + c] * cw[c * 4 + k];
    }
    acc = acc / (1.0f + __expf(-acc));
    u[(size_t)m * cDI + c] = acc;
}

// =====================================================================
// Selective scan: warp per (b, d)
// =====================================================================
__global__ __launch_bounds__(256) void mamba_scan(
    const float* __restrict__ delta, const float* __restrict__ u,
    const float* __restrict__ xdbc, const float* __restrict__ xz,
    const float* __restrict__ A_log, const float* __restrict__ Dssm,
    float* __restrict__ y)
{
    const int warp = threadIdx.x >> 5, lane = threadIdx.x & 31;
    const int d = blockIdx.x * 8 + warp;
    const int b = blockIdx.y;
    const float a0 = -__expf(A_log[d * cS + 2 * lane]);
    const float a1 = -__expf(A_log[d * cS + 2 * lane + 1]);
    const float Dd = Dssm[d];
    float h0 = 0.f, h1 = 0.f;
    const size_t base = (size_t)b * cL;

    for (int t = 0; t < cL; t++){
        const size_t m = base + t;
        const float dt = __ldg(&delta[m * cDI + d]);
        const float uu = __ldg(&u[m * cDI + d]);
        const float2 Bv = *(const float2*)&xdbc[m * 160 + 32 + 2 * lane];
        const float2 Cv = *(const float2*)&xdbc[m * 160 + 96 + 2 * lane];
        const float du = dt * uu;
        h0 = h0 * __expf(dt * a0) + du * Bv.x;
        h1 = h1 * __expf(dt * a1) + du * Bv.y;
        float p = h0 * Cv.x + h1 * Cv.y;
        p += __shfl_xor_sync(0xffffffffu, p, 16);
        p += __shfl_xor_sync(0xffffffffu, p, 8);
        p += __shfl_xor_sync(0xffffffffu, p, 4);
        p += __shfl_xor_sync(0xffffffffu, p, 2);
        p += __shfl_xor_sync(0xffffffffu, p, 1);
        if (lane == 0){
            const float z = xz[m * (2 * cDI) + cDI + d];
            float yv = p + uu * Dd;
            yv *= z / (1.0f + __expf(-z));
            y[m * cDI + d] = yv;
        }
    }
}

// =====================================================================
// Fused residual-sum + LN1 + LN2
// =====================================================================
__device__ __forceinline__ float blockSum256(float v, float* red){
#pragma unroll
    for (int off = 16; off > 0; off >>= 1) v += __shfl_xor_sync(0xffffffffu, v, off);
    if ((threadIdx.x & 31) == 0) red[threadIdx.x >> 5] = v;
    __syncthreads();
    const float s = red[0]+red[1]+red[2]+red[3]+red[4]+red[5]+red[6]+red[7];
    __syncthreads();
    return s;
}

__global__ __launch_bounds__(256) void ln_fuse(
    const float* __restrict__ xf, const float* __restrict__ attn, const float* __restrict__ mamba,
    const float* __restrict__ g1, const float* __restrict__ b1,
    const float* __restrict__ g2, const float* __restrict__ b2,
    float* __restrict__ h, float* __restrict__ hn)
{
    __shared__ float red[8];
    const size_t m = blockIdx.x;
    const int t = threadIdx.x;
    const size_t r = m * cD;
    float v0 = xf[r + t]       + attn[r + t]       + mamba[r + t];
    float v1 = xf[r + 256 + t] + attn[r + 256 + t] + mamba[r + 256 + t];

    const float mean = blockSum256(v0 + v1, red) * (1.0f / cD);
    const float d0 = v0 - mean, d1 = v1 - mean;
    const float var = blockSum256(d0 * d0 + d1 * d1, red) * (1.0f / cD);
    const float inv = rsqrtf(var + 1e-5f);
    const float h0 = d0 * inv * g1[t]       + b1[t];
    const float h1 = d1 * inv * g1[256 + t] + b1[256 + t];
    h[r + t] = h0;
    h[r + 256 + t] = h1;

    const float mean2 = blockSum256(h0 + h1, red) * (1.0f / cD);
    const float e0 = h0 - mean2, e1 = h1 - mean2;
    const float var2 = blockSum256(e0 * e0 + e1 * e1, red) * (1.0f / cD);
    const float inv2 = rsqrtf(var2 + 1e-6f);
    hn[r + t]       = e0 * inv2 * g2[t]       + b2[t];
    hn[r + 256 + t] = e1 * inv2 * g2[256 + t] + b2[256 + t];
}

// =====================================================================
// Launch
// =====================================================================
extern "C" void kernel_launch(void* const* d_in, const int* in_sizes, int n_in,
                              void* d_out, int out_size)
{
    (void)in_sizes; (void)n_in; (void)out_size;
    const float* x      = (const float*)d_in[0];
    const unsigned char* mask = (const unsigned char*)d_in[1];
    const float* Wq = (const float*)d_in[2];  const float* bq = (const float*)d_in[3];
    const float* Wk = (const float*)d_in[4];  const float* bk = (const float*)d_in[5];
    const float* Wv = (const float*)d_in[6];  const float* bv = (const float*)d_in[7];
    const float* Wo = (const float*)d_in[8];  const float* bo = (const float*)d_in[9];
    const float* in_w   = (const float*)d_in[10];
    const float* conv_w = (const float*)d_in[11];
    const float* conv_b = (const float*)d_in[12];
    const float* xproj_w= (const float*)d_in[13];
    const float* dt_w   = (const float*)d_in[14];
    const float* dt_b   = (const float*)d_in[15];
    const float* A_log  = (const float*)d_in[16];
    const float* Dssm   = (const float*)d_in[17];
    const float* outp_w = (const float*)d_in[18];
    const float* ln1g   = (const float*)d_in[19];
    const float* ln1b   = (const float*)d_in[20];
    const float* fw1    = (const float*)d_in[21];
    const float* fb1    = (const float*)d_in[22];
    const float* fw2    = (const float*)d_in[23];
    const float* fb2    = (const float*)d_in[24];
    const float* ln2g   = (const float*)d_in[25];
    const float* ln2b   = (const float*)d_in[26];
    float* out = (float*)d_out;

    float *q,*k,*v,*ao,*attn,*xz,*u,*xdbc,*dlt,*y,*mmb,*h,*hn,*ff1;
    cudaGetSymbolAddress((void**)&q,    g_q);
    cudaGetSymbolAddress((void**)&k,    g_kk);
    cudaGetSymbolAddress((void**)&v,    g_vv);
    cudaGetSymbolAddress((void**)&ao,   g_ao);
    cudaGetSymbolAddress((void**)&attn, g_attn);
    cudaGetSymbolAddress((void**)&xz,   g_xz);
    cudaGetSymbolAddress((void**)&u,    g_u);
    cudaGetSymbolAddress((void**)&xdbc, g_xdbc);
    cudaGetSymbolAddress((void**)&dlt,  g_dlt);
    cudaGetSymbolAddress((void**)&y,    g_y);
    cudaGetSymbolAddress((void**)&mmb,  g_mmb);
    cudaGetSymbolAddress((void**)&h,    g_h);
    cudaGetSymbolAddress((void**)&hn,   g_hn);
    cudaGetSymbolAddress((void**)&ff1,  g_ff1);

    bf16 *px3,*pao3,*pu3,*pxdbc3,*py3,*phn3,*pff13;
    bf16 *pwq,*pwk,*pwv,*pwo,*pwin,*pwxp,*pwdt,*pwout,*pwf1,*pwf2;
    cudaGetSymbolAddress((void**)&px3,   gx3);
    cudaGetSymbolAddress((void**)&pao3,  gao3);
    cudaGetSymbolAddress((void**)&pu3,   gu3);
    cudaGetSymbolAddress((void**)&pxdbc3,gxdbc3);
    cudaGetSymbolAddress((void**)&py3,   gy3);
    cudaGetSymbolAddress((void**)&phn3,  ghn3);
    cudaGetSymbolAddress((void**)&pff13, gff13);
    cudaGetSymbolAddress((void**)&pwq,   wq3);
    cudaGetSymbolAddress((void**)&pwk,   wk3);
    cudaGetSymbolAddress((void**)&pwv,   wv3);
    cudaGetSymbolAddress((void**)&pwo,   wo3);
    cudaGetSymbolAddress((void**)&pwin,  win3);
    cudaGetSymbolAddress((void**)&pwxp,  wxp3);
    cudaGetSymbolAddress((void**)&pwdt,  wdt3);
    cudaGetSymbolAddress((void**)&pwout, wout3);
    cudaGetSymbolAddress((void**)&pwf1,  wff13);
    cudaGetSymbolAddress((void**)&pwf2,  wff23);

    const int flashSmem = (4 * 64 * 68 + 64) * 4;
    cudaFuncSetAttribute(flash_attn, cudaFuncAttributeMaxDynamicSharedMemorySize, flashSmem);

    // ---- weight conversions ----
    split3_wgt<<<dim3(24, 512),  64>>>(Wq,      512,  512,  pwq,   1536);
    split3_wgt<<<dim3(24, 512),  64>>>(Wk,      512,  512,  pwk,   1536);
    split3_wgt<<<dim3(24, 512),  64>>>(Wv,      512,  512,  pwv,   1536);
    split3_wgt<<<dim3(24, 512),  64>>>(Wo,      512,  512,  pwo,   1536);
    split3_wgt<<<dim3(24, 2048), 64>>>(in_w,    512,  512,  pwin,  1536);
    split3_wgt<<<dim3(48, 160),  64>>>(xproj_w, 1024, 1024, pwxp,  3072);
    split3_wgt<<<dim3(2,  1024), 64>>>(dt_w,    32,   32,   pwdt,  128);
    split3_wgt<<<dim3(48, 512),  64>>>(outp_w,  1024, 1024, pwout, 3072);
    split3_wgt<<<dim3(24, 2048), 64>>>(fw1,     512,  512,  pwf1,  1536);
    split3_wgt<<<dim3(96, 512),  64>>>(fw2,     2048, 2048, pwf2,  6144);

    // ---- attention branch ----
    split3_act<<<dim3(24, cM), 64>>>(x, 512, 512, px3, 1536);
    hmma_gemm<1><<<dim3(4, 72), 256>>>(px3, 1536, pwq, 1536, bq, nullptr, q, 512);
    hmma_gemm<1><<<dim3(4, 72), 256>>>(px3, 1536, pwk, 1536, bk, nullptr, k, 512);
    hmma_gemm<1><<<dim3(4, 72), 256>>>(px3, 1536, pwv, 1536, bv, nullptr, v, 512);
    flash_attn<<<dim3(cL / 64, cB * 8), 256, flashSmem>>>(q, k, v, mask, ao);
    split3_act<<<dim3(24, cM), 64>>>(ao, 512, 512, pao3, 1536);
    hmma_gemm<1><<<dim3(4, 72), 256>>>(pao3, 1536, pwo, 1536, bo, nullptr, attn, 512);

    // ---- mamba branch ----
    hmma_gemm<0><<<dim3(16, 72), 256>>>(px3, 1536, pwin, 1536, nullptr, nullptr, xz, 2048);
    conv_silu<<<(cM * cDI) / 256, 256>>>(xz, conv_w, conv_b, u);
    split3_act<<<dim3(48, cM), 64>>>(u, 1024, 1024, pu3, 3072);
    hmma_gemm<0><<<dim3(2, 72), 256>>>(pu3, 3072, pwxp, 3072, nullptr, nullptr, xdbc, 160);
    split3_act<<<dim3(2, cM), 64>>>(xdbc, 160, 32, pxdbc3, 128);
    hmma_gemm<2><<<dim3(8, 72), 256>>>(pxdbc3, 128, pwdt, 128, dt_b, nullptr, dlt, 1024);
    mamba_scan<<<dim3(cDI / 8, cB), 256>>>(dlt, u, xdbc, xz, A_log, Dssm, y);
    split3_act<<<dim3(48, cM), 64>>>(y, 1024, 1024, py3, 3072);
    hmma_gemm<0><<<dim3(4, 72), 256>>>(py3, 3072, pwout, 3072, nullptr, nullptr, mmb, 512);

    // ---- merge + LN + FFN ----
    ln_fuse<<<cM, 256>>>(x, attn, mmb, ln1g, ln1b, ln2g, ln2b, h, hn);
    split3_act<<<dim3(24, cM), 64>>>(hn, 512, 512, phn3, 1536);
    hmma_gemm<3><<<dim3(16, 72), 256>>>(phn3, 1536, pwf1, 1536, fb1, nullptr, ff1, 2048);
    split3_act<<<dim3(96, cM), 64>>>(ff1, 2048, 2048, pff13, 6144);
    hmma_gemm<4><<<dim3(4, 72), 256>>>(pff13, 6144, pwf2, 6144, fb2, h, out, 512);
}

// round 6
// speedup vs baseline: 1.2478x; 1.2478x over previous
#include <cuda_runtime.h>
#include <cuda_bf16.h>
#include <cstdint>
#include <math.h>

typedef __nv_bfloat16 bf16;

// ---------------- dims ----------------
static const int cB  = 8;
static const int cL  = 1152;      // T*W
static const int cD  = 512;
static const int cDI = 1024;
static const int cS  = 64;
static const int cDFF= 2048;
static const int cM  = 9216;      // B*L

// ---------------- fp32 workspaces ----------------
__device__ float g_q   [cM*cD];
__device__ float g_kk  [cM*cD];
__device__ float g_vv  [cM*cD];
__device__ float g_ao  [cM*cD];
__device__ float g_attn[cM*cD];
__device__ float g_xz  [cM*2*cDI];
__device__ float g_u   [cM*cDI];
__device__ float g_xdbc[cM*160];
__device__ float g_dlt [cM*cDI];
__device__ float g_mmb [cM*cD];
__device__ float g_h   [cM*cD];

// ---------------- bf16 split-3 buffers (activations) ----------------
__device__ bf16 gx3   [cM*1536];
__device__ bf16 gao3  [cM*1536];
__device__ bf16 gu3   [cM*3072];
__device__ bf16 gxdbc3[cM*128];
__device__ bf16 gy3   [cM*3072];
__device__ bf16 ghn3  [cM*1536];
__device__ bf16 gff13 [cM*6144];

// ---------------- bf16 split-3 weights ----------------
__device__ bf16 wq3  [512*1536];
__device__ bf16 wk3  [512*1536];
__device__ bf16 wv3  [512*1536];
__device__ bf16 wo3  [512*1536];
__device__ bf16 win3 [2048*1536];
__device__ bf16 wxp3 [160*3072];
__device__ bf16 wdt3 [1024*128];
__device__ bf16 wout3[512*3072];
__device__ bf16 wff13[2048*1536];
__device__ bf16 wff23[512*6144];

// ---------------- helpers ----------------
__device__ __forceinline__ void fma2(unsigned long long &d, unsigned long long a, unsigned long long b){
    asm("fma.rn.f32x2 %0, %1, %2, %0;" : "+l"(d) : "l"(a), "l"(b));
}
union F4U { float4 f4; unsigned long long l[2]; float f[4]; };

__device__ __forceinline__ float softplus_f(float v){
    return fmaxf(v, 0.0f) + log1pf(__expf(-fabsf(v)));
}
__device__ __forceinline__ float gelu_f(float v){
    return 0.5f * v * (1.0f + erff(v * 0.70710678118654752f));
}
__device__ __forceinline__ bf16 hi_bf(float a){ return __float2bfloat16(a); }
__device__ __forceinline__ bf16 lo_bf(float a){
    bf16 h = __float2bfloat16(a);
    return __float2bfloat16(a - __bfloat162float(h));
}
__device__ __forceinline__ __nv_bfloat162 hi2(float a, float b){
    return __floats2bfloat162_rn(a, b);
}
__device__ __forceinline__ __nv_bfloat162 lo2(float a, float b){
    __nv_bfloat162 h = __floats2bfloat162_rn(a, b);
    return __floats2bfloat162_rn(a - __bfloat162float(h.x), b - __bfloat162float(h.y));
}

__device__ __forceinline__ uint32_t smem_u32(const void* p){
    uint32_t a;
    asm("{ .reg .u64 t; cvta.to.shared.u64 t, %1; cvt.u32.u64 %0, t; }" : "=r"(a) : "l"(p));
    return a;
}
__device__ __forceinline__ void cp16(uint32_t dst, const void* src){
    asm volatile("cp.async.cg.shared.global [%0], [%1], 16;" :: "r"(dst), "l"(src));
}
__device__ __forceinline__ void ldsm4(uint32_t &r0, uint32_t &r1, uint32_t &r2, uint32_t &r3, uint32_t addr){
    asm volatile("ldmatrix.sync.aligned.m8n8.x4.shared.b16 {%0,%1,%2,%3}, [%4];"
        : "=r"(r0), "=r"(r1), "=r"(r2), "=r"(r3) : "r"(addr));
}
__device__ __forceinline__ void mma16816(float* c, uint32_t a0, uint32_t a1, uint32_t a2, uint32_t a3,
                                         uint32_t b0, uint32_t b1){
    asm volatile("mma.sync.aligned.m16n8k16.row.col.f32.bf16.bf16.f32 "
        "{%0,%1,%2,%3}, {%4,%5,%6,%7}, {%8,%9}, {%0,%1,%2,%3};"
        : "+f"(c[0]), "+f"(c[1]), "+f"(c[2]), "+f"(c[3])
        : "r"(a0), "r"(a1), "r"(a2), "r"(a3), "r"(b0), "r"(b1));
}

// =====================================================================
// Fast split3: 8 elems per thread, 16B stores.
//   activations: [hi | lo | hi] (+zero pad blocks); weights: [hi | hi | lo]
// =====================================================================
__global__ __launch_bounds__(256) void split3_act_fast(
    const float* __restrict__ in, int lda, int K,
    bf16* __restrict__ out, int k3p, int rows)
{
    const int chunks = k3p >> 3;
    const long idx = (long)blockIdx.x * 256 + threadIdx.x;
    if (idx >= (long)rows * chunks) return;
    const int row = (int)(idx / chunks);
    const int kc = (int)(idx - (long)row * chunks);
    const int blk = (kc * 8) / K;
    const int within = kc * 8 - blk * K;
    __nv_bfloat162 o[4];
    if (blk >= 3){
        o[0] = o[1] = o[2] = o[3] = __floats2bfloat162_rn(0.f, 0.f);
    } else {
        const float* src = in + (size_t)row * lda + within;
        F4U s0, s1; s0.f4 = *(const float4*)src; s1.f4 = *(const float4*)(src + 4);
        if (blk == 1){
            o[0] = lo2(s0.f[0], s0.f[1]); o[1] = lo2(s0.f[2], s0.f[3]);
            o[2] = lo2(s1.f[0], s1.f[1]); o[3] = lo2(s1.f[2], s1.f[3]);
        } else {
            o[0] = hi2(s0.f[0], s0.f[1]); o[1] = hi2(s0.f[2], s0.f[3]);
            o[2] = hi2(s1.f[0], s1.f[1]); o[3] = hi2(s1.f[2], s1.f[3]);
        }
    }
    *(uint4*)&out[(size_t)row * k3p + kc * 8] = *(uint4*)o;
}

__global__ __launch_bounds__(256) void split3_wgt_fast(
    const float* __restrict__ in, int lda, int K,
    bf16* __restrict__ out, int k3p, int rows)
{
    const int chunks = k3p >> 3;
    const long idx = (long)blockIdx.x * 256 + threadIdx.x;
    if (idx >= (long)rows * chunks) return;
    const int row = (int)(idx / chunks);
    const int kc = (int)(idx - (long)row * chunks);
    const int blk = (kc * 8) / K;
    const int within = kc * 8 - blk * K;
    __nv_bfloat162 o[4];
    if (blk >= 3){
        o[0] = o[1] = o[2] = o[3] = __floats2bfloat162_rn(0.f, 0.f);
    } else {
        const float* src = in + (size_t)row * lda + within;
        F4U s0, s1; s0.f4 = *(const float4*)src; s1.f4 = *(const float4*)(src + 4);
        if (blk == 2){
            o[0] = lo2(s0.f[0], s0.f[1]); o[1] = lo2(s0.f[2], s0.f[3]);
            o[2] = lo2(s1.f[0], s1.f[1]); o[3] = lo2(s1.f[2], s1.f[3]);
        } else {
            o[0] = hi2(s0.f[0], s0.f[1]); o[1] = hi2(s0.f[2], s0.f[3]);
            o[2] = hi2(s1.f[0], s1.f[1]); o[3] = hi2(s1.f[2], s1.f[3]);
        }
    }
    *(uint4*)&out[(size_t)row * k3p + kc * 8] = *(uint4*)o;
}

// =====================================================================
// HMMA GEMM, 3-stage cp.async pipeline, one sync per K-chunk (BK=32).
// CTA 128M x 128N; smem rows padded to 80B; 8 warps (wm=wid&1, wn=wid>>1).
// EPI: 0=none 1=bias 2=bias+softplus 3=bias+gelu(optionally OUT3) 4=bias+res
// OUT3: write bf16 [hi|lo|hi] triple to C3 (k3p_out = 3N) instead of fp32.
// =====================================================================
#define TILE_BYTES 20480           // A(128x80) + B(128x80)
#define GEMM_SMEM  (3 * TILE_BYTES)
template<int EPI, bool OUT3>
__global__ __launch_bounds__(256, 2) void hmma_gemm(
    const bf16* __restrict__ A3, int lda3,
    const bf16* __restrict__ W3, int k3p,
    const float* __restrict__ bias, const float* __restrict__ res,
    float* __restrict__ C, bf16* __restrict__ C3, int N)
{
    extern __shared__ char smem[];
    const uint32_t sb = smem_u32(smem);
    const int tid = threadIdx.x;
    const int wid = tid >> 5, lane = tid & 31;
    const int bm = blockIdx.y * 128;
    const int bn = blockIdx.x * 128;
    const int wm = wid & 1, wn = wid >> 1;

    float acc[4][4][4];
#pragma unroll
    for (int i = 0; i < 4; i++)
#pragma unroll
        for (int j = 0; j < 4; j++)
#pragma unroll
            for (int e = 0; e < 4; e++) acc[i][j][e] = 0.f;

    const int NC = k3p >> 5;
    const int c0 = tid;

    auto load_tile = [&](int ci, uint32_t sbase){
#pragma unroll
        for (int cc = 0; cc < 4; cc++){
            const int c = c0 + cc * 256;
            if (c < 512){
                const int row = c >> 2, ch = c & 3;
                cp16(sbase + row * 80 + ch * 16,
                     &A3[(size_t)(bm + row) * lda3 + ci * 32 + ch * 8]);
            } else {
                const int c2 = c - 512;
                const int row = c2 >> 2, ch = c2 & 3;
                int br = bn + row; if (br >= N) br = N - 1;
                cp16(sbase + 128 * 80 + row * 80 + ch * 16,
                     &W3[(size_t)br * k3p + ci * 32 + ch * 8]);
            }
        }
        asm volatile("cp.async.commit_group;" ::: "memory");
    };

    load_tile(0, sb);
    if (NC > 1) load_tile(1, sb + TILE_BYTES);

    const uint32_t aOff = (uint32_t)((wm * 64 + (lane & 15)) * 80 + (lane >> 4) * 16);
    const uint32_t bOff = (uint32_t)(128 * 80 +
                          (wn * 32 + (lane & 7) + ((lane & 16) ? 8 : 0)) * 80 +
                          ((lane >> 3) & 1) * 16);

    for (int ci = 0; ci < NC; ci++){
        if (ci + 1 < NC) asm volatile("cp.async.wait_group 1;" ::: "memory");
        else             asm volatile("cp.async.wait_group 0;" ::: "memory");
        __syncthreads();
        if (ci + 2 < NC){
            const int nb = (ci + 2) % 3;
            load_tile(ci + 2, sb + (uint32_t)nb * TILE_BYTES);
        }
        const uint32_t cur = sb + (uint32_t)(ci % 3) * TILE_BYTES;

#pragma unroll
        for (int s = 0; s < 2; s++){
            uint32_t a[4][4];
#pragma unroll
            for (int i = 0; i < 4; i++)
                ldsm4(a[i][0], a[i][1], a[i][2], a[i][3], cur + aOff + i * (16 * 80) + s * 32);
            uint32_t b0, b1, b2, b3, b4, b5, b6, b7;
            ldsm4(b0, b1, b2, b3, cur + bOff + s * 32);
            ldsm4(b4, b5, b6, b7, cur + bOff + 16 * 80 + s * 32);
#pragma unroll
            for (int i = 0; i < 4; i++){
                mma16816(acc[i][0], a[i][0], a[i][1], a[i][2], a[i][3], b0, b1);
                mma16816(acc[i][1], a[i][0], a[i][1], a[i][2], a[i][3], b2, b3);
                mma16816(acc[i][2], a[i][0], a[i][1], a[i][2], a[i][3], b4, b5);
                mma16816(acc[i][3], a[i][0], a[i][1], a[i][2], a[i][3], b6, b7);
            }
        }
    }

    const int t4 = lane >> 2, tp = (lane & 3) * 2;
#pragma unroll
    for (int i = 0; i < 4; i++){
#pragma unroll
        for (int j = 0; j < 4; j++){
            const int col = bn + wn * 32 + j * 8 + tp;
            if (col >= N) continue;
            const int row0 = bm + wm * 64 + i * 16 + t4;
            float v0 = acc[i][j][0], v1 = acc[i][j][1];
            float v2 = acc[i][j][2], v3 = acc[i][j][3];
            if (EPI >= 1){
                const float bb0 = bias[col], bb1 = bias[col + 1];
                v0 += bb0; v1 += bb1; v2 += bb0; v3 += bb1;
            }
            if (EPI == 2){ v0 = softplus_f(v0); v1 = softplus_f(v1); v2 = softplus_f(v2); v3 = softplus_f(v3); }
            if (EPI == 3){ v0 = gelu_f(v0); v1 = gelu_f(v1); v2 = gelu_f(v2); v3 = gelu_f(v3); }
            if (EPI == 4){
                v0 += res[(size_t)row0 * N + col];
                v1 += res[(size_t)row0 * N + col + 1];
                v2 += res[(size_t)(row0 + 8) * N + col];
                v3 += res[(size_t)(row0 + 8) * N + col + 1];
            }
            if (OUT3){
                const size_t r0 = (size_t)row0 * (3 * N), r1 = (size_t)(row0 + 8) * (3 * N);
                *(__nv_bfloat162*)&C3[r0 + col]         = hi2(v0, v1);
                *(__nv_bfloat162*)&C3[r0 + N + col]     = lo2(v0, v1);
                *(__nv_bfloat162*)&C3[r0 + 2 * N + col] = hi2(v0, v1);
                *(__nv_bfloat162*)&C3[r1 + col]         = hi2(v2, v3);
                *(__nv_bfloat162*)&C3[r1 + N + col]     = lo2(v2, v3);
                *(__nv_bfloat162*)&C3[r1 + 2 * N + col] = hi2(v2, v3);
            } else {
                *(float2*)&C[(size_t)row0 * N + col]       = make_float2(v0, v1);
                *(float2*)&C[(size_t)(row0 + 8) * N + col] = make_float2(v2, v3);
            }
        }
    }
}

// =====================================================================
// Flash attention (fp32, QK^T with f32x2)
// =====================================================================
__global__ __launch_bounds__(256) void flash_attn(
    const float* __restrict__ Q, const float* __restrict__ K, const float* __restrict__ V,
    const unsigned char* __restrict__ mask, float* __restrict__ O)
{
    extern __shared__ float smx[];
    float* Qs = smx;                 // 64*68
    float* Ks = Qs + 64 * 68;
    float* Vs = Ks + 64 * 68;
    float* Ps = Vs + 64 * 68;
    float* msk = Ps + 64 * 68;       // 64

    const int tid = threadIdx.x, tx = tid & 15, ty = tid >> 4;
    const int bh = blockIdx.y;
    const int b = bh >> 3, h = bh & 7;
    const int q0 = blockIdx.x * 64;
    const size_t basebl = (size_t)b * cL;

    for (int i = tid; i < 1024; i += 256){
        const int r = i >> 4, c = (i & 15) * 4;
        *(float4*)&Qs[r * 68 + c] = *(const float4*)&Q[(basebl + q0 + r) * cD + h * 64 + c];
    }

    float o[4][4], mrow[4], lrow[4];
#pragma unroll
    for (int i = 0; i < 4; i++){
        mrow[i] = -1e30f; lrow[i] = 0.f;
#pragma unroll
        for (int j = 0; j < 4; j++) o[i][j] = 0.f;
    }

    for (int jt = 0; jt < cL / 64; jt++){
        __syncthreads();
        const int k0 = jt * 64;
        for (int i = tid; i < 1024; i += 256){
            const int r = i >> 4, c = (i & 15) * 4;
            *(float4*)&Ks[r * 68 + c] = *(const float4*)&K[(basebl + k0 + r) * cD + h * 64 + c];
            *(float4*)&Vs[r * 68 + c] = *(const float4*)&V[(basebl + k0 + r) * cD + h * 64 + c];
        }
        if (tid < 64) msk[tid] = mask[b * cL + k0 + tid] ? -1e30f : 0.0f;
        __syncthreads();

        unsigned long long s2[4][4];
#pragma unroll
        for (int i = 0; i < 4; i++)
#pragma unroll
            for (int j = 0; j < 4; j++) s2[i][j] = 0ULL;

#pragma unroll 4
        for (int k = 0; k < 64; k += 4){
            F4U qv[4], kv[4];
#pragma unroll
            for (int i = 0; i < 4; i++) qv[i].f4 = *(const float4*)&Qs[(ty * 4 + i) * 68 + k];
#pragma unroll
            for (int j = 0; j < 4; j++) kv[j].f4 = *(const float4*)&Ks[(tx * 4 + j) * 68 + k];
#pragma unroll
            for (int i = 0; i < 4; i++)
#pragma unroll
                for (int j = 0; j < 4; j++){
                    fma2(s2[i][j], qv[i].l[0], kv[j].l[0]);
                    fma2(s2[i][j], qv[i].l[1], kv[j].l[1]);
                }
        }

#pragma unroll
        for (int i = 0; i < 4; i++){
            float sv[4];
#pragma unroll
            for (int j = 0; j < 4; j++){
                const unsigned long long t = s2[i][j];
                const float slo = __uint_as_float((unsigned)(t & 0xffffffffULL));
                const float shi = __uint_as_float((unsigned)(t >> 32));
                sv[j] = (slo + shi) * 0.125f + msk[tx * 4 + j];
            }
            float rm = fmaxf(fmaxf(sv[0], sv[1]), fmaxf(sv[2], sv[3]));
#pragma unroll
            for (int off = 1; off < 16; off <<= 1)
                rm = fmaxf(rm, __shfl_xor_sync(0xffffffffu, rm, off));
            const float mnew = fmaxf(mrow[i], rm);
            const float fac = __expf(mrow[i] - mnew);
            float rs = 0.f;
#pragma unroll
            for (int j = 0; j < 4; j++){
                const float p = __expf(sv[j] - mnew);
                rs += p;
                Ps[(ty * 4 + i) * 68 + tx * 4 + j] = p;
            }
#pragma unroll
            for (int off = 1; off < 16; off <<= 1)
                rs += __shfl_xor_sync(0xffffffffu, rs, off);
            lrow[i] = lrow[i] * fac + rs;
            mrow[i] = mnew;
#pragma unroll
            for (int j = 0; j < 4; j++) o[i][j] *= fac;
        }
        __syncthreads();

#pragma unroll 4
        for (int n = 0; n < 64; n += 4){
            F4U pv[4], vr[4];
#pragma unroll
            for (int i = 0; i < 4; i++) pv[i].f4 = *(const float4*)&Ps[(ty * 4 + i) * 68 + n];
#pragma unroll
            for (int jj = 0; jj < 4; jj++) vr[jj].f4 = *(const float4*)&Vs[(n + jj) * 68 + tx * 4];
#pragma unroll
            for (int i = 0; i < 4; i++)
#pragma unroll
                for (int e = 0; e < 4; e++)
                    o[i][e] += pv[i].f[0]*vr[0].f[e] + pv[i].f[1]*vr[1].f[e]
                             + pv[i].f[2]*vr[2].f[e] + pv[i].f[3]*vr[3].f[e];
        }
    }

#pragma unroll
    for (int i = 0; i < 4; i++){
        const float inv = 1.0f / lrow[i];
#pragma unroll
        for (int e = 0; e < 4; e++)
            O[(basebl + q0 + ty * 4 + i) * cD + h * 64 + tx * 4 + e] = o[i][e] * inv;
    }
}

// =====================================================================
// Depthwise causal conv (KC=4) + SiLU; 2 channels/thread; writes u + u3
// =====================================================================
__global__ __launch_bounds__(256) void conv_silu(
    const float* __restrict__ xz, const float* __restrict__ cw,
    const float* __restrict__ cb, float* __restrict__ u, bf16* __restrict__ u3)
{
    const long idx = (long)blockIdx.x * 256 + threadIdx.x;  // over M*512
    const int c = (int)(idx & 511) * 2;
    const int m = (int)(idx >> 9);
    const int b = m / cL, l = m % cL;
    float a0 = cb[c], a1 = cb[c + 1];
#pragma unroll
    for (int k = 0; k < 4; k++){
        const int ls = l + k - 3;
        if (ls >= 0){
            const size_t row = (size_t)(b * cL + ls) * (2 * cDI);
            a0 += xz[row + c]     * cw[c * 4 + k];
            a1 += xz[row + c + 1] * cw[(c + 1) * 4 + k];
        }
    }
    a0 = a0 / (1.0f + __expf(-a0));
    a1 = a1 / (1.0f + __expf(-a1));
    *(float2*)&u[(size_t)m * cDI + c] = make_float2(a0, a1);
    const size_t r3 = (size_t)m * 3072;
    *(__nv_bfloat162*)&u3[r3 + c]        = hi2(a0, a1);
    *(__nv_bfloat162*)&u3[r3 + 1024 + c] = lo2(a0, a1);
    *(__nv_bfloat162*)&u3[r3 + 2048 + c] = hi2(a0, a1);
}

// =====================================================================
// Selective scan: warp per (b, d); writes y3 triple directly
// =====================================================================
__global__ __launch_bounds__(256) void mamba_scan(
    const float* __restrict__ delta, const float* __restrict__ u,
    const float* __restrict__ xdbc, const float* __restrict__ xz,
    const float* __restrict__ A_log, const float* __restrict__ Dssm,
    bf16* __restrict__ y3)
{
    const int warp = threadIdx.x >> 5, lane = threadIdx.x & 31;
    const int d = blockIdx.x * 8 + warp;
    const int b = blockIdx.y;
    const float a0 = -__expf(A_log[d * cS + 2 * lane]);
    const float a1 = -__expf(A_log[d * cS + 2 * lane + 1]);
    const float Dd = Dssm[d];
    float h0 = 0.f, h1 = 0.f;
    const size_t base = (size_t)b * cL;

    for (int t = 0; t < cL; t++){
        const size_t m = base + t;
        const float dt = __ldg(&delta[m * cDI + d]);
        const float uu = __ldg(&u[m * cDI + d]);
        const float2 Bv = *(const float2*)&xdbc[m * 160 + 32 + 2 * lane];
        const float2 Cv = *(const float2*)&xdbc[m * 160 + 96 + 2 * lane];
        const float du = dt * uu;
        h0 = h0 * __expf(dt * a0) + du * Bv.x;
        h1 = h1 * __expf(dt * a1) + du * Bv.y;
        float p = h0 * Cv.x + h1 * Cv.y;
        p += __shfl_xor_sync(0xffffffffu, p, 16);
        p += __shfl_xor_sync(0xffffffffu, p, 8);
        p += __shfl_xor_sync(0xffffffffu, p, 4);
        p += __shfl_xor_sync(0xffffffffu, p, 2);
        p += __shfl_xor_sync(0xffffffffu, p, 1);
        if (lane == 0){
            const float z = xz[m * (2 * cDI) + cDI + d];
            float yv = p + uu * Dd;
            yv *= z / (1.0f + __expf(-z));
            const size_t r3 = m * 3072;
            y3[r3 + d]        = hi_bf(yv);
            y3[r3 + 1024 + d] = lo_bf(yv);
            y3[r3 + 2048 + d] = hi_bf(yv);
        }
    }
}

// =====================================================================
// Fused residual-sum + LN1 + LN2; writes h (fp32) and hn3 (bf16 triple)
// thread t handles cols 2t, 2t+1
// =====================================================================
__device__ __forceinline__ float blockSum256(float v, float* red){
#pragma unroll
    for (int off = 16; off > 0; off >>= 1) v += __shfl_xor_sync(0xffffffffu, v, off);
    if ((threadIdx.x & 31) == 0) red[threadIdx.x >> 5] = v;
    __syncthreads();
    const float s = red[0]+red[1]+red[2]+red[3]+red[4]+red[5]+red[6]+red[7];
    __syncthreads();
    return s;
}

__global__ __launch_bounds__(256) void ln_fuse(
    const float* __restrict__ xf, const float* __restrict__ attn, const float* __restrict__ mamba,
    const float* __restrict__ g1, const float* __restrict__ b1,
    const float* __restrict__ g2, const float* __restrict__ b2,
    float* __restrict__ h, bf16* __restrict__ hn3)
{
    __shared__ float red[8];
    const size_t m = blockIdx.x;
    const int t = threadIdx.x * 2;
    const size_t r = m * cD;
    float v0 = xf[r + t]     + attn[r + t]     + mamba[r + t];
    float v1 = xf[r + t + 1] + attn[r + t + 1] + mamba[r + t + 1];

    const float mean = blockSum256(v0 + v1, red) * (1.0f / cD);
    const float d0 = v0 - mean, d1 = v1 - mean;
    const float var = blockSum256(d0 * d0 + d1 * d1, red) * (1.0f / cD);
    const float inv = rsqrtf(var + 1e-5f);
    const float h0 = d0 * inv * g1[t]     + b1[t];
    const float h1 = d1 * inv * g1[t + 1] + b1[t + 1];
    *(float2*)&h[r + t] = make_float2(h0, h1);

    const float mean2 = blockSum256(h0 + h1, red) * (1.0f / cD);
    const float e0 = h0 - mean2, e1 = h1 - mean2;
    const float var2 = blockSum256(e0 * e0 + e1 * e1, red) * (1.0f / cD);
    const float inv2 = rsqrtf(var2 + 1e-6f);
    const float n0 = e0 * inv2 * g2[t]     + b2[t];
    const float n1 = e1 * inv2 * g2[t + 1] + b2[t + 1];
    const size_t r3 = m * 1536;
    *(__nv_bfloat162*)&hn3[r3 + t]        = hi2(n0, n1);
    *(__nv_bfloat162*)&hn3[r3 + 512 + t]  = lo2(n0, n1);
    *(__nv_bfloat162*)&hn3[r3 + 1024 + t] = hi2(n0, n1);
}

// =====================================================================
// Launch
// =====================================================================
static inline int sgrid(long rows, int k3p){
    return (int)((rows * (k3p >> 3) + 255) / 256);
}

extern "C" void kernel_launch(void* const* d_in, const int* in_sizes, int n_in,
                              void* d_out, int out_size)
{
    (void)in_sizes; (void)n_in; (void)out_size;
    const float* x      = (const float*)d_in[0];
    const unsigned char* mask = (const unsigned char*)d_in[1];
    const float* Wq = (const float*)d_in[2];  const float* bq = (const float*)d_in[3];
    const float* Wk = (const float*)d_in[4];  const float* bk = (const float*)d_in[5];
    const float* Wv = (const float*)d_in[6];  const float* bv = (const float*)d_in[7];
    const float* Wo = (const float*)d_in[8];  const float* bo = (const float*)d_in[9];
    const float* in_w   = (const float*)d_in[10];
    const float* conv_w = (const float*)d_in[11];
    const float* conv_b = (const float*)d_in[12];
    const float* xproj_w= (const float*)d_in[13];
    const float* dt_w   = (const float*)d_in[14];
    const float* dt_b   = (const float*)d_in[15];
    const float* A_log  = (const float*)d_in[16];
    const float* Dssm   = (const float*)d_in[17];
    const float* outp_w = (const float*)d_in[18];
    const float* ln1g   = (const float*)d_in[19];
    const float* ln1b   = (const float*)d_in[20];
    const float* fw1    = (const float*)d_in[21];
    const float* fb1    = (const float*)d_in[22];
    const float* fw2    = (const float*)d_in[23];
    const float* fb2    = (const float*)d_in[24];
    const float* ln2g   = (const float*)d_in[25];
    const float* ln2b   = (const float*)d_in[26];
    float* out = (float*)d_out;

    float *q,*k,*v,*ao,*attn,*xz,*u,*xdbc,*dlt,*mmb,*h;
    cudaGetSymbolAddress((void**)&q,    g_q);
    cudaGetSymbolAddress((void**)&k,    g_kk);
    cudaGetSymbolAddress((void**)&v,    g_vv);
    cudaGetSymbolAddress((void**)&ao,   g_ao);
    cudaGetSymbolAddress((void**)&attn, g_attn);
    cudaGetSymbolAddress((void**)&xz,   g_xz);
    cudaGetSymbolAddress((void**)&u,    g_u);
    cudaGetSymbolAddress((void**)&xdbc, g_xdbc);
    cudaGetSymbolAddress((void**)&dlt,  g_dlt);
    cudaGetSymbolAddress((void**)&mmb,  g_mmb);
    cudaGetSymbolAddress((void**)&h,    g_h);

    bf16 *px3,*pao3,*pu3,*pxdbc3,*py3,*phn3,*pff13;
    bf16 *pwq,*pwk,*pwv,*pwo,*pwin,*pwxp,*pwdt,*pwout,*pwf1,*pwf2;
    cudaGetSymbolAddress((void**)&px3,   gx3);
    cudaGetSymbolAddress((void**)&pao3,  gao3);
    cudaGetSymbolAddress((void**)&pu3,   gu3);
    cudaGetSymbolAddress((void**)&pxdbc3,gxdbc3);
    cudaGetSymbolAddress((void**)&py3,   gy3);
    cudaGetSymbolAddress((void**)&phn3,  ghn3);
    cudaGetSymbolAddress((void**)&pff13, gff13);
    cudaGetSymbolAddress((void**)&pwq,   wq3);
    cudaGetSymbolAddress((void**)&pwk,   wk3);
    cudaGetSymbolAddress((void**)&pwv,   wv3);
    cudaGetSymbolAddress((void**)&pwo,   wo3);
    cudaGetSymbolAddress((void**)&pwin,  win3);
    cudaGetSymbolAddress((void**)&pwxp,  wxp3);
    cudaGetSymbolAddress((void**)&pwdt,  wdt3);
    cudaGetSymbolAddress((void**)&pwout, wout3);
    cudaGetSymbolAddress((void**)&pwf1,  wff13);
    cudaGetSymbolAddress((void**)&pwf2,  wff23);

    const int flashSmem = (4 * 64 * 68 + 64) * 4;
    cudaFuncSetAttribute(flash_attn, cudaFuncAttributeMaxDynamicSharedMemorySize, flashSmem);
    cudaFuncSetAttribute(hmma_gemm<0,false>, cudaFuncAttributeMaxDynamicSharedMemorySize, GEMM_SMEM);
    cudaFuncSetAttribute(hmma_gemm<1,false>, cudaFuncAttributeMaxDynamicSharedMemorySize, GEMM_SMEM);
    cudaFuncSetAttribute(hmma_gemm<2,false>, cudaFuncAttributeMaxDynamicSharedMemorySize, GEMM_SMEM);
    cudaFuncSetAttribute(hmma_gemm<3,true>,  cudaFuncAttributeMaxDynamicSharedMemorySize, GEMM_SMEM);
    cudaFuncSetAttribute(hmma_gemm<4,false>, cudaFuncAttributeMaxDynamicSharedMemorySize, GEMM_SMEM);

    // ---- attention-branch weights + x split first (GEMM lands at ncu -s 5) ----
    split3_wgt_fast<<<sgrid(512, 1536), 256>>>(Wq, 512, 512, pwq, 1536, 512);
    split3_wgt_fast<<<sgrid(512, 1536), 256>>>(Wk, 512, 512, pwk, 1536, 512);
    split3_wgt_fast<<<sgrid(512, 1536), 256>>>(Wv, 512, 512, pwv, 1536, 512);
    split3_wgt_fast<<<sgrid(512, 1536), 256>>>(Wo, 512, 512, pwo, 1536, 512);
    split3_act_fast<<<sgrid(cM, 1536), 256>>>(x, 512, 512, px3, 1536, cM);
    hmma_gemm<1,false><<<dim3(4, 72), 256, GEMM_SMEM>>>(px3, 1536, pwq, 1536, bq, nullptr, q, nullptr, 512);
    hmma_gemm<1,false><<<dim3(4, 72), 256, GEMM_SMEM>>>(px3, 1536, pwk, 1536, bk, nullptr, k, nullptr, 512);
    hmma_gemm<1,false><<<dim3(4, 72), 256, GEMM_SMEM>>>(px3, 1536, pwv, 1536, bv, nullptr, v, nullptr, 512);
    flash_attn<<<dim3(cL / 64, cB * 8), 256, flashSmem>>>(q, k, v, mask, ao);
    split3_act_fast<<<sgrid(cM, 1536), 256>>>(ao, 512, 512, pao3, 1536, cM);
    hmma_gemm<1,false><<<dim3(4, 72), 256, GEMM_SMEM>>>(pao3, 1536, pwo, 1536, bo, nullptr, attn, nullptr, 512);

    // ---- mamba branch ----
    split3_wgt_fast<<<sgrid(2048, 1536), 256>>>(in_w, 512, 512, pwin, 1536, 2048);
    hmma_gemm<0,false><<<dim3(16, 72), 256, GEMM_SMEM>>>(px3, 1536, pwin, 1536, nullptr, nullptr, xz, nullptr, 2048);
    conv_silu<<<(cM * 512) / 256, 256>>>(xz, conv_w, conv_b, u, pu3);
    split3_wgt_fast<<<sgrid(160, 3072), 256>>>(xproj_w, 1024, 1024, pwxp, 3072, 160);
    hmma_gemm<0,false><<<dim3(2, 72), 256, GEMM_SMEM>>>(pu3, 3072, pwxp, 3072, nullptr, nullptr, xdbc, nullptr, 160);
    split3_act_fast<<<sgrid(cM, 128), 256>>>(xdbc, 160, 32, pxdbc3, 128, cM);
    split3_wgt_fast<<<sgrid(1024, 128), 256>>>(dt_w, 32, 32, pwdt, 128, 1024);
    hmma_gemm<2,false><<<dim3(8, 72), 256, GEMM_SMEM>>>(pxdbc3, 128, pwdt, 128, dt_b, nullptr, dlt, nullptr, 1024);
    mamba_scan<<<dim3(cDI / 8, cB), 256>>>(dlt, u, xdbc, xz, A_log, Dssm, py3);
    split3_wgt_fast<<<sgrid(512, 3072), 256>>>(outp_w, 1024, 1024, pwout, 3072, 512);
    hmma_gemm<0,false><<<dim3(4, 72), 256, GEMM_SMEM>>>(py3, 3072, pwout, 3072, nullptr, nullptr, mmb, nullptr, 512);

    // ---- merge + LN + FFN ----
    ln_fuse<<<cM, 256>>>(x, attn, mmb, ln1g, ln1b, ln2g, ln2b, h, phn3);
    split3_wgt_fast<<<sgrid(2048, 1536), 256>>>(fw1, 512, 512, pwf1, 1536, 2048);
    hmma_gemm<3,true><<<dim3(16, 72), 256, GEMM_SMEM>>>(phn3, 1536, pwf1, 1536, fb1, nullptr, nullptr, pff13, 2048);
    split3_wgt_fast<<<sgrid(512, 6144), 256>>>(fw2, 2048, 2048, pwf2, 6144, 512);
    hmma_gemm<4,false><<<dim3(4, 72), 256, GEMM_SMEM>>>(pff13, 6144, pwf2, 6144, fb2, h, out, nullptr, 512);
}

// round 7
// speedup vs baseline: 1.3007x; 1.0423x over previous
#include <cuda_runtime.h>
#include <cuda_bf16.h>
#include <cstdint>
#include <math.h>

typedef __nv_bfloat16 bf16;

// ---------------- dims ----------------
static const int cB  = 8;
static const int cL  = 1152;      // T*W
static const int cD  = 512;
static const int cDI = 1024;
static const int cS  = 64;
static const int cDFF= 2048;
static const int cM  = 9216;      // B*L

// ---------------- fp32 workspaces ----------------
__device__ float g_qkv [cM*1536];
__device__ float g_attn[cM*cD];
__device__ float g_xz  [cM*2*cDI];
__device__ float g_u   [cM*cDI];
__device__ float g_xdbc[cM*160];
__device__ float g_dlt [cM*cDI];
__device__ float g_mmb [cM*cD];
__device__ float g_h   [cM*cD];
__device__ float g_bqkv[1536];

// ---------------- bf16 split-3 activations ----------------
__device__ bf16 gx3   [cM*1536];
__device__ bf16 gao3  [cM*1536];
__device__ bf16 gu3   [cM*3072];
__device__ bf16 gxdbc3[cM*128];
__device__ bf16 gy3   [cM*3072];
__device__ bf16 ghn3  [cM*1536];
__device__ bf16 gff13 [cM*6144];

// ---------------- bf16 split-3 weights ----------------
__device__ bf16 wqkv3[1536*1536];
__device__ bf16 wo3  [512*1536];
__device__ bf16 win3 [2048*1536];
__device__ bf16 wxp3 [160*3072];
__device__ bf16 wdt3 [1024*128];
__device__ bf16 wout3[512*3072];
__device__ bf16 wff13[2048*1536];
__device__ bf16 wff23[512*6144];

// ---------------- streams (static init: before harness checkpoints) ----
struct StreamHolder {
    cudaStream_t sB;
    cudaEvent_t evRoot, evB;
    StreamHolder(){
        cudaStreamCreateWithFlags(&sB, cudaStreamNonBlocking);
        cudaEventCreateWithFlags(&evRoot, cudaEventDisableTiming);
        cudaEventCreateWithFlags(&evB,   cudaEventDisableTiming);
    }
};
static StreamHolder g_sh;

// ---------------- helpers ----------------
__device__ __forceinline__ void fma2(unsigned long long &d, unsigned long long a, unsigned long long b){
    asm("fma.rn.f32x2 %0, %1, %2, %0;" : "+l"(d) : "l"(a), "l"(b));
}
union F4U { float4 f4; unsigned long long l[2]; float f[4]; };

__device__ __forceinline__ float softplus_f(float v){
    return fmaxf(v, 0.0f) + log1pf(__expf(-fabsf(v)));
}
__device__ __forceinline__ float gelu_f(float v){
    return 0.5f * v * (1.0f + erff(v * 0.70710678118654752f));
}
__device__ __forceinline__ bf16 hi_bf(float a){ return __float2bfloat16(a); }
__device__ __forceinline__ bf16 lo_bf(float a){
    bf16 h = __float2bfloat16(a);
    return __float2bfloat16(a - __bfloat162float(h));
}
__device__ __forceinline__ __nv_bfloat162 hi2(float a, float b){
    return __floats2bfloat162_rn(a, b);
}
__device__ __forceinline__ __nv_bfloat162 lo2(float a, float b){
    __nv_bfloat162 h = __floats2bfloat162_rn(a, b);
    return __floats2bfloat162_rn(a - __bfloat162float(h.x), b - __bfloat162float(h.y));
}

__device__ __forceinline__ uint32_t smem_u32(const void* p){
    uint32_t a;
    asm("{ .reg .u64 t; cvta.to.shared.u64 t, %1; cvt.u32.u64 %0, t; }" : "=r"(a) : "l"(p));
    return a;
}
__device__ __forceinline__ void cp16(uint32_t dst, const void* src){
    asm volatile("cp.async.cg.shared.global [%0], [%1], 16;" :: "r"(dst), "l"(src));
}
__device__ __forceinline__ void ldsm4(uint32_t &r0, uint32_t &r1, uint32_t &r2, uint32_t &r3, uint32_t addr){
    asm volatile("ldmatrix.sync.aligned.m8n8.x4.shared.b16 {%0,%1,%2,%3}, [%4];"
        : "=r"(r0), "=r"(r1), "=r"(r2), "=r"(r3) : "r"(addr));
}
__device__ __forceinline__ void mma16816(float* c, uint32_t a0, uint32_t a1, uint32_t a2, uint32_t a3,
                                         uint32_t b0, uint32_t b1){
    asm volatile("mma.sync.aligned.m16n8k16.row.col.f32.bf16.bf16.f32 "
        "{%0,%1,%2,%3}, {%4,%5,%6,%7}, {%8,%9}, {%0,%1,%2,%3};"
        : "+f"(c[0]), "+f"(c[1]), "+f"(c[2]), "+f"(c[3])
        : "r"(a0), "r"(a1), "r"(a2), "r"(a3), "r"(b0), "r"(b1));
}

// =====================================================================
// Fused weight split3 (all weights, one launch). weights: [hi | hi | lo]
// =====================================================================
struct WSpec { const float* src; bf16* dst; int K; int k3p; long rows; long base; };
struct WTab  { WSpec e[10]; };

__global__ __launch_bounds__(256) void split3_wgt_all(WTab tab)
{
    const long idx = (long)blockIdx.x * 256 + threadIdx.x;
    int i = 0;
#pragma unroll
    for (int j = 1; j < 10; j++) if (idx >= tab.e[j].base) i = j;
    const WSpec w = tab.e[i];
    const long local = idx - w.base;
    const int chunks = w.k3p >> 3;
    if (local >= w.rows * chunks) return;
    const int row = (int)(local / chunks);
    const int kc = (int)(local - (long)row * chunks);
    const int blk = (kc * 8) / w.K;
    const int within = kc * 8 - blk * w.K;
    __nv_bfloat162 o[4];
    const float* src = w.src + (size_t)row * w.K + within;
    F4U s0, s1; s0.f4 = *(const float4*)src; s1.f4 = *(const float4*)(src + 4);
    if (blk == 2){
        o[0] = lo2(s0.f[0], s0.f[1]); o[1] = lo2(s0.f[2], s0.f[3]);
        o[2] = lo2(s1.f[0], s1.f[1]); o[3] = lo2(s1.f[2], s1.f[3]);
    } else {
        o[0] = hi2(s0.f[0], s0.f[1]); o[1] = hi2(s0.f[2], s0.f[3]);
        o[2] = hi2(s1.f[0], s1.f[1]); o[3] = hi2(s1.f[2], s1.f[3]);
    }
    *(uint4*)&w.dst[(size_t)row * w.k3p + kc * 8] = *(uint4*)o;
}

// bias concat for fused QKV
__global__ void biascat(const float* __restrict__ bq, const float* __restrict__ bk,
                        const float* __restrict__ bv, float* __restrict__ o)
{
    const int i = blockIdx.x * 256 + threadIdx.x;
    if (i >= 1536) return;
    o[i] = (i < 512) ? bq[i] : (i < 1024) ? bk[i - 512] : bv[i - 1024];
}

// activation split3: [hi | lo | hi] (+zero pad block)
__global__ __launch_bounds__(256) void split3_act_fast(
    const float* __restrict__ in, int lda, int K,
    bf16* __restrict__ out, int k3p, int rows)
{
    const int chunks = k3p >> 3;
    const long idx = (long)blockIdx.x * 256 + threadIdx.x;
    if (idx >= (long)rows * chunks) return;
    const int row = (int)(idx / chunks);
    const int kc = (int)(idx - (long)row * chunks);
    const int blk = (kc * 8) / K;
    const int within = kc * 8 - blk * K;
    __nv_bfloat162 o[4];
    if (blk >= 3){
        o[0] = o[1] = o[2] = o[3] = __floats2bfloat162_rn(0.f, 0.f);
    } else {
        const float* src = in + (size_t)row * lda + within;
        F4U s0, s1; s0.f4 = *(const float4*)src; s1.f4 = *(const float4*)(src + 4);
        if (blk == 1){
            o[0] = lo2(s0.f[0], s0.f[1]); o[1] = lo2(s0.f[2], s0.f[3]);
            o[2] = lo2(s1.f[0], s1.f[1]); o[3] = lo2(s1.f[2], s1.f[3]);
        } else {
            o[0] = hi2(s0.f[0], s0.f[1]); o[1] = hi2(s0.f[2], s0.f[3]);
            o[2] = hi2(s1.f[0], s1.f[1]); o[3] = hi2(s1.f[2], s1.f[3]);
        }
    }
    *(uint4*)&out[(size_t)row * k3p + kc * 8] = *(uint4*)o;
}

// =====================================================================
// HMMA GEMM, 3-stage cp.async pipeline (BK=32), CTA 128x128, 8 warps.
// EPI: 0=none 1=bias 2=bias+softplus 3=bias+gelu 4=bias+residual
// OUT3: bf16 [hi|lo|hi] triple output
// =====================================================================
#define TILE_BYTES 20480
#define GEMM_SMEM  (3 * TILE_BYTES)
template<int EPI, bool OUT3>
__global__ __launch_bounds__(256, 2) void hmma_gemm(
    const bf16* __restrict__ A3, int lda3,
    const bf16* __restrict__ W3, int k3p,
    const float* __restrict__ bias, const float* __restrict__ res,
    float* __restrict__ C, bf16* __restrict__ C3, int N)
{
    extern __shared__ char smem[];
    const uint32_t sb = smem_u32(smem);
    const int tid = threadIdx.x;
    const int wid = tid >> 5, lane = tid & 31;
    const int bm = blockIdx.y * 128;
    const int bn = blockIdx.x * 128;
    const int wm = wid & 1, wn = wid >> 1;

    float acc[4][4][4];
#pragma unroll
    for (int i = 0; i < 4; i++)
#pragma unroll
        for (int j = 0; j < 4; j++)
#pragma unroll
            for (int e = 0; e < 4; e++) acc[i][j][e] = 0.f;

    const int NC = k3p >> 5;
    const int c0 = tid;

    auto load_tile = [&](int ci, uint32_t sbase){
#pragma unroll
        for (int cc = 0; cc < 4; cc++){
            const int c = c0 + cc * 256;
            if (c < 512){
                const int row = c >> 2, ch = c & 3;
                cp16(sbase + row * 80 + ch * 16,
                     &A3[(size_t)(bm + row) * lda3 + ci * 32 + ch * 8]);
            } else {
                const int c2 = c - 512;
                const int row = c2 >> 2, ch = c2 & 3;
                int br = bn + row; if (br >= N) br = N - 1;
                cp16(sbase + 128 * 80 + row * 80 + ch * 16,
                     &W3[(size_t)br * k3p + ci * 32 + ch * 8]);
            }
        }
        asm volatile("cp.async.commit_group;" ::: "memory");
    };

    load_tile(0, sb);
    if (NC > 1) load_tile(1, sb + TILE_BYTES);

    const uint32_t aOff = (uint32_t)((wm * 64 + (lane & 15)) * 80 + (lane >> 4) * 16);
    const uint32_t bOff = (uint32_t)(128 * 80 +
                          (wn * 32 + (lane & 7) + ((lane & 16) ? 8 : 0)) * 80 +
                          ((lane >> 3) & 1) * 16);

    for (int ci = 0; ci < NC; ci++){
        if (ci + 1 < NC) asm volatile("cp.async.wait_group 1;" ::: "memory");
        else             asm volatile("cp.async.wait_group 0;" ::: "memory");
        __syncthreads();
        if (ci + 2 < NC){
            const int nb = (ci + 2) % 3;
            load_tile(ci + 2, sb + (uint32_t)nb * TILE_BYTES);
        }
        const uint32_t cur = sb + (uint32_t)(ci % 3) * TILE_BYTES;

#pragma unroll
        for (int s = 0; s < 2; s++){
            uint32_t a[4][4];
#pragma unroll
            for (int i = 0; i < 4; i++)
                ldsm4(a[i][0], a[i][1], a[i][2], a[i][3], cur + aOff + i * (16 * 80) + s * 32);
            uint32_t b0, b1, b2, b3, b4, b5, b6, b7;
            ldsm4(b0, b1, b2, b3, cur + bOff + s * 32);
            ldsm4(b4, b5, b6, b7, cur + bOff + 16 * 80 + s * 32);
#pragma unroll
            for (int i = 0; i < 4; i++){
                mma16816(acc[i][0], a[i][0], a[i][1], a[i][2], a[i][3], b0, b1);
                mma16816(acc[i][1], a[i][0], a[i][1], a[i][2], a[i][3], b2, b3);
                mma16816(acc[i][2], a[i][0], a[i][1], a[i][2], a[i][3], b4, b5);
                mma16816(acc[i][3], a[i][0], a[i][1], a[i][2], a[i][3], b6, b7);
            }
        }
    }

    const int t4 = lane >> 2, tp = (lane & 3) * 2;
#pragma unroll
    for (int i = 0; i < 4; i++){
#pragma unroll
        for (int j = 0; j < 4; j++){
            const int col = bn + wn * 32 + j * 8 + tp;
            if (col >= N) continue;
            const int row0 = bm + wm * 64 + i * 16 + t4;
            float v0 = acc[i][j][0], v1 = acc[i][j][1];
            float v2 = acc[i][j][2], v3 = acc[i][j][3];
            if (EPI >= 1){
                const float bb0 = bias[col], bb1 = bias[col + 1];
                v0 += bb0; v1 += bb1; v2 += bb0; v3 += bb1;
            }
            if (EPI == 2){ v0 = softplus_f(v0); v1 = softplus_f(v1); v2 = softplus_f(v2); v3 = softplus_f(v3); }
            if (EPI == 3){ v0 = gelu_f(v0); v1 = gelu_f(v1); v2 = gelu_f(v2); v3 = gelu_f(v3); }
            if (EPI == 4){
                v0 += res[(size_t)row0 * N + col];
                v1 += res[(size_t)row0 * N + col + 1];
                v2 += res[(size_t)(row0 + 8) * N + col];
                v3 += res[(size_t)(row0 + 8) * N + col + 1];
            }
            if (OUT3){
                const size_t r0 = (size_t)row0 * (3 * N), r1 = (size_t)(row0 + 8) * (3 * N);
                *(__nv_bfloat162*)&C3[r0 + col]         = hi2(v0, v1);
                *(__nv_bfloat162*)&C3[r0 + N + col]     = lo2(v0, v1);
                *(__nv_bfloat162*)&C3[r0 + 2 * N + col] = hi2(v0, v1);
                *(__nv_bfloat162*)&C3[r1 + col]         = hi2(v2, v3);
                *(__nv_bfloat162*)&C3[r1 + N + col]     = lo2(v2, v3);
                *(__nv_bfloat162*)&C3[r1 + 2 * N + col] = hi2(v2, v3);
            } else {
                *(float2*)&C[(size_t)row0 * N + col]       = make_float2(v0, v1);
                *(float2*)&C[(size_t)(row0 + 8) * N + col] = make_float2(v2, v3);
            }
        }
    }
}

// =====================================================================
// Flash attention: reads fused qkv [M,1536]; writes ao3 split directly.
// =====================================================================
__global__ __launch_bounds__(256) void flash_attn(
    const float* __restrict__ QKV, const unsigned char* __restrict__ mask,
    bf16* __restrict__ AO3)
{
    extern __shared__ float smx[];
    float* Qs = smx;                 // 64*68
    float* Ks = Qs + 64 * 68;
    float* Vs = Ks + 64 * 68;
    float* Ps = Vs + 64 * 68;
    float* msk = Ps + 64 * 68;       // 64

    const int tid = threadIdx.x, tx = tid & 15, ty = tid >> 4;
    const int bh = blockIdx.y;
    const int b = bh >> 3, h = bh & 7;
    const int q0 = blockIdx.x * 64;
    const size_t basebl = (size_t)b * cL;

    for (int i = tid; i < 1024; i += 256){
        const int r = i >> 4, c = (i & 15) * 4;
        *(float4*)&Qs[r * 68 + c] = *(const float4*)&QKV[(basebl + q0 + r) * 1536 + h * 64 + c];
    }

    float o[4][4], mrow[4], lrow[4];
#pragma unroll
    for (int i = 0; i < 4; i++){
        mrow[i] = -1e30f; lrow[i] = 0.f;
#pragma unroll
        for (int j = 0; j < 4; j++) o[i][j] = 0.f;
    }

    for (int jt = 0; jt < cL / 64; jt++){
        __syncthreads();
        const int k0 = jt * 64;
        for (int i = tid; i < 1024; i += 256){
            const int r = i >> 4, c = (i & 15) * 4;
            *(float4*)&Ks[r * 68 + c] = *(const float4*)&QKV[(basebl + k0 + r) * 1536 + 512 + h * 64 + c];
            *(float4*)&Vs[r * 68 + c] = *(const float4*)&QKV[(basebl + k0 + r) * 1536 + 1024 + h * 64 + c];
        }
        if (tid < 64) msk[tid] = mask[b * cL + k0 + tid] ? -1e30f : 0.0f;
        __syncthreads();

        unsigned long long s2[4][4];
#pragma unroll
        for (int i = 0; i < 4; i++)
#pragma unroll
            for (int j = 0; j < 4; j++) s2[i][j] = 0ULL;

#pragma unroll 4
        for (int k = 0; k < 64; k += 4){
            F4U qv[4], kv[4];
#pragma unroll
            for (int i = 0; i < 4; i++) qv[i].f4 = *(const float4*)&Qs[(ty * 4 + i) * 68 + k];
#pragma unroll
            for (int j = 0; j < 4; j++) kv[j].f4 = *(const float4*)&Ks[(tx * 4 + j) * 68 + k];
#pragma unroll
            for (int i = 0; i < 4; i++)
#pragma unroll
                for (int j = 0; j < 4; j++){
                    fma2(s2[i][j], qv[i].l[0], kv[j].l[0]);
                    fma2(s2[i][j], qv[i].l[1], kv[j].l[1]);
                }
        }

#pragma unroll
        for (int i = 0; i < 4; i++){
            float sv[4];
#pragma unroll
            for (int j = 0; j < 4; j++){
                const unsigned long long t = s2[i][j];
                const float slo = __uint_as_float((unsigned)(t & 0xffffffffULL));
                const float shi = __uint_as_float((unsigned)(t >> 32));
                sv[j] = (slo + shi) * 0.125f + msk[tx * 4 + j];
            }
            float rm = fmaxf(fmaxf(sv[0], sv[1]), fmaxf(sv[2], sv[3]));
#pragma unroll
            for (int off = 1; off < 16; off <<= 1)
                rm = fmaxf(rm, __shfl_xor_sync(0xffffffffu, rm, off));
            const float mnew = fmaxf(mrow[i], rm);
            const float fac = __expf(mrow[i] - mnew);
            float rs = 0.f;
#pragma unroll
            for (int j = 0; j < 4; j++){
                const float p = __expf(sv[j] - mnew);
                rs += p;
                Ps[(ty * 4 + i) * 68 + tx * 4 + j] = p;
            }
#pragma unroll
            for (int off = 1; off < 16; off <<= 1)
                rs += __shfl_xor_sync(0xffffffffu, rs, off);
            lrow[i] = lrow[i] * fac + rs;
            mrow[i] = mnew;
#pragma unroll
            for (int j = 0; j < 4; j++) o[i][j] *= fac;
        }
        __syncthreads();

#pragma unroll 4
        for (int n = 0; n < 64; n += 4){
            F4U pv[4], vr[4];
#pragma unroll
            for (int i = 0; i < 4; i++) pv[i].f4 = *(const float4*)&Ps[(ty * 4 + i) * 68 + n];
#pragma unroll
            for (int jj = 0; jj < 4; jj++) vr[jj].f4 = *(const float4*)&Vs[(n + jj) * 68 + tx * 4];
#pragma unroll
            for (int i = 0; i < 4; i++)
#pragma unroll
                for (int e = 0; e < 4; e++)
                    o[i][e] += pv[i].f[0]*vr[0].f[e] + pv[i].f[1]*vr[1].f[e]
                             + pv[i].f[2]*vr[2].f[e] + pv[i].f[3]*vr[3].f[e];
        }
    }

#pragma unroll
    for (int i = 0; i < 4; i++){
        const float inv = 1.0f / lrow[i];
        const float a0 = o[i][0] * inv, a1 = o[i][1] * inv;
        const float a2 = o[i][2] * inv, a3 = o[i][3] * inv;
        const size_t r3 = (basebl + q0 + ty * 4 + i) * 1536;
        const int col = h * 64 + tx * 4;
        *(__nv_bfloat162*)&AO3[r3 + col]            = hi2(a0, a1);
        *(__nv_bfloat162*)&AO3[r3 + col + 2]        = hi2(a2, a3);
        *(__nv_bfloat162*)&AO3[r3 + 512 + col]      = lo2(a0, a1);
        *(__nv_bfloat162*)&AO3[r3 + 512 + col + 2]  = lo2(a2, a3);
        *(__nv_bfloat162*)&AO3[r3 + 1024 + col]     = hi2(a0, a1);
        *(__nv_bfloat162*)&AO3[r3 + 1024 + col + 2] = hi2(a2, a3);
    }
}

// =====================================================================
// Depthwise causal conv (KC=4) + SiLU; writes u (fp32) + u3 (triple)
// =====================================================================
__global__ __launch_bounds__(256) void conv_silu(
    const float* __restrict__ xz, const float* __restrict__ cw,
    const float* __restrict__ cb, float* __restrict__ u, bf16* __restrict__ u3)
{
    const long idx = (long)blockIdx.x * 256 + threadIdx.x;  // over M*512
    const int c = (int)(idx & 511) * 2;
    const int m = (int)(idx >> 9);
    const int b = m / cL, l = m % cL;
    float a0 = cb[c], a1 = cb[c + 1];
#pragma unroll
    for (int k = 0; k < 4; k++){
        const int ls = l + k - 3;
        if (ls >= 0){
            const size_t row = (size_t)(b * cL + ls) * (2 * cDI);
            a0 += xz[row + c]     * cw[c * 4 + k];
            a1 += xz[row + c + 1] * cw[(c + 1) * 4 + k];
        }
    }
    a0 = a0 / (1.0f + __expf(-a0));
    a1 = a1 / (1.0f + __expf(-a1));
    *(float2*)&u[(size_t)m * cDI + c] = make_float2(a0, a1);
    const size_t r3 = (size_t)m * 3072;
    *(__nv_bfloat162*)&u3[r3 + c]        = hi2(a0, a1);
    *(__nv_bfloat162*)&u3[r3 + 1024 + c] = lo2(a0, a1);
    *(__nv_bfloat162*)&u3[r3 + 2048 + c] = hi2(a0, a1);
}

// =====================================================================
// Selective scan: warp per (b, d); writes y3 triple
// =====================================================================
__global__ __launch_bounds__(256) void mamba_scan(
    const float* __restrict__ delta, const float* __restrict__ u,
    const float* __restrict__ xdbc, const float* __restrict__ xz,
    const float* __restrict__ A_log, const float* __restrict__ Dssm,
    bf16* __restrict__ y3)
{
    const int warp = threadIdx.x >> 5, lane = threadIdx.x & 31;
    const int d = blockIdx.x * 8 + warp;
    const int b = blockIdx.y;
    const float a0 = -__expf(A_log[d * cS + 2 * lane]);
    const float a1 = -__expf(A_log[d * cS + 2 * lane + 1]);
    const float Dd = Dssm[d];
    float h0 = 0.f, h1 = 0.f;
    const size_t base = (size_t)b * cL;

    for (int t = 0; t < cL; t++){
        const size_t m = base + t;
        const float dt = __ldg(&delta[m * cDI + d]);
        const float uu = __ldg(&u[m * cDI + d]);
        const float2 Bv = *(const float2*)&xdbc[m * 160 + 32 + 2 * lane];
        const float2 Cv = *(const float2*)&xdbc[m * 160 + 96 + 2 * lane];
        const float du = dt * uu;
        h0 = h0 * __expf(dt * a0) + du * Bv.x;
        h1 = h1 * __expf(dt * a1) + du * Bv.y;
        float p = h0 * Cv.x + h1 * Cv.y;
        p += __shfl_xor_sync(0xffffffffu, p, 16);
        p += __shfl_xor_sync(0xffffffffu, p, 8);
        p += __shfl_xor_sync(0xffffffffu, p, 4);
        p += __shfl_xor_sync(0xffffffffu, p, 2);
        p += __shfl_xor_sync(0xffffffffu, p, 1);
        if (lane == 0){
            const float z = xz[m * (2 * cDI) + cDI + d];
            float yv = p + uu * Dd;
            yv *= z / (1.0f + __expf(-z));
            const size_t r3 = m * 3072;
            y3[r3 + d]        = hi_bf(yv);
            y3[r3 + 1024 + d] = lo_bf(yv);
            y3[r3 + 2048 + d] = hi_bf(yv);
        }
    }
}

// =====================================================================
// Fused residual + LN1 + LN2; writes h (fp32) and hn3 (triple)
// =====================================================================
__device__ __forceinline__ float blockSum256(float v, float* red){
#pragma unroll
    for (int off = 16; off > 0; off >>= 1) v += __shfl_xor_sync(0xffffffffu, v, off);
    if ((threadIdx.x & 31) == 0) red[threadIdx.x >> 5] = v;
    __syncthreads();
    const float s = red[0]+red[1]+red[2]+red[3]+red[4]+red[5]+red[6]+red[7];
    __syncthreads();
    return s;
}

__global__ __launch_bounds__(256) void ln_fuse(
    const float* __restrict__ xf, const float* __restrict__ attn, const float* __restrict__ mamba,
    const float* __restrict__ g1, const float* __restrict__ b1,
    const float* __restrict__ g2, const float* __restrict__ b2,
    float* __restrict__ h, bf16* __restrict__ hn3)
{
    __shared__ float red[8];
    const size_t m = blockIdx.x;
    const int t = threadIdx.x * 2;
    const size_t r = m * cD;
    float v0 = xf[r + t]     + attn[r + t]     + mamba[r + t];
    float v1 = xf[r + t + 1] + attn[r + t + 1] + mamba[r + t + 1];

    const float mean = blockSum256(v0 + v1, red) * (1.0f / cD);
    const float d0 = v0 - mean, d1 = v1 - mean;
    const float var = blockSum256(d0 * d0 + d1 * d1, red) * (1.0f / cD);
    const float inv = rsqrtf(var + 1e-5f);
    const float h0 = d0 * inv * g1[t]     + b1[t];
    const float h1 = d1 * inv * g1[t + 1] + b1[t + 1];
    *(float2*)&h[r + t] = make_float2(h0, h1);

    const float mean2 = blockSum256(h0 + h1, red) * (1.0f / cD);
    const float e0 = h0 - mean2, e1 = h1 - mean2;
    const float var2 = blockSum256(e0 * e0 + e1 * e1, red) * (1.0f / cD);
    const float inv2 = rsqrtf(var2 + 1e-6f);
    const float n0 = e0 * inv2 * g2[t]     + b2[t];
    const float n1 = e1 * inv2 * g2[t + 1] + b2[t + 1];
    const size_t r3 = m * 1536;
    *(__nv_bfloat162*)&hn3[r3 + t]        = hi2(n0, n1);
    *(__nv_bfloat162*)&hn3[r3 + 512 + t]  = lo2(n0, n1);
    *(__nv_bfloat162*)&hn3[r3 + 1024 + t] = hi2(n0, n1);
}

// =====================================================================
// Launch
// =====================================================================
static inline int sgrid(long rows, int k3p){
    return (int)((rows * (k3p >> 3) + 255) / 256);
}

extern "C" void kernel_launch(void* const* d_in, const int* in_sizes, int n_in,
                              void* d_out, int out_size)
{
    (void)in_sizes; (void)n_in; (void)out_size;
    const float* x      = (const float*)d_in[0];
    const unsigned char* mask = (const unsigned char*)d_in[1];
    const float* Wq = (const float*)d_in[2];  const float* bq = (const float*)d_in[3];
    const float* Wk = (const float*)d_in[4];  const float* bk = (const float*)d_in[5];
    const float* Wv = (const float*)d_in[6];  const float* bv = (const float*)d_in[7];
    const float* Wo = (const float*)d_in[8];  const float* bo = (const float*)d_in[9];
    const float* in_w   = (const float*)d_in[10];
    const float* conv_w = (const float*)d_in[11];
    const float* conv_b = (const float*)d_in[12];
    const float* xproj_w= (const float*)d_in[13];
    const float* dt_w   = (const float*)d_in[14];
    const float* dt_b   = (const float*)d_in[15];
    const float* A_log  = (const float*)d_in[16];
    const float* Dssm   = (const float*)d_in[17];
    const float* outp_w = (const float*)d_in[18];
    const float* ln1g   = (const float*)d_in[19];
    const float* ln1b   = (const float*)d_in[20];
    const float* fw1    = (const float*)d_in[21];
    const float* fb1    = (const float*)d_in[22];
    const float* fw2    = (const float*)d_in[23];
    const float* fb2    = (const float*)d_in[24];
    const float* ln2g   = (const float*)d_in[25];
    const float* ln2b   = (const float*)d_in[26];
    float* out = (float*)d_out;

    float *qkv,*attn,*xz,*u,*xdbc,*dlt,*mmb,*h,*bqkv;
    cudaGetSymbolAddress((void**)&qkv,  g_qkv);
    cudaGetSymbolAddress((void**)&attn, g_attn);
    cudaGetSymbolAddress((void**)&xz,   g_xz);
    cudaGetSymbolAddress((void**)&u,    g_u);
    cudaGetSymbolAddress((void**)&xdbc, g_xdbc);
    cudaGetSymbolAddress((void**)&dlt,  g_dlt);
    cudaGetSymbolAddress((void**)&mmb,  g_mmb);
    cudaGetSymbolAddress((void**)&h,    g_h);
    cudaGetSymbolAddress((void**)&bqkv, g_bqkv);

    bf16 *px3,*pao3,*pu3,*pxdbc3,*py3,*phn3,*pff13;
    bf16 *pwqkv,*pwo,*pwin,*pwxp,*pwdt,*pwout,*pwf1,*pwf2;
    cudaGetSymbolAddress((void**)&px3,   gx3);
    cudaGetSymbolAddress((void**)&pao3,  gao3);
    cudaGetSymbolAddress((void**)&pu3,   gu3);
    cudaGetSymbolAddress((void**)&pxdbc3,gxdbc3);
    cudaGetSymbolAddress((void**)&py3,   gy3);
    cudaGetSymbolAddress((void**)&phn3,  ghn3);
    cudaGetSymbolAddress((void**)&pff13, gff13);
    cudaGetSymbolAddress((void**)&pwqkv, wqkv3);
    cudaGetSymbolAddress((void**)&pwo,   wo3);
    cudaGetSymbolAddress((void**)&pwin,  win3);
    cudaGetSymbolAddress((void**)&pwxp,  wxp3);
    cudaGetSymbolAddress((void**)&pwdt,  wdt3);
    cudaGetSymbolAddress((void**)&pwout, wout3);
    cudaGetSymbolAddress((void**)&pwf1,  wff13);
    cudaGetSymbolAddress((void**)&pwf2,  wff23);

    const int flashSmem = (4 * 64 * 68 + 64) * 4;
    cudaFuncSetAttribute(flash_attn, cudaFuncAttributeMaxDynamicSharedMemorySize, flashSmem);
    cudaFuncSetAttribute(hmma_gemm<0,false>, cudaFuncAttributeMaxDynamicSharedMemorySize, GEMM_SMEM);
    cudaFuncSetAttribute(hmma_gemm<1,false>, cudaFuncAttributeMaxDynamicSharedMemorySize, GEMM_SMEM);
    cudaFuncSetAttribute(hmma_gemm<2,false>, cudaFuncAttributeMaxDynamicSharedMemorySize, GEMM_SMEM);
    cudaFuncSetAttribute(hmma_gemm<3,true>,  cudaFuncAttributeMaxDynamicSharedMemorySize, GEMM_SMEM);
    cudaFuncSetAttribute(hmma_gemm<4,false>, cudaFuncAttributeMaxDynamicSharedMemorySize, GEMM_SMEM);

    // ---- build fused weight-split table ----
    WTab tab;
    long base = 0;
    auto add = [&](int i, const float* src, bf16* dst, int K, int k3p, long rows){
        tab.e[i] = {src, dst, K, k3p, rows, base};
        base += rows * (k3p >> 3);
    };
    add(0, Wq,      pwqkv,               512,  1536, 512);
    add(1, Wk,      pwqkv + 512 * 1536,  512,  1536, 512);
    add(2, Wv,      pwqkv + 1024 * 1536, 512,  1536, 512);
    add(3, Wo,      pwo,                 512,  1536, 512);
    add(4, in_w,    pwin,                512,  1536, 2048);
    add(5, xproj_w, pwxp,                1024, 3072, 160);
    add(6, dt_w,    pwdt,                32,   128,  1024);
    add(7, outp_w,  pwout,               1024, 3072, 512);
    add(8, fw1,     pwf1,                512,  1536, 2048);
    add(9, fw2,     pwf2,                2048, 6144, 512);
    const int wgrid = (int)((base + 255) / 256);

    cudaStream_t s0 = 0, sB = g_sh.sB;

    // 0: all weight splits
    split3_wgt_all<<<wgrid, 256, 0, s0>>>(tab);
    // 1: bias concat
    biascat<<<6, 256, 0, s0>>>(bq, bk, bv, bqkv);
    // 2: x split
    split3_act_fast<<<sgrid(cM, 1536), 256, 0, s0>>>(x, 512, 512, px3, 1536, cM);

    // fork mamba branch
    cudaEventRecord(g_sh.evRoot, s0);
    cudaStreamWaitEvent(sB, g_sh.evRoot, 0);

    // 3: fused QKV GEMM (ncu target)
    hmma_gemm<1,false><<<dim3(12, 72), 256, GEMM_SMEM, s0>>>(px3, 1536, pwqkv, 1536, bqkv, nullptr, qkv, nullptr, 1536);
    // mamba branch on sB
    hmma_gemm<0,false><<<dim3(16, 72), 256, GEMM_SMEM, sB>>>(px3, 1536, pwin, 1536, nullptr, nullptr, xz, nullptr, 2048);
    // attention on s0
    flash_attn<<<dim3(cL / 64, cB * 8), 256, flashSmem, s0>>>(qkv, mask, pao3);
    conv_silu<<<(cM * 512) / 256, 256, 0, sB>>>(xz, conv_w, conv_b, u, pu3);
    hmma_gemm<0,false><<<dim3(2, 72), 256, GEMM_SMEM, sB>>>(pu3, 3072, pwxp, 3072, nullptr, nullptr, xdbc, nullptr, 160);
    hmma_gemm<1,false><<<dim3(4, 72), 256, GEMM_SMEM, s0>>>(pao3, 1536, pwo, 1536, bo, nullptr, attn, nullptr, 512);
    split3_act_fast<<<sgrid(cM, 128), 256, 0, sB>>>(xdbc, 160, 32, pxdbc3, 128, cM);
    hmma_gemm<2,false><<<dim3(8, 72), 256, GEMM_SMEM, sB>>>(pxdbc3, 128, pwdt, 128, dt_b, nullptr, dlt, nullptr, 1024);
    mamba_scan<<<dim3(cDI / 8, cB), 256, 0, sB>>>(dlt, u, xdbc, xz, A_log, Dssm, py3);
    hmma_gemm<0,false><<<dim3(4, 72), 256, GEMM_SMEM, sB>>>(py3, 3072, pwout, 3072, nullptr, nullptr, mmb, nullptr, 512);
    cudaEventRecord(g_sh.evB, sB);

    // join
    cudaStreamWaitEvent(s0, g_sh.evB, 0);
    ln_fuse<<<cM, 256, 0, s0>>>(x, attn, mmb, ln1g, ln1b, ln2g, ln2b, h, phn3);
    hmma_gemm<3,true><<<dim3(16, 72), 256, GEMM_SMEM, s0>>>(phn3, 1536, pwf1, 1536, fb1, nullptr, nullptr, pff13, 2048);
    hmma_gemm<4,false><<<dim3(4, 72), 256, GEMM_SMEM, s0>>>(pff13, 6144, pwf2, 6144, fb2, h, out, nullptr, 512);
}

// round 8
// speedup vs baseline: 1.4905x; 1.1460x over previous
#include <cuda_runtime.h>
#include <cuda_bf16.h>
#include <cstdint>
#include <math.h>

typedef __nv_bfloat16 bf16;

// ---------------- dims ----------------
static const int cB  = 8;
static const int cL  = 1152;      // T*W
static const int cD  = 512;
static const int cDI = 1024;
static const int cS  = 64;
static const int cDFF= 2048;
static const int cM  = 9216;      // B*L

// ---------------- fp32 workspaces ----------------
__device__ float g_qkv [cM*1536];
__device__ float g_attn[cM*cD];
__device__ float g_xz  [cM*2*cDI];
__device__ float g_u   [cM*cDI];
__device__ float g_xdbc[cM*160];
__device__ float g_dlt [cM*cDI];
__device__ float g_mmb [cM*cD];
__device__ float g_h   [cM*cD];
__device__ float g_bqkv[1536];

// ---------------- bf16 split-3 activations ----------------
__device__ bf16 gx3   [cM*1536];
__device__ bf16 gao3  [cM*1536];
__device__ bf16 gu3   [cM*3072];
__device__ bf16 gxdbc3[cM*128];
__device__ bf16 gy3   [cM*3072];
__device__ bf16 ghn3  [cM*1536];
__device__ bf16 gff13 [cM*6144];

// ---------------- bf16 split-3 weights ----------------
__device__ bf16 wqkv3[1536*1536];
__device__ bf16 wo3  [512*1536];
__device__ bf16 win3 [2048*1536];
__device__ bf16 wxp3 [160*3072];
__device__ bf16 wdt3 [1024*128];
__device__ bf16 wout3[512*3072];
__device__ bf16 wff13[2048*1536];
__device__ bf16 wff23[512*6144];

// ---------------- streams (static init: before harness checkpoints) ----
struct StreamHolder {
    cudaStream_t sB;
    cudaEvent_t evRoot, evB;
    StreamHolder(){
        cudaStreamCreateWithFlags(&sB, cudaStreamNonBlocking);
        cudaEventCreateWithFlags(&evRoot, cudaEventDisableTiming);
        cudaEventCreateWithFlags(&evB,   cudaEventDisableTiming);
    }
};
static StreamHolder g_sh;

// ---------------- helpers ----------------
union F4U { float4 f4; unsigned long long l[2]; float f[4]; };

__device__ __forceinline__ float softplus_f(float v){
    return fmaxf(v, 0.0f) + log1pf(__expf(-fabsf(v)));
}
__device__ __forceinline__ float gelu_f(float v){
    return 0.5f * v * (1.0f + erff(v * 0.70710678118654752f));
}
__device__ __forceinline__ bf16 hi_bf(float a){ return __float2bfloat16(a); }
__device__ __forceinline__ bf16 lo_bf(float a){
    bf16 h = __float2bfloat16(a);
    return __float2bfloat16(a - __bfloat162float(h));
}
__device__ __forceinline__ __nv_bfloat162 hi2(float a, float b){
    return __floats2bfloat162_rn(a, b);
}
__device__ __forceinline__ __nv_bfloat162 lo2(float a, float b){
    __nv_bfloat162 h = __floats2bfloat162_rn(a, b);
    return __floats2bfloat162_rn(a - __bfloat162float(h.x), b - __bfloat162float(h.y));
}

__device__ __forceinline__ uint32_t smem_u32(const void* p){
    uint32_t a;
    asm("{ .reg .u64 t; cvta.to.shared.u64 t, %1; cvt.u32.u64 %0, t; }" : "=r"(a) : "l"(p));
    return a;
}
__device__ __forceinline__ void cp16(uint32_t dst, const void* src){
    asm volatile("cp.async.cg.shared.global [%0], [%1], 16;" :: "r"(dst), "l"(src));
}
__device__ __forceinline__ void ldsm4(uint32_t &r0, uint32_t &r1, uint32_t &r2, uint32_t &r3, uint32_t addr){
    asm volatile("ldmatrix.sync.aligned.m8n8.x4.shared.b16 {%0,%1,%2,%3}, [%4];"
        : "=r"(r0), "=r"(r1), "=r"(r2), "=r"(r3) : "r"(addr));
}
__device__ __forceinline__ void ldsm4t(uint32_t &r0, uint32_t &r1, uint32_t &r2, uint32_t &r3, uint32_t addr){
    asm volatile("ldmatrix.sync.aligned.m8n8.x4.trans.shared.b16 {%0,%1,%2,%3}, [%4];"
        : "=r"(r0), "=r"(r1), "=r"(r2), "=r"(r3) : "r"(addr));
}
__device__ __forceinline__ void mma16816(float* c, uint32_t a0, uint32_t a1, uint32_t a2, uint32_t a3,
                                         uint32_t b0, uint32_t b1){
    asm volatile("mma.sync.aligned.m16n8k16.row.col.f32.bf16.bf16.f32 "
        "{%0,%1,%2,%3}, {%4,%5,%6,%7}, {%8,%9}, {%0,%1,%2,%3};"
        : "+f"(c[0]), "+f"(c[1]), "+f"(c[2]), "+f"(c[3])
        : "r"(a0), "r"(a1), "r"(a2), "r"(a3), "r"(b0), "r"(b1));
}

// =====================================================================
// Fused weight split3 (all weights, one launch). weights: [hi | hi | lo]
// =====================================================================
struct WSpec { const float* src; bf16* dst; int K; int k3p; long rows; long base; };
struct WTab  { WSpec e[10]; };

__global__ __launch_bounds__(256) void split3_wgt_all(WTab tab)
{
    const long idx = (long)blockIdx.x * 256 + threadIdx.x;
    int i = 0;
#pragma unroll
    for (int j = 1; j < 10; j++) if (idx >= tab.e[j].base) i = j;
    const WSpec w = tab.e[i];
    const long local = idx - w.base;
    const int chunks = w.k3p >> 3;
    if (local >= w.rows * chunks) return;
    const int row = (int)(local / chunks);
    const int kc = (int)(local - (long)row * chunks);
    const int blk = (kc * 8) / w.K;
    const int within = kc * 8 - blk * w.K;
    __nv_bfloat162 o[4];
    const float* src = w.src + (size_t)row * w.K + within;
    F4U s0, s1; s0.f4 = *(const float4*)src; s1.f4 = *(const float4*)(src + 4);
    if (blk == 2){
        o[0] = lo2(s0.f[0], s0.f[1]); o[1] = lo2(s0.f[2], s0.f[3]);
        o[2] = lo2(s1.f[0], s1.f[1]); o[3] = lo2(s1.f[2], s1.f[3]);
    } else {
        o[0] = hi2(s0.f[0], s0.f[1]); o[1] = hi2(s0.f[2], s0.f[3]);
        o[2] = hi2(s1.f[0], s1.f[1]); o[3] = hi2(s1.f[2], s1.f[3]);
    }
    *(uint4*)&w.dst[(size_t)row * w.k3p + kc * 8] = *(uint4*)o;
}

// bias concat for fused QKV
__global__ void biascat(const float* __restrict__ bq, const float* __restrict__ bk,
                        const float* __restrict__ bv, float* __restrict__ o)
{
    const int i = blockIdx.x * 256 + threadIdx.x;
    if (i >= 1536) return;
    o[i] = (i < 512) ? bq[i] : (i < 1024) ? bk[i - 512] : bv[i - 1024];
}

// activation split3: [hi | lo | hi] (+zero pad block)
__global__ __launch_bounds__(256) void split3_act_fast(
    const float* __restrict__ in, int lda, int K,
    bf16* __restrict__ out, int k3p, int rows)
{
    const int chunks = k3p >> 3;
    const long idx = (long)blockIdx.x * 256 + threadIdx.x;
    if (idx >= (long)rows * chunks) return;
    const int row = (int)(idx / chunks);
    const int kc = (int)(idx - (long)row * chunks);
    const int blk = (kc * 8) / K;
    const int within = kc * 8 - blk * K;
    __nv_bfloat162 o[4];
    if (blk >= 3){
        o[0] = o[1] = o[2] = o[3] = __floats2bfloat162_rn(0.f, 0.f);
    } else {
        const float* src = in + (size_t)row * lda + within;
        F4U s0, s1; s0.f4 = *(const float4*)src; s1.f4 = *(const float4*)(src + 4);
        if (blk == 1){
            o[0] = lo2(s0.f[0], s0.f[1]); o[1] = lo2(s0.f[2], s0.f[3]);
            o[2] = lo2(s1.f[0], s1.f[1]); o[3] = lo2(s1.f[2], s1.f[3]);
        } else {
            o[0] = hi2(s0.f[0], s0.f[1]); o[1] = hi2(s0.f[2], s0.f[3]);
            o[2] = hi2(s1.f[0], s1.f[1]); o[3] = hi2(s1.f[2], s1.f[3]);
        }
    }
    *(uint4*)&out[(size_t)row * k3p + kc * 8] = *(uint4*)o;
}

// =====================================================================
// HMMA GEMM, 3-stage cp.async pipeline (BK=32), CTA 128x128, 8 warps.
// =====================================================================
#define TILE_BYTES 20480
#define GEMM_SMEM  (3 * TILE_BYTES)
template<int EPI, bool OUT3>
__global__ __launch_bounds__(256, 2) void hmma_gemm(
    const bf16* __restrict__ A3, int lda3,
    const bf16* __restrict__ W3, int k3p,
    const float* __restrict__ bias, const float* __restrict__ res,
    float* __restrict__ C, bf16* __restrict__ C3, int N)
{
    extern __shared__ char smem[];
    const uint32_t sb = smem_u32(smem);
    const int tid = threadIdx.x;
    const int wid = tid >> 5, lane = tid & 31;
    const int bm = blockIdx.y * 128;
    const int bn = blockIdx.x * 128;
    const int wm = wid & 1, wn = wid >> 1;

    float acc[4][4][4];
#pragma unroll
    for (int i = 0; i < 4; i++)
#pragma unroll
        for (int j = 0; j < 4; j++)
#pragma unroll
            for (int e = 0; e < 4; e++) acc[i][j][e] = 0.f;

    const int NC = k3p >> 5;
    const int c0 = tid;

    auto load_tile = [&](int ci, uint32_t sbase){
#pragma unroll
        for (int cc = 0; cc < 4; cc++){
            const int c = c0 + cc * 256;
            if (c < 512){
                const int row = c >> 2, ch = c & 3;
                cp16(sbase + row * 80 + ch * 16,
                     &A3[(size_t)(bm + row) * lda3 + ci * 32 + ch * 8]);
            } else {
                const int c2 = c - 512;
                const int row = c2 >> 2, ch = c2 & 3;
                int br = bn + row; if (br >= N) br = N - 1;
                cp16(sbase + 128 * 80 + row * 80 + ch * 16,
                     &W3[(size_t)br * k3p + ci * 32 + ch * 8]);
            }
        }
        asm volatile("cp.async.commit_group;" ::: "memory");
    };

    load_tile(0, sb);
    if (NC > 1) load_tile(1, sb + TILE_BYTES);

    const uint32_t aOff = (uint32_t)((wm * 64 + (lane & 15)) * 80 + (lane >> 4) * 16);
    const uint32_t bOff = (uint32_t)(128 * 80 +
                          (wn * 32 + (lane & 7) + ((lane & 16) ? 8 : 0)) * 80 +
                          ((lane >> 3) & 1) * 16);

    for (int ci = 0; ci < NC; ci++){
        if (ci + 1 < NC) asm volatile("cp.async.wait_group 1;" ::: "memory");
        else             asm volatile("cp.async.wait_group 0;" ::: "memory");
        __syncthreads();
        if (ci + 2 < NC){
            const int nb = (ci + 2) % 3;
            load_tile(ci + 2, sb + (uint32_t)nb * TILE_BYTES);
        }
        const uint32_t cur = sb + (uint32_t)(ci % 3) * TILE_BYTES;

#pragma unroll
        for (int s = 0; s < 2; s++){
            uint32_t a[4][4];
#pragma unroll
            for (int i = 0; i < 4; i++)
                ldsm4(a[i][0], a[i][1], a[i][2], a[i][3], cur + aOff + i * (16 * 80) + s * 32);
            uint32_t b0, b1, b2, b3, b4, b5, b6, b7;
            ldsm4(b0, b1, b2, b3, cur + bOff + s * 32);
            ldsm4(b4, b5, b6, b7, cur + bOff + 16 * 80 + s * 32);
#pragma unroll
            for (int i = 0; i < 4; i++){
                mma16816(acc[i][0], a[i][0], a[i][1], a[i][2], a[i][3], b0, b1);
                mma16816(acc[i][1], a[i][0], a[i][1], a[i][2], a[i][3], b2, b3);
                mma16816(acc[i][2], a[i][0], a[i][1], a[i][2], a[i][3], b4, b5);
                mma16816(acc[i][3], a[i][0], a[i][1], a[i][2], a[i][3], b6, b7);
            }
        }
    }

    const int t4 = lane >> 2, tp = (lane & 3) * 2;
#pragma unroll
    for (int i = 0; i < 4; i++){
#pragma unroll
        for (int j = 0; j < 4; j++){
            const int col = bn + wn * 32 + j * 8 + tp;
            if (col >= N) continue;
            const int row0 = bm + wm * 64 + i * 16 + t4;
            float v0 = acc[i][j][0], v1 = acc[i][j][1];
            float v2 = acc[i][j][2], v3 = acc[i][j][3];
            if (EPI >= 1){
                const float bb0 = bias[col], bb1 = bias[col + 1];
                v0 += bb0; v1 += bb1; v2 += bb0; v3 += bb1;
            }
            if (EPI == 2){ v0 = softplus_f(v0); v1 = softplus_f(v1); v2 = softplus_f(v2); v3 = softplus_f(v3); }
            if (EPI == 3){ v0 = gelu_f(v0); v1 = gelu_f(v1); v2 = gelu_f(v2); v3 = gelu_f(v3); }
            if (EPI == 4){
                v0 += res[(size_t)row0 * N + col];
                v1 += res[(size_t)row0 * N + col + 1];
                v2 += res[(size_t)(row0 + 8) * N + col];
                v3 += res[(size_t)(row0 + 8) * N + col + 1];
            }
            if (OUT3){
                const size_t r0 = (size_t)row0 * (3 * N), r1 = (size_t)(row0 + 8) * (3 * N);
                *(__nv_bfloat162*)&C3[r0 + col]         = hi2(v0, v1);
                *(__nv_bfloat162*)&C3[r0 + N + col]     = lo2(v0, v1);
                *(__nv_bfloat162*)&C3[r0 + 2 * N + col] = hi2(v0, v1);
                *(__nv_bfloat162*)&C3[r1 + col]         = hi2(v2, v3);
                *(__nv_bfloat162*)&C3[r1 + N + col]     = lo2(v2, v3);
                *(__nv_bfloat162*)&C3[r1 + 2 * N + col] = hi2(v2, v3);
            } else {
                *(float2*)&C[(size_t)row0 * N + col]       = make_float2(v0, v1);
                *(float2*)&C[(size_t)(row0 + 8) * N + col] = make_float2(v2, v3);
            }
        }
    }
}

// =====================================================================
// Tensor-core flash attention (split-3 bf16 via mma.sync).
// Per (b,h), 64 q-rows/CTA, streaming 64-key tiles.
// Q/P smem: [64 rows][hi 64 | lo 64] pitch 272B; K same ([hi|lo] blocks);
// V smem: [Vh rows 0-63 | Vl rows 64-127][64 e] pitch 144B.
// k-steps (12 of k16): A=[hi,lo,hi], B(K)=[hi,hi,lo], B(V rows)=[Vh,Vh,Vl].
// 8 warps: wm=wid&1 (q 32-half), wn=wid>>1 (16-col quarter).
// =====================================================================
#define FO_Q 0
#define FO_K 17408
#define FO_V 34816
#define FO_P 53248
#define FO_S 70656
#define FO_M 88064
#define FO_L 88320
#define FO_F 88576
#define FO_MSK 88832
#define FLASH_SMEM 89088

__global__ __launch_bounds__(256, 2) void flash_mma(
    const float* __restrict__ QKV, const unsigned char* __restrict__ mask,
    bf16* __restrict__ AO3)
{
    extern __shared__ char sm[];
    const uint32_t sb = smem_u32(sm);
    float* Ssm  = (float*)(sm + FO_S);
    float* mrow = (float*)(sm + FO_M);
    float* lrow = (float*)(sm + FO_L);
    float* facs = (float*)(sm + FO_F);
    float* mskf = (float*)(sm + FO_MSK);

    const int tid = threadIdx.x;
    const int wid = tid >> 5, lane = tid & 31;
    const int wm = wid & 1, wn = wid >> 1;
    const int bh = blockIdx.y;
    const int b = bh >> 3, h = bh & 7;
    const int q0 = blockIdx.x * 64;
    const size_t basebl = (size_t)b * cL;

    if (tid < 64){ mrow[tid] = -1e30f; lrow[tid] = 0.f; }

    // load Q (once): hi at cols 0-63, lo at 64-127
    for (int idx = tid; idx < 1024; idx += 256){
        const int row = idx >> 4, c4 = idx & 15;
        F4U qv; qv.f4 = *(const float4*)&QKV[(basebl + q0 + row) * 1536 + h * 64 + c4 * 4];
        const uint32_t base = sb + FO_Q + row * 272 + c4 * 8;
        *(__nv_bfloat162*)(size_t)(uintptr_t)(sm + FO_Q + row * 272 + c4 * 8)       = hi2(qv.f[0], qv.f[1]);
        *(__nv_bfloat162*)(uintptr_t)(sm + FO_Q + row * 272 + c4 * 8 + 4)           = hi2(qv.f[2], qv.f[3]);
        *(__nv_bfloat162*)(uintptr_t)(sm + FO_Q + row * 272 + 128 + c4 * 8)         = lo2(qv.f[0], qv.f[1]);
        *(__nv_bfloat162*)(uintptr_t)(sm + FO_Q + row * 272 + 128 + c4 * 8 + 4)     = lo2(qv.f[2], qv.f[3]);
        (void)base;
    }

    float o[2][2][4];
#pragma unroll
    for (int i = 0; i < 2; i++)
#pragma unroll
        for (int j = 0; j < 2; j++)
#pragma unroll
            for (int e = 0; e < 4; e++) o[i][j][e] = 0.f;

    for (int jt = 0; jt < cL / 64; jt++){
        const int k0 = jt * 64;
        __syncthreads();
        // load K, V tiles + split
        for (int idx = tid; idx < 1024; idx += 256){
            const int row = idx >> 4, c4 = idx & 15;
            const size_t gr = (basebl + k0 + row) * 1536 + h * 64 + c4 * 4;
            F4U kv; kv.f4 = *(const float4*)&QKV[gr + 512];
            F4U vv; vv.f4 = *(const float4*)&QKV[gr + 1024];
            *(__nv_bfloat162*)(uintptr_t)(sm + FO_K + row * 272 + c4 * 8)       = hi2(kv.f[0], kv.f[1]);
            *(__nv_bfloat162*)(uintptr_t)(sm + FO_K + row * 272 + c4 * 8 + 4)   = hi2(kv.f[2], kv.f[3]);
            *(__nv_bfloat162*)(uintptr_t)(sm + FO_K + row * 272 + 128 + c4 * 8)     = lo2(kv.f[0], kv.f[1]);
            *(__nv_bfloat162*)(uintptr_t)(sm + FO_K + row * 272 + 128 + c4 * 8 + 4) = lo2(kv.f[2], kv.f[3]);
            *(__nv_bfloat162*)(uintptr_t)(sm + FO_V + row * 144 + c4 * 8)       = hi2(vv.f[0], vv.f[1]);
            *(__nv_bfloat162*)(uintptr_t)(sm + FO_V + row * 144 + c4 * 8 + 4)   = hi2(vv.f[2], vv.f[3]);
            *(__nv_bfloat162*)(uintptr_t)(sm + FO_V + (64 + row) * 144 + c4 * 8)     = lo2(vv.f[0], vv.f[1]);
            *(__nv_bfloat162*)(uintptr_t)(sm + FO_V + (64 + row) * 144 + c4 * 8 + 4) = lo2(vv.f[2], vv.f[3]);
        }
        if (tid < 64) mskf[tid] = mask[b * cL + k0 + tid] ? -1e30f : 0.0f;
        __syncthreads();

        // ---- QK^T mma: S[64x64] over k3=192 (12 k16 steps) ----
        float sacc[2][2][4];
#pragma unroll
        for (int i = 0; i < 2; i++)
#pragma unroll
            for (int j = 0; j < 2; j++)
#pragma unroll
                for (int e = 0; e < 4; e++) sacc[i][j][e] = 0.f;

#pragma unroll
        for (int s = 0; s < 12; s++){
            const int ab = (s < 4) ? s * 32 : (s < 8) ? 128 + (s - 4) * 32 : (s - 8) * 32;
            const int bb = (s < 8) ? (s & 3) * 32 : 128 + (s - 8) * 32;
            uint32_t a[2][4];
#pragma unroll
            for (int i = 0; i < 2; i++)
                ldsm4(a[i][0], a[i][1], a[i][2], a[i][3],
                      sb + FO_Q + (wm * 32 + i * 16 + (lane & 15)) * 272 + ab + ((lane >> 4) * 16));
            uint32_t b0, b1, b2, b3;
            ldsm4(b0, b1, b2, b3,
                  sb + FO_K + (wn * 16 + (lane & 7) + ((lane & 16) ? 8 : 0)) * 272 + bb + (((lane >> 3) & 1) * 16));
#pragma unroll
            for (int i = 0; i < 2; i++){
                mma16816(sacc[i][0], a[i][0], a[i][1], a[i][2], a[i][3], b0, b1);
                mma16816(sacc[i][1], a[i][0], a[i][1], a[i][2], a[i][3], b2, b3);
            }
        }
        // write S to smem fp32
        {
            const int r0 = wm * 32 + (lane >> 2), c0 = wn * 16 + (lane & 3) * 2;
#pragma unroll
            for (int i = 0; i < 2; i++)
#pragma unroll
                for (int j = 0; j < 2; j++){
                    *(float2*)&Ssm[(r0 + i * 16) * 68 + c0 + j * 8]     = make_float2(sacc[i][j][0], sacc[i][j][1]);
                    *(float2*)&Ssm[(r0 + i * 16 + 8) * 68 + c0 + j * 8] = make_float2(sacc[i][j][2], sacc[i][j][3]);
                }
        }
        __syncthreads();

        // ---- online softmax (4 threads per row) ----
        {
            const int r = tid >> 2, sg = (tid & 3) * 16;
            float pv[16];
            float mx = -1e30f;
#pragma unroll
            for (int c = 0; c < 16; c++){
                const float sv = Ssm[r * 68 + sg + c] * 0.125f + mskf[sg + c];
                pv[c] = sv;
                mx = fmaxf(mx, sv);
            }
            mx = fmaxf(mx, __shfl_xor_sync(0xffffffffu, mx, 1));
            mx = fmaxf(mx, __shfl_xor_sync(0xffffffffu, mx, 2));
            const float mold = mrow[r];
            const float mnew = fmaxf(mold, mx);
            const float fac = __expf(mold - mnew);
            float sum = 0.f;
#pragma unroll
            for (int c = 0; c < 16; c++){
                const float p = __expf(pv[c] - mnew);
                pv[c] = p;
                sum += p;
            }
            sum += __shfl_xor_sync(0xffffffffu, sum, 1);
            sum += __shfl_xor_sync(0xffffffffu, sum, 2);
#pragma unroll
            for (int c = 0; c < 16; c += 2){
                *(__nv_bfloat162*)(uintptr_t)(sm + FO_P + r * 272 + (sg + c) * 2)       = hi2(pv[c], pv[c + 1]);
                *(__nv_bfloat162*)(uintptr_t)(sm + FO_P + r * 272 + 128 + (sg + c) * 2) = lo2(pv[c], pv[c + 1]);
            }
            if ((tid & 3) == 0){
                facs[r] = fac;
                mrow[r] = mnew;
                lrow[r] = lrow[r] * fac + sum;
            }
        }
        __syncthreads();

        // ---- rescale O then P*V mma ----
        {
            const int r0 = wm * 32 + (lane >> 2);
            const float f00 = facs[r0],     f01 = facs[r0 + 8];
            const float f10 = facs[r0 + 16], f11 = facs[r0 + 24];
#pragma unroll
            for (int j = 0; j < 2; j++){
                o[0][j][0] *= f00; o[0][j][1] *= f00; o[0][j][2] *= f01; o[0][j][3] *= f01;
                o[1][j][0] *= f10; o[1][j][1] *= f10; o[1][j][2] *= f11; o[1][j][3] *= f11;
            }
        }
#pragma unroll
        for (int s = 0; s < 12; s++){
            const int ab = (s < 4) ? s * 32 : (s < 8) ? 128 + (s - 4) * 32 : (s - 8) * 32;  // P: hi,lo,hi
            const int vr = (s < 8) ? (s & 3) * 16 : 64 + (s - 8) * 16;                      // V: Vh,Vh,Vl
            uint32_t a[2][4];
#pragma unroll
            for (int i = 0; i < 2; i++)
                ldsm4(a[i][0], a[i][1], a[i][2], a[i][3],
                      sb + FO_P + (wm * 32 + i * 16 + (lane & 15)) * 272 + ab + ((lane >> 4) * 16));
            uint32_t v0, v1, v2, v3;
            ldsm4t(v0, v1, v2, v3,
                   sb + FO_V + (vr + (lane & 15)) * 144 + (wn * 16 + ((lane & 16) ? 8 : 0)) * 2);
#pragma unroll
            for (int i = 0; i < 2; i++){
                mma16816(o[i][0], a[i][0], a[i][1], a[i][2], a[i][3], v0, v1);
                mma16816(o[i][1], a[i][0], a[i][1], a[i][2], a[i][3], v2, v3);
            }
        }
    }

    // ---- epilogue: normalize + write AO3 split ----
    {
        const int r0 = wm * 32 + (lane >> 2), c0 = wn * 16 + (lane & 3) * 2;
#pragma unroll
        for (int i = 0; i < 2; i++){
            const int rA = r0 + i * 16, rB = rA + 8;
            const float invA = 1.0f / lrow[rA];
            const float invB = 1.0f / lrow[rB];
#pragma unroll
            for (int j = 0; j < 2; j++){
                const float a0 = o[i][j][0] * invA, a1 = o[i][j][1] * invA;
                const float a2 = o[i][j][2] * invB, a3 = o[i][j][3] * invB;
                const int col = h * 64 + c0 + j * 8;
                const size_t gA = (basebl + q0 + rA) * 1536;
                const size_t gB = (basebl + q0 + rB) * 1536;
                *(__nv_bfloat162*)&AO3[gA + col]        = hi2(a0, a1);
                *(__nv_bfloat162*)&AO3[gA + 512 + col]  = lo2(a0, a1);
                *(__nv_bfloat162*)&AO3[gA + 1024 + col] = hi2(a0, a1);
                *(__nv_bfloat162*)&AO3[gB + col]        = hi2(a2, a3);
                *(__nv_bfloat162*)&AO3[gB + 512 + col]  = lo2(a2, a3);
                *(__nv_bfloat162*)&AO3[gB + 1024 + col] = hi2(a2, a3);
            }
        }
    }
}

// =====================================================================
// Depthwise causal conv (KC=4) + SiLU; writes u (fp32) + u3 (triple)
// =====================================================================
__global__ __launch_bounds__(256) void conv_silu(
    const float* __restrict__ xz, const float* __restrict__ cw,
    const float* __restrict__ cb, float* __restrict__ u, bf16* __restrict__ u3)
{
    const long idx = (long)blockIdx.x * 256 + threadIdx.x;  // over M*512
    const int c = (int)(idx & 511) * 2;
    const int m = (int)(idx >> 9);
    const int b = m / cL, l = m % cL;
    float a0 = cb[c], a1 = cb[c + 1];
#pragma unroll
    for (int k = 0; k < 4; k++){
        const int ls = l + k - 3;
        if (ls >= 0){
            const size_t row = (size_t)(b * cL + ls) * (2 * cDI);
            a0 += xz[row + c]     * cw[c * 4 + k];
            a1 += xz[row + c + 1] * cw[(c + 1) * 4 + k];
        }
    }
    a0 = a0 / (1.0f + __expf(-a0));
    a1 = a1 / (1.0f + __expf(-a1));
    *(float2*)&u[(size_t)m * cDI + c] = make_float2(a0, a1);
    const size_t r3 = (size_t)m * 3072;
    *(__nv_bfloat162*)&u3[r3 + c]        = hi2(a0, a1);
    *(__nv_bfloat162*)&u3[r3 + 1024 + c] = lo2(a0, a1);
    *(__nv_bfloat162*)&u3[r3 + 2048 + c] = hi2(a0, a1);
}

// =====================================================================
// Selective scan: warp per (b, d); writes y3 triple
// =====================================================================
__global__ __launch_bounds__(256) void mamba_scan(
    const float* __restrict__ delta, const float* __restrict__ u,
    const float* __restrict__ xdbc, const float* __restrict__ xz,
    const float* __restrict__ A_log, const float* __restrict__ Dssm,
    bf16* __restrict__ y3)
{
    const int warp = threadIdx.x >> 5, lane = threadIdx.x & 31;
    const int d = blockIdx.x * 8 + warp;
    const int b = blockIdx.y;
    const float a0 = -__expf(A_log[d * cS + 2 * lane]);
    const float a1 = -__expf(A_log[d * cS + 2 * lane + 1]);
    const float Dd = Dssm[d];
    float h0 = 0.f, h1 = 0.f;
    const size_t base = (size_t)b * cL;

    for (int t = 0; t < cL; t++){
        const size_t m = base + t;
        const float dt = __ldg(&delta[m * cDI + d]);
        const float uu = __ldg(&u[m * cDI + d]);
        const float2 Bv = *(const float2*)&xdbc[m * 160 + 32 + 2 * lane];
        const float2 Cv = *(const float2*)&xdbc[m * 160 + 96 + 2 * lane];
        const float du = dt * uu;
        h0 = h0 * __expf(dt * a0) + du * Bv.x;
        h1 = h1 * __expf(dt * a1) + du * Bv.y;
        float p = h0 * Cv.x + h1 * Cv.y;
        p += __shfl_xor_sync(0xffffffffu, p, 16);
        p += __shfl_xor_sync(0xffffffffu, p, 8);
        p += __shfl_xor_sync(0xffffffffu, p, 4);
        p += __shfl_xor_sync(0xffffffffu, p, 2);
        p += __shfl_xor_sync(0xffffffffu, p, 1);
        if (lane == 0){
            const float z = xz[m * (2 * cDI) + cDI + d];
            float yv = p + uu * Dd;
            yv *= z / (1.0f + __expf(-z));
            const size_t r3 = m * 3072;
            y3[r3 + d]        = hi_bf(yv);
            y3[r3 + 1024 + d] = lo_bf(yv);
            y3[r3 + 2048 + d] = hi_bf(yv);
        }
    }
}

// =====================================================================
// Fused residual + LN1 + LN2; writes h (fp32) and hn3 (triple)
// =====================================================================
__device__ __forceinline__ float blockSum256(float v, float* red){
#pragma unroll
    for (int off = 16; off > 0; off >>= 1) v += __shfl_xor_sync(0xffffffffu, v, off);
    if ((threadIdx.x & 31) == 0) red[threadIdx.x >> 5] = v;
    __syncthreads();
    const float s = red[0]+red[1]+red[2]+red[3]+red[4]+red[5]+red[6]+red[7];
    __syncthreads();
    return s;
}

__global__ __launch_bounds__(256) void ln_fuse(
    const float* __restrict__ xf, const float* __restrict__ attn, const float* __restrict__ mamba,
    const float* __restrict__ g1, const float* __restrict__ b1,
    const float* __restrict__ g2, const float* __restrict__ b2,
    float* __restrict__ h, bf16* __restrict__ hn3)
{
    __shared__ float red[8];
    const size_t m = blockIdx.x;
    const int t = threadIdx.x * 2;
    const size_t r = m * cD;
    float v0 = xf[r + t]     + attn[r + t]     + mamba[r + t];
    float v1 = xf[r + t + 1] + attn[r + t + 1] + mamba[r + t + 1];

    const float mean = blockSum256(v0 + v1, red) * (1.0f / cD);
    const float d0 = v0 - mean, d1 = v1 - mean;
    const float var = blockSum256(d0 * d0 + d1 * d1, red) * (1.0f / cD);
    const float inv = rsqrtf(var + 1e-5f);
    const float h0 = d0 * inv * g1[t]     + b1[t];
    const float h1 = d1 * inv * g1[t + 1] + b1[t + 1];
    *(float2*)&h[r + t] = make_float2(h0, h1);

    const float mean2 = blockSum256(h0 + h1, red) * (1.0f / cD);
    const float e0 = h0 - mean2, e1 = h1 - mean2;
    const float var2 = blockSum256(e0 * e0 + e1 * e1, red) * (1.0f / cD);
    const float inv2 = rsqrtf(var2 + 1e-6f);
    const float n0 = e0 * inv2 * g2[t]     + b2[t];
    const float n1 = e1 * inv2 * g2[t + 1] + b2[t + 1];
    const size_t r3 = m * 1536;
    *(__nv_bfloat162*)&hn3[r3 + t]        = hi2(n0, n1);
    *(__nv_bfloat162*)&hn3[r3 + 512 + t]  = lo2(n0, n1);
    *(__nv_bfloat162*)&hn3[r3 + 1024 + t] = hi2(n0, n1);
}

// =====================================================================
// Launch
// =====================================================================
static inline int sgrid(long rows, int k3p){
    return (int)((rows * (k3p >> 3) + 255) / 256);
}

extern "C" void kernel_launch(void* const* d_in, const int* in_sizes, int n_in,
                              void* d_out, int out_size)
{
    (void)in_sizes; (void)n_in; (void)out_size;
    const float* x      = (const float*)d_in[0];
    const unsigned char* mask = (const unsigned char*)d_in[1];
    const float* Wq = (const float*)d_in[2];  const float* bq = (const float*)d_in[3];
    const float* Wk = (const float*)d_in[4];  const float* bk = (const float*)d_in[5];
    const float* Wv = (const float*)d_in[6];  const float* bv = (const float*)d_in[7];
    const float* Wo = (const float*)d_in[8];  const float* bo = (const float*)d_in[9];
    const float* in_w   = (const float*)d_in[10];
    const float* conv_w = (const float*)d_in[11];
    const float* conv_b = (const float*)d_in[12];
    const float* xproj_w= (const float*)d_in[13];
    const float* dt_w   = (const float*)d_in[14];
    const float* dt_b   = (const float*)d_in[15];
    const float* A_log  = (const float*)d_in[16];
    const float* Dssm   = (const float*)d_in[17];
    const float* outp_w = (const float*)d_in[18];
    const float* ln1g   = (const float*)d_in[19];
    const float* ln1b   = (const float*)d_in[20];
    const float* fw1    = (const float*)d_in[21];
    const float* fb1    = (const float*)d_in[22];
    const float* fw2    = (const float*)d_in[23];
    const float* fb2    = (const float*)d_in[24];
    const float* ln2g   = (const float*)d_in[25];
    const float* ln2b   = (const float*)d_in[26];
    float* out = (float*)d_out;

    float *qkv,*attn,*xz,*u,*xdbc,*dlt,*mmb,*h,*bqkv;
    cudaGetSymbolAddress((void**)&qkv,  g_qkv);
    cudaGetSymbolAddress((void**)&attn, g_attn);
    cudaGetSymbolAddress((void**)&xz,   g_xz);
    cudaGetSymbolAddress((void**)&u,    g_u);
    cudaGetSymbolAddress((void**)&xdbc, g_xdbc);
    cudaGetSymbolAddress((void**)&dlt,  g_dlt);
    cudaGetSymbolAddress((void**)&mmb,  g_mmb);
    cudaGetSymbolAddress((void**)&h,    g_h);
    cudaGetSymbolAddress((void**)&bqkv, g_bqkv);

    bf16 *px3,*pao3,*pu3,*pxdbc3,*py3,*phn3,*pff13;
    bf16 *pwqkv,*pwo,*pwin,*pwxp,*pwdt,*pwout,*pwf1,*pwf2;
    cudaGetSymbolAddress((void**)&px3,   gx3);
    cudaGetSymbolAddress((void**)&pao3,  gao3);
    cudaGetSymbolAddress((void**)&pu3,   gu3);
    cudaGetSymbolAddress((void**)&pxdbc3,gxdbc3);
    cudaGetSymbolAddress((void**)&py3,   gy3);
    cudaGetSymbolAddress((void**)&phn3,  ghn3);
    cudaGetSymbolAddress((void**)&pff13, gff13);
    cudaGetSymbolAddress((void**)&pwqkv, wqkv3);
    cudaGetSymbolAddress((void**)&pwo,   wo3);
    cudaGetSymbolAddress((void**)&pwin,  win3);
    cudaGetSymbolAddress((void**)&pwxp,  wxp3);
    cudaGetSymbolAddress((void**)&pwdt,  wdt3);
    cudaGetSymbolAddress((void**)&pwout, wout3);
    cudaGetSymbolAddress((void**)&pwf1,  wff13);
    cudaGetSymbolAddress((void**)&pwf2,  wff23);

    cudaFuncSetAttribute(flash_mma, cudaFuncAttributeMaxDynamicSharedMemorySize, FLASH_SMEM);
    cudaFuncSetAttribute(hmma_gemm<0,false>, cudaFuncAttributeMaxDynamicSharedMemorySize, GEMM_SMEM);
    cudaFuncSetAttribute(hmma_gemm<1,false>, cudaFuncAttributeMaxDynamicSharedMemorySize, GEMM_SMEM);
    cudaFuncSetAttribute(hmma_gemm<2,false>, cudaFuncAttributeMaxDynamicSharedMemorySize, GEMM_SMEM);
    cudaFuncSetAttribute(hmma_gemm<3,true>,  cudaFuncAttributeMaxDynamicSharedMemorySize, GEMM_SMEM);
    cudaFuncSetAttribute(hmma_gemm<4,false>, cudaFuncAttributeMaxDynamicSharedMemorySize, GEMM_SMEM);

    // ---- fused weight-split table ----
    WTab tab;
    long base = 0;
    auto add = [&](int i, const float* src, bf16* dst, int K, int k3p, long rows){
        tab.e[i] = {src, dst, K, k3p, rows, base};
        base += rows * (k3p >> 3);
    };
    add(0, Wq,      pwqkv,               512,  1536, 512);
    add(1, Wk,      pwqkv + 512 * 1536,  512,  1536, 512);
    add(2, Wv,      pwqkv + 1024 * 1536, 512,  1536, 512);
    add(3, Wo,      pwo,                 512,  1536, 512);
    add(4, in_w,    pwin,                512,  1536, 2048);
    add(5, xproj_w, pwxp,                1024, 3072, 160);
    add(6, dt_w,    pwdt,                32,   128,  1024);
    add(7, outp_w,  pwout,               1024, 3072, 512);
    add(8, fw1,     pwf1,                512,  1536, 2048);
    add(9, fw2,     pwf2,                2048, 6144, 512);
    const int wgrid = (int)((base + 255) / 256);

    cudaStream_t s0 = 0, sB = g_sh.sB;

    split3_wgt_all<<<wgrid, 256, 0, s0>>>(tab);
    biascat<<<6, 256, 0, s0>>>(bq, bk, bv, bqkv);
    split3_act_fast<<<sgrid(cM, 1536), 256, 0, s0>>>(x, 512, 512, px3, 1536, cM);

    cudaEventRecord(g_sh.evRoot, s0);
    cudaStreamWaitEvent(sB, g_sh.evRoot, 0);

    // fused QKV GEMM
    hmma_gemm<1,false><<<dim3(12, 72), 256, GEMM_SMEM, s0>>>(px3, 1536, pwqkv, 1536, bqkv, nullptr, qkv, nullptr, 1536);
    // mamba branch on sB
    hmma_gemm<0,false><<<dim3(16, 72), 256, GEMM_SMEM, sB>>>(px3, 1536, pwin, 1536, nullptr, nullptr, xz, nullptr, 2048);
    // tensor-core flash attention on s0
    flash_mma<<<dim3(cL / 64, cB * 8), 256, FLASH_SMEM, s0>>>(qkv, mask, pao3);
    conv_silu<<<(cM * 512) / 256, 256, 0, sB>>>(xz, conv_w, conv_b, u, pu3);
    hmma_gemm<0,false><<<dim3(2, 72), 256, GEMM_SMEM, sB>>>(pu3, 3072, pwxp, 3072, nullptr, nullptr, xdbc, nullptr, 160);
    hmma_gemm<1,false><<<dim3(4, 72), 256, GEMM_SMEM, s0>>>(pao3, 1536, pwo, 1536, bo, nullptr, attn, nullptr, 512);
    split3_act_fast<<<sgrid(cM, 128), 256, 0, sB>>>(xdbc, 160, 32, pxdbc3, 128, cM);
    hmma_gemm<2,false><<<dim3(8, 72), 256, GEMM_SMEM, sB>>>(pxdbc3, 128, pwdt, 128, dt_b, nullptr, dlt, nullptr, 1024);
    mamba_scan<<<dim3(cDI / 8, cB), 256, 0, sB>>>(dlt, u, xdbc, xz, A_log, Dssm, py3);
    hmma_gemm<0,false><<<dim3(4, 72), 256, GEMM_SMEM, sB>>>(py3, 3072, pwout, 3072, nullptr, nullptr, mmb, nullptr, 512);
    cudaEventRecord(g_sh.evB, sB);

    cudaStreamWaitEvent(s0, g_sh.evB, 0);
    ln_fuse<<<cM, 256, 0, s0>>>(x, attn, mmb, ln1g, ln1b, ln2g, ln2b, h, phn3);
    hmma_gemm<3,true><<<dim3(16, 72), 256, GEMM_SMEM, s0>>>(phn3, 1536, pwf1, 1536, fb1, nullptr, nullptr, pff13, 2048);
    hmma_gemm<4,false><<<dim3(4, 72), 256, GEMM_SMEM, s0>>>(pff13, 6144, pwf2, 6144, fb2, h, out, nullptr, 512);
}

// round 9
// speedup vs baseline: 1.5002x; 1.0065x over previous
#include <cuda_runtime.h>
#include <cuda_bf16.h>
#include <cstdint>
#include <math.h>

typedef __nv_bfloat16 bf16;

// ---------------- dims ----------------
static const int cB  = 8;
static const int cL  = 1152;      // T*W
static const int cD  = 512;
static const int cDI = 1024;
static const int cS  = 64;
static const int cDFF= 2048;
static const int cM  = 9216;      // B*L

// ---------------- fp32 workspaces ----------------
__device__ float g_qkv [cM*1536];
__device__ float g_attn[cM*cD];
__device__ float g_xz  [cM*2*cDI];
__device__ float g_u   [cM*cDI];
__device__ float g_xdbc[cM*160];
__device__ float g_dlt [cM*cDI];
__device__ float g_mmb [cM*cD];
__device__ float g_h   [cM*cD];

// ---------------- bf16 split-3 activations ----------------
__device__ bf16 gx3   [cM*1536];
__device__ bf16 gao3  [cM*1536];
__device__ bf16 gu3   [cM*3072];
__device__ bf16 gxdbc3[cM*128];
__device__ bf16 gy3   [cM*3072];
__device__ bf16 ghn3  [cM*1536];
__device__ bf16 gff13 [cM*6144];

// ---------------- bf16 split-3 weights ----------------
__device__ bf16 wqkv3[1536*1536];
__device__ bf16 wo3  [512*1536];
__device__ bf16 win3 [2048*1536];
__device__ bf16 wxp3 [160*3072];
__device__ bf16 wdt3 [1024*128];
__device__ bf16 wout3[512*3072];
__device__ bf16 wff13[2048*1536];
__device__ bf16 wff23[512*6144];

// ---------------- streams (static init: before harness checkpoints) ----
struct StreamHolder {
    cudaStream_t sB;
    cudaEvent_t evRoot, evB;
    StreamHolder(){
        cudaStreamCreateWithFlags(&sB, cudaStreamNonBlocking);
        cudaEventCreateWithFlags(&evRoot, cudaEventDisableTiming);
        cudaEventCreateWithFlags(&evB,   cudaEventDisableTiming);
    }
};
static StreamHolder g_sh;

// ---------------- helpers ----------------
union F4U { float4 f4; unsigned long long l[2]; float f[4]; };

__device__ __forceinline__ float softplus_f(float v){
    return fmaxf(v, 0.0f) + log1pf(__expf(-fabsf(v)));
}
__device__ __forceinline__ float gelu_f(float v){
    return 0.5f * v * (1.0f + erff(v * 0.70710678118654752f));
}
__device__ __forceinline__ bf16 hi_bf(float a){ return __float2bfloat16(a); }
__device__ __forceinline__ bf16 lo_bf(float a){
    bf16 h = __float2bfloat16(a);
    return __float2bfloat16(a - __bfloat162float(h));
}
__device__ __forceinline__ __nv_bfloat162 hi2(float a, float b){
    return __floats2bfloat162_rn(a, b);
}
__device__ __forceinline__ __nv_bfloat162 lo2(float a, float b){
    __nv_bfloat162 h = __floats2bfloat162_rn(a, b);
    return __floats2bfloat162_rn(a - __bfloat162float(h.x), b - __bfloat162float(h.y));
}

__device__ __forceinline__ uint32_t smem_u32(const void* p){
    uint32_t a;
    asm("{ .reg .u64 t; cvta.to.shared.u64 t, %1; cvt.u32.u64 %0, t; }" : "=r"(a) : "l"(p));
    return a;
}
__device__ __forceinline__ void cp16(uint32_t dst, const void* src){
    asm volatile("cp.async.cg.shared.global [%0], [%1], 16;" :: "r"(dst), "l"(src));
}
__device__ __forceinline__ void ldsm4(uint32_t &r0, uint32_t &r1, uint32_t &r2, uint32_t &r3, uint32_t addr){
    asm volatile("ldmatrix.sync.aligned.m8n8.x4.shared.b16 {%0,%1,%2,%3}, [%4];"
        : "=r"(r0), "=r"(r1), "=r"(r2), "=r"(r3) : "r"(addr));
}
__device__ __forceinline__ void ldsm4t(uint32_t &r0, uint32_t &r1, uint32_t &r2, uint32_t &r3, uint32_t addr){
    asm volatile("ldmatrix.sync.aligned.m8n8.x4.trans.shared.b16 {%0,%1,%2,%3}, [%4];"
        : "=r"(r0), "=r"(r1), "=r"(r2), "=r"(r3) : "r"(addr));
}
__device__ __forceinline__ void mma16816(float* c, uint32_t a0, uint32_t a1, uint32_t a2, uint32_t a3,
                                         uint32_t b0, uint32_t b1){
    asm volatile("mma.sync.aligned.m16n8k16.row.col.f32.bf16.bf16.f32 "
        "{%0,%1,%2,%3}, {%4,%5,%6,%7}, {%8,%9}, {%0,%1,%2,%3};"
        : "+f"(c[0]), "+f"(c[1]), "+f"(c[2]), "+f"(c[3])
        : "r"(a0), "r"(a1), "r"(a2), "r"(a3), "r"(b0), "r"(b1));
}

// =====================================================================
// Fused weight split3 (all weights, one launch). weights: [hi | hi | lo]
// =====================================================================
struct WSpec { const float* src; bf16* dst; int K; int k3p; long rows; long base; };
struct WTab  { WSpec e[10]; };

__global__ __launch_bounds__(256) void split3_wgt_all(WTab tab)
{
    const long idx = (long)blockIdx.x * 256 + threadIdx.x;
    int i = 0;
#pragma unroll
    for (int j = 1; j < 10; j++) if (idx >= tab.e[j].base) i = j;
    const WSpec w = tab.e[i];
    const long local = idx - w.base;
    const int chunks = w.k3p >> 3;
    if (local >= w.rows * chunks) return;
    const int row = (int)(local / chunks);
    const int kc = (int)(local - (long)row * chunks);
    const int blk = (kc * 8) / w.K;
    const int within = kc * 8 - blk * w.K;
    __nv_bfloat162 o[4];
    const float* src = w.src + (size_t)row * w.K + within;
    F4U s0, s1; s0.f4 = *(const float4*)src; s1.f4 = *(const float4*)(src + 4);
    if (blk == 2){
        o[0] = lo2(s0.f[0], s0.f[1]); o[1] = lo2(s0.f[2], s0.f[3]);
        o[2] = lo2(s1.f[0], s1.f[1]); o[3] = lo2(s1.f[2], s1.f[3]);
    } else {
        o[0] = hi2(s0.f[0], s0.f[1]); o[1] = hi2(s0.f[2], s0.f[3]);
        o[2] = hi2(s1.f[0], s1.f[1]); o[3] = hi2(s1.f[2], s1.f[3]);
    }
    *(uint4*)&w.dst[(size_t)row * w.k3p + kc * 8] = *(uint4*)o;
}

// activation split3: [hi | lo | hi] (+zero pad block)
__global__ __launch_bounds__(256) void split3_act_fast(
    const float* __restrict__ in, int lda, int K,
    bf16* __restrict__ out, int k3p, int rows)
{
    const int chunks = k3p >> 3;
    const long idx = (long)blockIdx.x * 256 + threadIdx.x;
    if (idx >= (long)rows * chunks) return;
    const int row = (int)(idx / chunks);
    const int kc = (int)(idx - (long)row * chunks);
    const int blk = (kc * 8) / K;
    const int within = kc * 8 - blk * K;
    __nv_bfloat162 o[4];
    if (blk >= 3){
        o[0] = o[1] = o[2] = o[3] = __floats2bfloat162_rn(0.f, 0.f);
    } else {
        const float* src = in + (size_t)row * lda + within;
        F4U s0, s1; s0.f4 = *(const float4*)src; s1.f4 = *(const float4*)(src + 4);
        if (blk == 1){
            o[0] = lo2(s0.f[0], s0.f[1]); o[1] = lo2(s0.f[2], s0.f[3]);
            o[2] = lo2(s1.f[0], s1.f[1]); o[3] = lo2(s1.f[2], s1.f[3]);
        } else {
            o[0] = hi2(s0.f[0], s0.f[1]); o[1] = hi2(s0.f[2], s0.f[3]);
            o[2] = hi2(s1.f[0], s1.f[1]); o[3] = hi2(s1.f[2], s1.f[3]);
        }
    }
    *(uint4*)&out[(size_t)row * k3p + kc * 8] = *(uint4*)o;
}

// =====================================================================
// HMMA GEMM: 512 threads, 16 warps (4x4 of 32x32 tiles), CTA 128x128,
// BK=32, 3-stage cp.async. __launch_bounds__(512,2) -> 32 warps/SM.
// EPI: 0=none 1=bias 2=bias+softplus 3=bias+gelu 4=bias+res 5=tri-bias
// OUT3: bf16 [hi|lo|hi] triple output
// =====================================================================
#define TILE_BYTES 20480
#define GEMM_SMEM  (3 * TILE_BYTES)
template<int EPI, bool OUT3>
__global__ __launch_bounds__(512, 2) void hmma_gemm(
    const bf16* __restrict__ A3, int lda3,
    const bf16* __restrict__ W3, int k3p,
    const float* __restrict__ bias, const float* __restrict__ bias_b,
    const float* __restrict__ bias_c, const float* __restrict__ res,
    float* __restrict__ C, bf16* __restrict__ C3, int N)
{
    extern __shared__ char smem[];
    const uint32_t sb = smem_u32(smem);
    const int tid = threadIdx.x;
    const int wid = tid >> 5, lane = tid & 31;
    const int bm = blockIdx.y * 128;
    const int bn = blockIdx.x * 128;
    const int wm = wid & 3, wn = wid >> 2;

    float acc[2][4][4];
#pragma unroll
    for (int i = 0; i < 2; i++)
#pragma unroll
        for (int j = 0; j < 4; j++)
#pragma unroll
            for (int e = 0; e < 4; e++) acc[i][j][e] = 0.f;

    const int NC = k3p >> 5;

    auto load_tile = [&](int ci, uint32_t sbase){
#pragma unroll
        for (int cc = 0; cc < 2; cc++){
            const int c = tid + cc * 512;
            if (c < 512){
                const int row = c >> 2, ch = c & 3;
                cp16(sbase + row * 80 + ch * 16,
                     &A3[(size_t)(bm + row) * lda3 + ci * 32 + ch * 8]);
            } else {
                const int c2 = c - 512;
                const int row = c2 >> 2, ch = c2 & 3;
                int br = bn + row; if (br >= N) br = N - 1;
                cp16(sbase + 128 * 80 + row * 80 + ch * 16,
                     &W3[(size_t)br * k3p + ci * 32 + ch * 8]);
            }
        }
        asm volatile("cp.async.commit_group;" ::: "memory");
    };

    load_tile(0, sb);
    if (NC > 1) load_tile(1, sb + TILE_BYTES);

    const uint32_t aOff = (uint32_t)((wm * 32 + (lane & 15)) * 80 + (lane >> 4) * 16);
    const uint32_t bOff = (uint32_t)(128 * 80 +
                          (wn * 32 + (lane & 7) + ((lane & 16) ? 8 : 0)) * 80 +
                          ((lane >> 3) & 1) * 16);

    for (int ci = 0; ci < NC; ci++){
        if (ci + 1 < NC) asm volatile("cp.async.wait_group 1;" ::: "memory");
        else             asm volatile("cp.async.wait_group 0;" ::: "memory");
        __syncthreads();
        if (ci + 2 < NC){
            const int nb = (ci + 2) % 3;
            load_tile(ci + 2, sb + (uint32_t)nb * TILE_BYTES);
        }
        const uint32_t cur = sb + (uint32_t)(ci % 3) * TILE_BYTES;

#pragma unroll
        for (int s = 0; s < 2; s++){
            uint32_t a[2][4];
#pragma unroll
            for (int i = 0; i < 2; i++)
                ldsm4(a[i][0], a[i][1], a[i][2], a[i][3], cur + aOff + i * (16 * 80) + s * 32);
            uint32_t b0, b1, b2, b3, b4, b5, b6, b7;
            ldsm4(b0, b1, b2, b3, cur + bOff + s * 32);
            ldsm4(b4, b5, b6, b7, cur + bOff + 16 * 80 + s * 32);
#pragma unroll
            for (int i = 0; i < 2; i++){
                mma16816(acc[i][0], a[i][0], a[i][1], a[i][2], a[i][3], b0, b1);
                mma16816(acc[i][1], a[i][0], a[i][1], a[i][2], a[i][3], b2, b3);
                mma16816(acc[i][2], a[i][0], a[i][1], a[i][2], a[i][3], b4, b5);
                mma16816(acc[i][3], a[i][0], a[i][1], a[i][2], a[i][3], b6, b7);
            }
        }
    }

    const int t4 = lane >> 2, tp = (lane & 3) * 2;
#pragma unroll
    for (int i = 0; i < 2; i++){
#pragma unroll
        for (int j = 0; j < 4; j++){
            const int col = bn + wn * 32 + j * 8 + tp;
            if (col >= N) continue;
            const int row0 = bm + wm * 32 + i * 16 + t4;
            float v0 = acc[i][j][0], v1 = acc[i][j][1];
            float v2 = acc[i][j][2], v3 = acc[i][j][3];
            if (EPI >= 1 && EPI <= 4){
                const float bb0 = bias[col], bb1 = bias[col + 1];
                v0 += bb0; v1 += bb1; v2 += bb0; v3 += bb1;
            }
            if (EPI == 5){
                const float* bp = (col < 512) ? bias : (col < 1024) ? (bias_b - 512) : (bias_c - 1024);
                const float bb0 = bp[col], bb1 = bp[col + 1];
                v0 += bb0; v1 += bb1; v2 += bb0; v3 += bb1;
            }
            if (EPI == 2){ v0 = softplus_f(v0); v1 = softplus_f(v1); v2 = softplus_f(v2); v3 = softplus_f(v3); }
            if (EPI == 3){ v0 = gelu_f(v0); v1 = gelu_f(v1); v2 = gelu_f(v2); v3 = gelu_f(v3); }
            if (EPI == 4){
                v0 += res[(size_t)row0 * N + col];
                v1 += res[(size_t)row0 * N + col + 1];
                v2 += res[(size_t)(row0 + 8) * N + col];
                v3 += res[(size_t)(row0 + 8) * N + col + 1];
            }
            if (OUT3){
                const size_t r0 = (size_t)row0 * (3 * N), r1 = (size_t)(row0 + 8) * (3 * N);
                *(__nv_bfloat162*)&C3[r0 + col]         = hi2(v0, v1);
                *(__nv_bfloat162*)&C3[r0 + N + col]     = lo2(v0, v1);
                *(__nv_bfloat162*)&C3[r0 + 2 * N + col] = hi2(v0, v1);
                *(__nv_bfloat162*)&C3[r1 + col]         = hi2(v2, v3);
                *(__nv_bfloat162*)&C3[r1 + N + col]     = lo2(v2, v3);
                *(__nv_bfloat162*)&C3[r1 + 2 * N + col] = hi2(v2, v3);
            } else {
                *(float2*)&C[(size_t)row0 * N + col]       = make_float2(v0, v1);
                *(float2*)&C[(size_t)(row0 + 8) * N + col] = make_float2(v2, v3);
            }
        }
    }
}

// =====================================================================
// Tensor-core flash attention (split-3 bf16 via mma.sync). Unchanged R8.
// =====================================================================
#define FO_Q 0
#define FO_K 17408
#define FO_V 34816
#define FO_P 53248
#define FO_S 70656
#define FO_M 88064
#define FO_L 88320
#define FO_F 88576
#define FO_MSK 88832
#define FLASH_SMEM 89088

__global__ __launch_bounds__(256, 2) void flash_mma(
    const float* __restrict__ QKV, const unsigned char* __restrict__ mask,
    bf16* __restrict__ AO3)
{
    extern __shared__ char sm[];
    const uint32_t sb = smem_u32(sm);
    float* Ssm  = (float*)(sm + FO_S);
    float* mrow = (float*)(sm + FO_M);
    float* lrow = (float*)(sm + FO_L);
    float* facs = (float*)(sm + FO_F);
    float* mskf = (float*)(sm + FO_MSK);

    const int tid = threadIdx.x;
    const int wid = tid >> 5, lane = tid & 31;
    const int wm = wid & 1, wn = wid >> 1;
    const int bh = blockIdx.y;
    const int b = bh >> 3, h = bh & 7;
    const int q0 = blockIdx.x * 64;
    const size_t basebl = (size_t)b * cL;

    if (tid < 64){ mrow[tid] = -1e30f; lrow[tid] = 0.f; }

    for (int idx = tid; idx < 1024; idx += 256){
        const int row = idx >> 4, c4 = idx & 15;
        F4U qv; qv.f4 = *(const float4*)&QKV[(basebl + q0 + row) * 1536 + h * 64 + c4 * 4];
        *(__nv_bfloat162*)(uintptr_t)(sm + FO_Q + row * 272 + c4 * 8)           = hi2(qv.f[0], qv.f[1]);
        *(__nv_bfloat162*)(uintptr_t)(sm + FO_Q + row * 272 + c4 * 8 + 4)       = hi2(qv.f[2], qv.f[3]);
        *(__nv_bfloat162*)(uintptr_t)(sm + FO_Q + row * 272 + 128 + c4 * 8)     = lo2(qv.f[0], qv.f[1]);
        *(__nv_bfloat162*)(uintptr_t)(sm + FO_Q + row * 272 + 128 + c4 * 8 + 4) = lo2(qv.f[2], qv.f[3]);
    }

    float o[2][2][4];
#pragma unroll
    for (int i = 0; i < 2; i++)
#pragma unroll
        for (int j = 0; j < 2; j++)
#pragma unroll
            for (int e = 0; e < 4; e++) o[i][j][e] = 0.f;

    for (int jt = 0; jt < cL / 64; jt++){
        const int k0 = jt * 64;
        __syncthreads();
        for (int idx = tid; idx < 1024; idx += 256){
            const int row = idx >> 4, c4 = idx & 15;
            const size_t gr = (basebl + k0 + row) * 1536 + h * 64 + c4 * 4;
            F4U kv; kv.f4 = *(const float4*)&QKV[gr + 512];
            F4U vv; vv.f4 = *(const float4*)&QKV[gr + 1024];
            *(__nv_bfloat162*)(uintptr_t)(sm + FO_K + row * 272 + c4 * 8)       = hi2(kv.f[0], kv.f[1]);
            *(__nv_bfloat162*)(uintptr_t)(sm + FO_K + row * 272 + c4 * 8 + 4)   = hi2(kv.f[2], kv.f[3]);
            *(__nv_bfloat162*)(uintptr_t)(sm + FO_K + row * 272 + 128 + c4 * 8)     = lo2(kv.f[0], kv.f[1]);
            *(__nv_bfloat162*)(uintptr_t)(sm + FO_K + row * 272 + 128 + c4 * 8 + 4) = lo2(kv.f[2], kv.f[3]);
            *(__nv_bfloat162*)(uintptr_t)(sm + FO_V + row * 144 + c4 * 8)       = hi2(vv.f[0], vv.f[1]);
            *(__nv_bfloat162*)(uintptr_t)(sm + FO_V + row * 144 + c4 * 8 + 4)   = hi2(vv.f[2], vv.f[3]);
            *(__nv_bfloat162*)(uintptr_t)(sm + FO_V + (64 + row) * 144 + c4 * 8)     = lo2(vv.f[0], vv.f[1]);
            *(__nv_bfloat162*)(uintptr_t)(sm + FO_V + (64 + row) * 144 + c4 * 8 + 4) = lo2(vv.f[2], vv.f[3]);
        }
        if (tid < 64) mskf[tid] = mask[b * cL + k0 + tid] ? -1e30f : 0.0f;
        __syncthreads();

        float sacc[2][2][4];
#pragma unroll
        for (int i = 0; i < 2; i++)
#pragma unroll
            for (int j = 0; j < 2; j++)
#pragma unroll
                for (int e = 0; e < 4; e++) sacc[i][j][e] = 0.f;

#pragma unroll
        for (int s = 0; s < 12; s++){
            const int ab = (s < 4) ? s * 32 : (s < 8) ? 128 + (s - 4) * 32 : (s - 8) * 32;
            const int bb = (s < 8) ? (s & 3) * 32 : 128 + (s - 8) * 32;
            uint32_t a[2][4];
#pragma unroll
            for (int i = 0; i < 2; i++)
                ldsm4(a[i][0], a[i][1], a[i][2], a[i][3],
                      sb + FO_Q + (wm * 32 + i * 16 + (lane & 15)) * 272 + ab + ((lane >> 4) * 16));
            uint32_t b0, b1, b2, b3;
            ldsm4(b0, b1, b2, b3,
                  sb + FO_K + (wn * 16 + (lane & 7) + ((lane & 16) ? 8 : 0)) * 272 + bb + (((lane >> 3) & 1) * 16));
#pragma unroll
            for (int i = 0; i < 2; i++){
                mma16816(sacc[i][0], a[i][0], a[i][1], a[i][2], a[i][3], b0, b1);
                mma16816(sacc[i][1], a[i][0], a[i][1], a[i][2], a[i][3], b2, b3);
            }
        }
        {
            const int r0 = wm * 32 + (lane >> 2), c0 = wn * 16 + (lane & 3) * 2;
#pragma unroll
            for (int i = 0; i < 2; i++)
#pragma unroll
                for (int j = 0; j < 2; j++){
                    *(float2*)&Ssm[(r0 + i * 16) * 68 + c0 + j * 8]     = make_float2(sacc[i][j][0], sacc[i][j][1]);
                    *(float2*)&Ssm[(r0 + i * 16 + 8) * 68 + c0 + j * 8] = make_float2(sacc[i][j][2], sacc[i][j][3]);
                }
        }
        __syncthreads();

        {
            const int r = tid >> 2, sg = (tid & 3) * 16;
            float pv[16];
            float mx = -1e30f;
#pragma unroll
            for (int c = 0; c < 16; c++){
                const float sv = Ssm[r * 68 + sg + c] * 0.125f + mskf[sg + c];
                pv[c] = sv;
                mx = fmaxf(mx, sv);
            }
            mx = fmaxf(mx, __shfl_xor_sync(0xffffffffu, mx, 1));
            mx = fmaxf(mx, __shfl_xor_sync(0xffffffffu, mx, 2));
            const float mold = mrow[r];
            const float mnew = fmaxf(mold, mx);
            const float fac = __expf(mold - mnew);
            float sum = 0.f;
#pragma unroll
            for (int c = 0; c < 16; c++){
                const float p = __expf(pv[c] - mnew);
                pv[c] = p;
                sum += p;
            }
            sum += __shfl_xor_sync(0xffffffffu, sum, 1);
            sum += __shfl_xor_sync(0xffffffffu, sum, 2);
#pragma unroll
            for (int c = 0; c < 16; c += 2){
                *(__nv_bfloat162*)(uintptr_t)(sm + FO_P + r * 272 + (sg + c) * 2)       = hi2(pv[c], pv[c + 1]);
                *(__nv_bfloat162*)(uintptr_t)(sm + FO_P + r * 272 + 128 + (sg + c) * 2) = lo2(pv[c], pv[c + 1]);
            }
            if ((tid & 3) == 0){
                facs[r] = fac;
                mrow[r] = mnew;
                lrow[r] = lrow[r] * fac + sum;
            }
        }
        __syncthreads();

        {
            const int r0 = wm * 32 + (lane >> 2);
            const float f00 = facs[r0],     f01 = facs[r0 + 8];
            const float f10 = facs[r0 + 16], f11 = facs[r0 + 24];
#pragma unroll
            for (int j = 0; j < 2; j++){
                o[0][j][0] *= f00; o[0][j][1] *= f00; o[0][j][2] *= f01; o[0][j][3] *= f01;
                o[1][j][0] *= f10; o[1][j][1] *= f10; o[1][j][2] *= f11; o[1][j][3] *= f11;
            }
        }
#pragma unroll
        for (int s = 0; s < 12; s++){
            const int ab = (s < 4) ? s * 32 : (s < 8) ? 128 + (s - 4) * 32 : (s - 8) * 32;
            const int vr = (s < 8) ? (s & 3) * 16 : 64 + (s - 8) * 16;
            uint32_t a[2][4];
#pragma unroll
            for (int i = 0; i < 2; i++)
                ldsm4(a[i][0], a[i][1], a[i][2], a[i][3],
                      sb + FO_P + (wm * 32 + i * 16 + (lane & 15)) * 272 + ab + ((lane >> 4) * 16));
            uint32_t v0, v1, v2, v3;
            ldsm4t(v0, v1, v2, v3,
                   sb + FO_V + (vr + (lane & 15)) * 144 + (wn * 16 + ((lane & 16) ? 8 : 0)) * 2);
#pragma unroll
            for (int i = 0; i < 2; i++){
                mma16816(o[i][0], a[i][0], a[i][1], a[i][2], a[i][3], v0, v1);
                mma16816(o[i][1], a[i][0], a[i][1], a[i][2], a[i][3], v2, v3);
            }
        }
    }

    {
        const int r0 = wm * 32 + (lane >> 2), c0 = wn * 16 + (lane & 3) * 2;
#pragma unroll
        for (int i = 0; i < 2; i++){
            const int rA = r0 + i * 16, rB = rA + 8;
            const float invA = 1.0f / lrow[rA];
            const float invB = 1.0f / lrow[rB];
#pragma unroll
            for (int j = 0; j < 2; j++){
                const float a0 = o[i][j][0] * invA, a1 = o[i][j][1] * invA;
                const float a2 = o[i][j][2] * invB, a3 = o[i][j][3] * invB;
                const int col = h * 64 + c0 + j * 8;
                const size_t gA = (basebl + q0 + rA) * 1536;
                const size_t gB = (basebl + q0 + rB) * 1536;
                *(__nv_bfloat162*)&AO3[gA + col]        = hi2(a0, a1);
                *(__nv_bfloat162*)&AO3[gA + 512 + col]  = lo2(a0, a1);
                *(__nv_bfloat162*)&AO3[gA + 1024 + col] = hi2(a0, a1);
                *(__nv_bfloat162*)&AO3[gB + col]        = hi2(a2, a3);
                *(__nv_bfloat162*)&AO3[gB + 512 + col]  = lo2(a2, a3);
                *(__nv_bfloat162*)&AO3[gB + 1024 + col] = hi2(a2, a3);
            }
        }
    }
}

// =====================================================================
// Depthwise causal conv (KC=4) + SiLU; float4 (4 channels/thread)
// =====================================================================
__global__ __launch_bounds__(256) void conv_silu(
    const float* __restrict__ xz, const float* __restrict__ cw,
    const float* __restrict__ cb, float* __restrict__ u, bf16* __restrict__ u3)
{
    const long idx = (long)blockIdx.x * 256 + threadIdx.x;  // over M*256
    const int c = (int)(idx & 255) * 4;
    const int m = (int)(idx >> 8);
    const int b = m / cL, l = m % cL;
    F4U acc; acc.f4 = *(const float4*)&cb[c];
    F4U w0, w1, w2, w3;
    w0.f4 = *(const float4*)&cw[c * 4];
    w1.f4 = *(const float4*)&cw[(c + 1) * 4];
    w2.f4 = *(const float4*)&cw[(c + 2) * 4];
    w3.f4 = *(const float4*)&cw[(c + 3) * 4];
#pragma unroll
    for (int k = 0; k < 4; k++){
        const int ls = l + k - 3;
        if (ls >= 0){
            F4U xv; xv.f4 = *(const float4*)&xz[(size_t)(b * cL + ls) * (2 * cDI) + c];
            acc.f[0] += xv.f[0] * w0.f[k];
            acc.f[1] += xv.f[1] * w1.f[k];
            acc.f[2] += xv.f[2] * w2.f[k];
            acc.f[3] += xv.f[3] * w3.f[k];
        }
    }
#pragma unroll
    for (int e = 0; e < 4; e++) acc.f[e] = acc.f[e] / (1.0f + __expf(-acc.f[e]));
    *(float4*)&u[(size_t)m * cDI + c] = acc.f4;
    const size_t r3 = (size_t)m * 3072;
    __nv_bfloat162 hh[2] = { hi2(acc.f[0], acc.f[1]), hi2(acc.f[2], acc.f[3]) };
    __nv_bfloat162 ll[2] = { lo2(acc.f[0], acc.f[1]), lo2(acc.f[2], acc.f[3]) };
    *(uint2*)&u3[r3 + c]        = *(uint2*)hh;
    *(uint2*)&u3[r3 + 1024 + c] = *(uint2*)ll;
    *(uint2*)&u3[r3 + 2048 + c] = *(uint2*)hh;
}

// =====================================================================
// Selective scan: warp per (b, d); writes y3 triple
// =====================================================================
__global__ __launch_bounds__(256) void mamba_scan(
    const float* __restrict__ delta, const float* __restrict__ u,
    const float* __restrict__ xdbc, const float* __restrict__ xz,
    const float* __restrict__ A_log, const float* __restrict__ Dssm,
    bf16* __restrict__ y3)
{
    const int warp = threadIdx.x >> 5, lane = threadIdx.x & 31;
    const int d = blockIdx.x * 8 + warp;
    const int b = blockIdx.y;
    const float a0 = -__expf(A_log[d * cS + 2 * lane]);
    const float a1 = -__expf(A_log[d * cS + 2 * lane + 1]);
    const float Dd = Dssm[d];
    float h0 = 0.f, h1 = 0.f;
    const size_t base = (size_t)b * cL;

    for (int t = 0; t < cL; t++){
        const size_t m = base + t;
        const float dt = __ldg(&delta[m * cDI + d]);
        const float uu = __ldg(&u[m * cDI + d]);
        const float2 Bv = *(const float2*)&xdbc[m * 160 + 32 + 2 * lane];
        const float2 Cv = *(const float2*)&xdbc[m * 160 + 96 + 2 * lane];
        const float du = dt * uu;
        h0 = h0 * __expf(dt * a0) + du * Bv.x;
        h1 = h1 * __expf(dt * a1) + du * Bv.y;
        float p = h0 * Cv.x + h1 * Cv.y;
        p += __shfl_xor_sync(0xffffffffu, p, 16);
        p += __shfl_xor_sync(0xffffffffu, p, 8);
        p += __shfl_xor_sync(0xffffffffu, p, 4);
        p += __shfl_xor_sync(0xffffffffu, p, 2);
        p += __shfl_xor_sync(0xffffffffu, p, 1);
        if (lane == 0){
            const float z = xz[m * (2 * cDI) + cDI + d];
            float yv = p + uu * Dd;
            yv *= z / (1.0f + __expf(-z));
            const size_t r3 = m * 3072;
            y3[r3 + d]        = hi_bf(yv);
            y3[r3 + 1024 + d] = lo_bf(yv);
            y3[r3 + 2048 + d] = hi_bf(yv);
        }
    }
}

// =====================================================================
// Fused residual + LN1 + LN2; writes h (fp32) and hn3 (triple)
// =====================================================================
__device__ __forceinline__ float blockSum256(float v, float* red){
#pragma unroll
    for (int off = 16; off > 0; off >>= 1) v += __shfl_xor_sync(0xffffffffu, v, off);
    if ((threadIdx.x & 31) == 0) red[threadIdx.x >> 5] = v;
    __syncthreads();
    const float s = red[0]+red[1]+red[2]+red[3]+red[4]+red[5]+red[6]+red[7];
    __syncthreads();
    return s;
}

__global__ __launch_bounds__(256) void ln_fuse(
    const float* __restrict__ xf, const float* __restrict__ attn, const float* __restrict__ mamba,
    const float* __restrict__ g1, const float* __restrict__ b1,
    const float* __restrict__ g2, const float* __restrict__ b2,
    float* __restrict__ h, bf16* __restrict__ hn3)
{
    __shared__ float red[8];
    const size_t m = blockIdx.x;
    const int t = threadIdx.x * 2;
    const size_t r = m * cD;
    const float2 xv = *(const float2*)&xf[r + t];
    const float2 av = *(const float2*)&attn[r + t];
    const float2 mv = *(const float2*)&mamba[r + t];
    float v0 = xv.x + av.x + mv.x;
    float v1 = xv.y + av.y + mv.y;

    const float mean = blockSum256(v0 + v1, red) * (1.0f / cD);
    const float d0 = v0 - mean, d1 = v1 - mean;
    const float var = blockSum256(d0 * d0 + d1 * d1, red) * (1.0f / cD);
    const float inv = rsqrtf(var + 1e-5f);
    const float2 g1v = *(const float2*)&g1[t];
    const float2 b1v = *(const float2*)&b1[t];
    const float h0 = d0 * inv * g1v.x + b1v.x;
    const float h1 = d1 * inv * g1v.y + b1v.y;
    *(float2*)&h[r + t] = make_float2(h0, h1);

    const float mean2 = blockSum256(h0 + h1, red) * (1.0f / cD);
    const float e0 = h0 - mean2, e1 = h1 - mean2;
    const float var2 = blockSum256(e0 * e0 + e1 * e1, red) * (1.0f / cD);
    const float inv2 = rsqrtf(var2 + 1e-6f);
    const float2 g2v = *(const float2*)&g2[t];
    const float2 b2v = *(const float2*)&b2[t];
    const float n0 = e0 * inv2 * g2v.x + b2v.x;
    const float n1 = e1 * inv2 * g2v.y + b2v.y;
    const size_t r3 = m * 1536;
    *(__nv_bfloat162*)&hn3[r3 + t]        = hi2(n0, n1);
    *(__nv_bfloat162*)&hn3[r3 + 512 + t]  = lo2(n0, n1);
    *(__nv_bfloat162*)&hn3[r3 + 1024 + t] = hi2(n0, n1);
}

// =====================================================================
// Launch
// =====================================================================
static inline int sgrid(long rows, int k3p){
    return (int)((rows * (k3p >> 3) + 255) / 256);
}

extern "C" void kernel_launch(void* const* d_in, const int* in_sizes, int n_in,
                              void* d_out, int out_size)
{
    (void)in_sizes; (void)n_in; (void)out_size;
    const float* x      = (const float*)d_in[0];
    const unsigned char* mask = (const unsigned char*)d_in[1];
    const float* Wq = (const float*)d_in[2];  const float* bq = (const float*)d_in[3];
    const float* Wk = (const float*)d_in[4];  const float* bk = (const float*)d_in[5];
    const float* Wv = (const float*)d_in[6];  const float* bv = (const float*)d_in[7];
    const float* Wo = (const float*)d_in[8];  const float* bo = (const float*)d_in[9];
    const float* in_w   = (const float*)d_in[10];
    const float* conv_w = (const float*)d_in[11];
    const float* conv_b = (const float*)d_in[12];
    const float* xproj_w= (const float*)d_in[13];
    const float* dt_w   = (const float*)d_in[14];
    const float* dt_b   = (const float*)d_in[15];
    const float* A_log  = (const float*)d_in[16];
    const float* Dssm   = (const float*)d_in[17];
    const float* outp_w = (const float*)d_in[18];
    const float* ln1g   = (const float*)d_in[19];
    const float* ln1b   = (const float*)d_in[20];
    const float* fw1    = (const float*)d_in[21];
    const float* fb1    = (const float*)d_in[22];
    const float* fw2    = (const float*)d_in[23];
    const float* fb2    = (const float*)d_in[24];
    const float* ln2g   = (const float*)d_in[25];
    const float* ln2b   = (const float*)d_in[26];
    float* out = (float*)d_out;

    float *qkv,*attn,*xz,*u,*xdbc,*dlt,*mmb,*h;
    cudaGetSymbolAddress((void**)&qkv,  g_qkv);
    cudaGetSymbolAddress((void**)&attn, g_attn);
    cudaGetSymbolAddress((void**)&xz,   g_xz);
    cudaGetSymbolAddress((void**)&u,    g_u);
    cudaGetSymbolAddress((void**)&xdbc, g_xdbc);
    cudaGetSymbolAddress((void**)&dlt,  g_dlt);
    cudaGetSymbolAddress((void**)&mmb,  g_mmb);
    cudaGetSymbolAddress((void**)&h,    g_h);

    bf16 *px3,*pao3,*pu3,*pxdbc3,*py3,*phn3,*pff13;
    bf16 *pwqkv,*pwo,*pwin,*pwxp,*pwdt,*pwout,*pwf1,*pwf2;
    cudaGetSymbolAddress((void**)&px3,   gx3);
    cudaGetSymbolAddress((void**)&pao3,  gao3);
    cudaGetSymbolAddress((void**)&pu3,   gu3);
    cudaGetSymbolAddress((void**)&pxdbc3,gxdbc3);
    cudaGetSymbolAddress((void**)&py3,   gy3);
    cudaGetSymbolAddress((void**)&phn3,  ghn3);
    cudaGetSymbolAddress((void**)&pff13, gff13);
    cudaGetSymbolAddress((void**)&pwqkv, wqkv3);
    cudaGetSymbolAddress((void**)&pwo,   wo3);
    cudaGetSymbolAddress((void**)&pwin,  win3);
    cudaGetSymbolAddress((void**)&pwxp,  wxp3);
    cudaGetSymbolAddress((void**)&pwdt,  wdt3);
    cudaGetSymbolAddress((void**)&pwout, wout3);
    cudaGetSymbolAddress((void**)&pwf1,  wff13);
    cudaGetSymbolAddress((void**)&pwf2,  wff23);

    cudaFuncSetAttribute(flash_mma, cudaFuncAttributeMaxDynamicSharedMemorySize, FLASH_SMEM);
    cudaFuncSetAttribute(hmma_gemm<0,false>, cudaFuncAttributeMaxDynamicSharedMemorySize, GEMM_SMEM);
    cudaFuncSetAttribute(hmma_gemm<1,false>, cudaFuncAttributeMaxDynamicSharedMemorySize, GEMM_SMEM);
    cudaFuncSetAttribute(hmma_gemm<2,false>, cudaFuncAttributeMaxDynamicSharedMemorySize, GEMM_SMEM);
    cudaFuncSetAttribute(hmma_gemm<3,true>,  cudaFuncAttributeMaxDynamicSharedMemorySize, GEMM_SMEM);
    cudaFuncSetAttribute(hmma_gemm<4,false>, cudaFuncAttributeMaxDynamicSharedMemorySize, GEMM_SMEM);
    cudaFuncSetAttribute(hmma_gemm<5,false>, cudaFuncAttributeMaxDynamicSharedMemorySize, GEMM_SMEM);

    // ---- fused weight-split table ----
    WTab tab;
    long base = 0;
    auto add = [&](int i, const float* src, bf16* dst, int K, int k3p, long rows){
        tab.e[i] = {src, dst, K, k3p, rows, base};
        base += rows * (k3p >> 3);
    };
    add(0, Wq,      pwqkv,               512,  1536, 512);
    add(1, Wk,      pwqkv + 512 * 1536,  512,  1536, 512);
    add(2, Wv,      pwqkv + 1024 * 1536, 512,  1536, 512);
    add(3, Wo,      pwo,                 512,  1536, 512);
    add(4, in_w,    pwin,                512,  1536, 2048);
    add(5, xproj_w, pwxp,                1024, 3072, 160);
    add(6, dt_w,    pwdt,                32,   128,  1024);
    add(7, outp_w,  pwout,               1024, 3072, 512);
    add(8, fw1,     pwf1,                512,  1536, 2048);
    add(9, fw2,     pwf2,                2048, 6144, 512);
    const int wgrid = (int)((base + 255) / 256);

    cudaStream_t s0 = 0, sB = g_sh.sB;

    // slot 0, 1
    split3_wgt_all<<<wgrid, 256, 0, s0>>>(tab);
    split3_act_fast<<<sgrid(cM, 1536), 256, 0, s0>>>(x, 512, 512, px3, 1536, cM);

    cudaEventRecord(g_sh.evRoot, s0);
    cudaStreamWaitEvent(sB, g_sh.evRoot, 0);

    // slot 2: fused QKV GEMM with tri-bias epilogue
    hmma_gemm<5,false><<<dim3(12, 72), 512, GEMM_SMEM, s0>>>(px3, 1536, pwqkv, 1536, bq, bk, bv, nullptr, qkv, nullptr, 1536);
    // slot 3: flash attention (ncu target)
    flash_mma<<<dim3(cL / 64, cB * 8), 256, FLASH_SMEM, s0>>>(qkv, mask, pao3);
    hmma_gemm<1,false><<<dim3(4, 72), 512, GEMM_SMEM, s0>>>(pao3, 1536, pwo, 1536, bo, nullptr, nullptr, nullptr, attn, nullptr, 512);

    // mamba branch on sB
    hmma_gemm<0,false><<<dim3(16, 72), 512, GEMM_SMEM, sB>>>(px3, 1536, pwin, 1536, nullptr, nullptr, nullptr, nullptr, xz, nullptr, 2048);
    conv_silu<<<(cM * 256) / 256, 256, 0, sB>>>(xz, conv_w, conv_b, u, pu3);
    hmma_gemm<0,false><<<dim3(2, 72), 512, GEMM_SMEM, sB>>>(pu3, 3072, pwxp, 3072, nullptr, nullptr, nullptr, nullptr, xdbc, nullptr, 160);
    split3_act_fast<<<sgrid(cM, 128), 256, 0, sB>>>(xdbc, 160, 32, pxdbc3, 128, cM);
    hmma_gemm<2,false><<<dim3(8, 72), 512, GEMM_SMEM, sB>>>(pxdbc3, 128, pwdt, 128, dt_b, nullptr, nullptr, nullptr, dlt, nullptr, 1024);
    mamba_scan<<<dim3(cDI / 8, cB), 256, 0, sB>>>(dlt, u, xdbc, xz, A_log, Dssm, py3);
    hmma_gemm<0,false><<<dim3(4, 72), 512, GEMM_SMEM, sB>>>(py3, 3072, pwout, 3072, nullptr, nullptr, nullptr, nullptr, mmb, nullptr, 512);
    cudaEventRecord(g_sh.evB, sB);

    cudaStreamWaitEvent(s0, g_sh.evB, 0);
    ln_fuse<<<cM, 256, 0, s0>>>(x, attn, mmb, ln1g, ln1b, ln2g, ln2b, h, phn3);
    hmma_gemm<3,true><<<dim3(16, 72), 512, GEMM_SMEM, s0>>>(phn3, 1536, pwf1, 1536, fb1, nullptr, nullptr, nullptr, nullptr, pff13, 2048);
    hmma_gemm<4,false><<<dim3(4, 72), 512, GEMM_SMEM, s0>>>(pff13, 6144, pwf2, 6144, fb2, nullptr, nullptr, h, out, nullptr, 512);
}

// round 10
// speedup vs baseline: 1.5715x; 1.0475x over previous
#include <cuda_runtime.h>
#include <cuda_bf16.h>
#include <cstdint>
#include <math.h>

typedef __nv_bfloat16 bf16;

// ---------------- dims ----------------
static const int cB  = 8;
static const int cL  = 1152;      // T*W
static const int cD  = 512;
static const int cDI = 1024;
static const int cS  = 64;
static const int cDFF= 2048;
static const int cM  = 9216;      // B*L

// ---------------- fp32 workspaces ----------------
__device__ float g_qkv [cM*1536];
__device__ float g_attn[cM*cD];
__device__ float g_xz  [cM*2*cDI];
__device__ float g_u   [cM*cDI];
__device__ float g_xdbc[cM*160];
__device__ float g_dlt [cM*cDI];
__device__ float g_mmb [cM*cD];
__device__ float g_h   [cM*cD];

// ---------------- bf16 split-2 storage [hi|lo] (block2 remapped) -------
__device__ bf16 gx2   [cM*1024];
__device__ bf16 gao2  [cM*1024];
__device__ bf16 gu2   [cM*2048];
__device__ bf16 gxdbc2[cM*64];
__device__ bf16 gy2   [cM*2048];
__device__ bf16 ghn2  [cM*1024];
__device__ bf16 gff12 [cM*4096];

__device__ bf16 wqkv2[1536*1024];
__device__ bf16 wo2  [512*1024];
__device__ bf16 win2 [2048*1024];
__device__ bf16 wxp2 [160*2048];
__device__ bf16 wdt2 [1024*64];
__device__ bf16 wout2[512*2048];
__device__ bf16 wff12[2048*1024];
__device__ bf16 wff22[512*4096];

// ---------------- streams (static init) ----------------
struct StreamHolder {
    cudaStream_t sB;
    cudaEvent_t evRoot, evB;
    StreamHolder(){
        cudaStreamCreateWithFlags(&sB, cudaStreamNonBlocking);
        cudaEventCreateWithFlags(&evRoot, cudaEventDisableTiming);
        cudaEventCreateWithFlags(&evB,   cudaEventDisableTiming);
    }
};
static StreamHolder g_sh;

// ---------------- helpers ----------------
union F4U { float4 f4; unsigned long long l[2]; float f[4]; };
union BU  { __nv_bfloat162 b; uint32_t u; };

__device__ __forceinline__ float softplus_f(float v){
    return fmaxf(v, 0.0f) + log1pf(__expf(-fabsf(v)));
}
__device__ __forceinline__ float gelu_f(float v){
    return 0.5f * v * (1.0f + erff(v * 0.70710678118654752f));
}
__device__ __forceinline__ bf16 hi_bf(float a){ return __float2bfloat16(a); }
__device__ __forceinline__ bf16 lo_bf(float a){
    bf16 h = __float2bfloat16(a);
    return __float2bfloat16(a - __bfloat162float(h));
}
__device__ __forceinline__ __nv_bfloat162 hi2(float a, float b){
    return __floats2bfloat162_rn(a, b);
}
__device__ __forceinline__ __nv_bfloat162 lo2(float a, float b){
    __nv_bfloat162 h = __floats2bfloat162_rn(a, b);
    return __floats2bfloat162_rn(a - __bfloat162float(h.x), b - __bfloat162float(h.y));
}
__device__ __forceinline__ uint32_t hi2u(float a, float b){ BU t; t.b = hi2(a, b); return t.u; }
__device__ __forceinline__ uint32_t lo2u(float a, float b){ BU t; t.b = lo2(a, b); return t.u; }

__device__ __forceinline__ uint32_t smem_u32(const void* p){
    uint32_t a;
    asm("{ .reg .u64 t; cvta.to.shared.u64 t, %1; cvt.u32.u64 %0, t; }" : "=r"(a) : "l"(p));
    return a;
}
__device__ __forceinline__ void cp16(uint32_t dst, const void* src){
    asm volatile("cp.async.cg.shared.global [%0], [%1], 16;" :: "r"(dst), "l"(src));
}
__device__ __forceinline__ void ldsm4(uint32_t &r0, uint32_t &r1, uint32_t &r2, uint32_t &r3, uint32_t addr){
    asm volatile("ldmatrix.sync.aligned.m8n8.x4.shared.b16 {%0,%1,%2,%3}, [%4];"
        : "=r"(r0), "=r"(r1), "=r"(r2), "=r"(r3) : "r"(addr));
}
__device__ __forceinline__ void ldsm4t(uint32_t &r0, uint32_t &r1, uint32_t &r2, uint32_t &r3, uint32_t addr){
    asm volatile("ldmatrix.sync.aligned.m8n8.x4.trans.shared.b16 {%0,%1,%2,%3}, [%4];"
        : "=r"(r0), "=r"(r1), "=r"(r2), "=r"(r3) : "r"(addr));
}
__device__ __forceinline__ void mma16816(float* c, uint32_t a0, uint32_t a1, uint32_t a2, uint32_t a3,
                                         uint32_t b0, uint32_t b1){
    asm volatile("mma.sync.aligned.m16n8k16.row.col.f32.bf16.bf16.f32 "
        "{%0,%1,%2,%3}, {%4,%5,%6,%7}, {%8,%9}, {%0,%1,%2,%3};"
        : "+f"(c[0]), "+f"(c[1]), "+f"(c[2]), "+f"(c[3])
        : "r"(a0), "r"(a1), "r"(a2), "r"(a3), "r"(b0), "r"(b1));
}

// =====================================================================
// split2: fp32 [rows x K] (stride lda) -> bf16 [rows x 2K] = [hi | lo]
// =====================================================================
__global__ __launch_bounds__(256) void split2(
    const float* __restrict__ in, int lda, int K,
    bf16* __restrict__ out, long rows)
{
    const int chunks = K >> 2;           // (2K)/8
    const long idx = (long)blockIdx.x * 256 + threadIdx.x;
    if (idx >= rows * chunks) return;
    const int row = (int)(idx / chunks);
    const int kc = (int)(idx - (long)row * chunks);
    const int blk = (kc * 8) / K;
    const int within = kc * 8 - blk * K;
    const float* src = in + (size_t)row * lda + within;
    F4U s0, s1; s0.f4 = *(const float4*)src; s1.f4 = *(const float4*)(src + 4);
    __nv_bfloat162 o[4];
    if (blk == 1){
        o[0] = lo2(s0.f[0], s0.f[1]); o[1] = lo2(s0.f[2], s0.f[3]);
        o[2] = lo2(s1.f[0], s1.f[1]); o[3] = lo2(s1.f[2], s1.f[3]);
    } else {
        o[0] = hi2(s0.f[0], s0.f[1]); o[1] = hi2(s0.f[2], s0.f[3]);
        o[2] = hi2(s1.f[0], s1.f[1]); o[3] = hi2(s1.f[2], s1.f[3]);
    }
    *(uint4*)&out[(size_t)row * (2 * K) + kc * 8] = *(uint4*)o;
}

// fused weight split (one launch for all 10 weights)
struct WSpec { const float* src; bf16* dst; int K; long rows; long base; };
struct WTab  { WSpec e[10]; };

__global__ __launch_bounds__(256) void split2_wgt_all(WTab tab)
{
    const long idx = (long)blockIdx.x * 256 + threadIdx.x;
    int i = 0;
#pragma unroll
    for (int j = 1; j < 10; j++) if (idx >= tab.e[j].base) i = j;
    const WSpec w = tab.e[i];
    const long local = idx - w.base;
    const int chunks = w.K >> 2;
    if (local >= w.rows * chunks) return;
    const int row = (int)(local / chunks);
    const int kc = (int)(local - (long)row * chunks);
    const int blk = (kc * 8) / w.K;
    const int within = kc * 8 - blk * w.K;
    const float* src = w.src + (size_t)row * w.K + within;
    F4U s0, s1; s0.f4 = *(const float4*)src; s1.f4 = *(const float4*)(src + 4);
    __nv_bfloat162 o[4];
    if (blk == 1){
        o[0] = lo2(s0.f[0], s0.f[1]); o[1] = lo2(s0.f[2], s0.f[3]);
        o[2] = lo2(s1.f[1-1], s1.f[1]); o[2] = lo2(s1.f[0], s1.f[1]); o[3] = lo2(s1.f[2], s1.f[3]);
    } else {
        o[0] = hi2(s0.f[0], s0.f[1]); o[1] = hi2(s0.f[2], s0.f[3]);
        o[2] = hi2(s1.f[0], s1.f[1]); o[3] = hi2(s1.f[2], s1.f[3]);
    }
    *(uint4*)&w.dst[(size_t)row * (2 * w.K) + kc * 8] = *(uint4*)o;
}

// =====================================================================
// HMMA GEMM: logical K3 = 3*Ka over [hi|lo|hi]A x [hi|hi|lo]W, stored 2K.
// 512 threads, 16 warps (4x4 of 32x32), CTA 128x128, BK=32, 3-stage.
// EPI: 0 none 1 bias 2 bias+softplus 3 bias+gelu 4 bias+res 5 tri-bias
// OUT3: bf16 [hi|lo] output, pitch 2N
// =====================================================================
#define TILE_BYTES 20480
#define GEMM_SMEM  (3 * TILE_BYTES)
template<int EPI, bool OUT3>
__global__ __launch_bounds__(512, 2) void hmma_gemm(
    const bf16* __restrict__ A2, const bf16* __restrict__ W2, int Ka,
    const float* __restrict__ bias, const float* __restrict__ bias_b,
    const float* __restrict__ bias_c, const float* __restrict__ res,
    float* __restrict__ C, bf16* __restrict__ C3, int N)
{
    extern __shared__ char smem[];
    const uint32_t sb = smem_u32(smem);
    const int tid = threadIdx.x;
    const int wid = tid >> 5, lane = tid & 31;
    const int bm = blockIdx.y * 128;
    const int bn = blockIdx.x * 128;
    const int wm = wid & 3, wn = wid >> 2;
    const int pitch = 2 * Ka;

    float acc[2][4][4];
#pragma unroll
    for (int i = 0; i < 2; i++)
#pragma unroll
        for (int j = 0; j < 4; j++)
#pragma unroll
            for (int e = 0; e < 4; e++) acc[i][j][e] = 0.f;

    const int NC = (3 * Ka) >> 5;

    auto load_tile = [&](int ci, uint32_t sbase){
        const int lcbase = ci * 32;
        int acol = lcbase; if (acol >= 2 * Ka) acol -= 2 * Ka;
        int wcol = lcbase; if (wcol >= Ka) wcol -= Ka;
#pragma unroll
        for (int cc = 0; cc < 2; cc++){
            const int c = tid + cc * 512;
            if (c < 512){
                const int row = c >> 2, ch = c & 3;
                cp16(sbase + row * 80 + ch * 16,
                     &A2[(size_t)(bm + row) * pitch + acol + ch * 8]);
            } else {
                const int c2 = c - 512;
                const int row = c2 >> 2, ch = c2 & 3;
                int br = bn + row; if (br >= N) br = N - 1;
                cp16(sbase + 128 * 80 + row * 80 + ch * 16,
                     &W2[(size_t)br * pitch + wcol + ch * 8]);
            }
        }
        asm volatile("cp.async.commit_group;" ::: "memory");
    };

    load_tile(0, sb);
    if (NC > 1) load_tile(1, sb + TILE_BYTES);

    const uint32_t aOff = (uint32_t)((wm * 32 + (lane & 15)) * 80 + (lane >> 4) * 16);
    const uint32_t bOff = (uint32_t)(128 * 80 +
                          (wn * 32 + (lane & 7) + ((lane & 16) ? 8 : 0)) * 80 +
                          ((lane >> 3) & 1) * 16);

    for (int ci = 0; ci < NC; ci++){
        if (ci + 1 < NC) asm volatile("cp.async.wait_group 1;" ::: "memory");
        else             asm volatile("cp.async.wait_group 0;" ::: "memory");
        __syncthreads();
        if (ci + 2 < NC){
            const int nb = (ci + 2) % 3;
            load_tile(ci + 2, sb + (uint32_t)nb * TILE_BYTES);
        }
        const uint32_t cur = sb + (uint32_t)(ci % 3) * TILE_BYTES;

#pragma unroll
        for (int s = 0; s < 2; s++){
            uint32_t a[2][4];
#pragma unroll
            for (int i = 0; i < 2; i++)
                ldsm4(a[i][0], a[i][1], a[i][2], a[i][3], cur + aOff + i * (16 * 80) + s * 32);
            uint32_t b0, b1, b2, b3, b4, b5, b6, b7;
            ldsm4(b0, b1, b2, b3, cur + bOff + s * 32);
            ldsm4(b4, b5, b6, b7, cur + bOff + 16 * 80 + s * 32);
#pragma unroll
            for (int i = 0; i < 2; i++){
                mma16816(acc[i][0], a[i][0], a[i][1], a[i][2], a[i][3], b0, b1);
                mma16816(acc[i][1], a[i][0], a[i][1], a[i][2], a[i][3], b2, b3);
                mma16816(acc[i][2], a[i][0], a[i][1], a[i][2], a[i][3], b4, b5);
                mma16816(acc[i][3], a[i][0], a[i][1], a[i][2], a[i][3], b6, b7);
            }
        }
    }

    const int t4 = lane >> 2, tp = (lane & 3) * 2;
#pragma unroll
    for (int i = 0; i < 2; i++){
#pragma unroll
        for (int j = 0; j < 4; j++){
            const int col = bn + wn * 32 + j * 8 + tp;
            if (col >= N) continue;
            const int row0 = bm + wm * 32 + i * 16 + t4;
            float v0 = acc[i][j][0], v1 = acc[i][j][1];
            float v2 = acc[i][j][2], v3 = acc[i][j][3];
            if (EPI >= 1 && EPI <= 4){
                const float bb0 = bias[col], bb1 = bias[col + 1];
                v0 += bb0; v1 += bb1; v2 += bb0; v3 += bb1;
            }
            if (EPI == 5){
                const float* bp = (col < 512) ? bias : (col < 1024) ? (bias_b - 512) : (bias_c - 1024);
                const float bb0 = bp[col], bb1 = bp[col + 1];
                v0 += bb0; v1 += bb1; v2 += bb0; v3 += bb1;
            }
            if (EPI == 2){ v0 = softplus_f(v0); v1 = softplus_f(v1); v2 = softplus_f(v2); v3 = softplus_f(v3); }
            if (EPI == 3){ v0 = gelu_f(v0); v1 = gelu_f(v1); v2 = gelu_f(v2); v3 = gelu_f(v3); }
            if (EPI == 4){
                v0 += res[(size_t)row0 * N + col];
                v1 += res[(size_t)row0 * N + col + 1];
                v2 += res[(size_t)(row0 + 8) * N + col];
                v3 += res[(size_t)(row0 + 8) * N + col + 1];
            }
            if (OUT3){
                const size_t r0 = (size_t)row0 * (2 * N), r1 = (size_t)(row0 + 8) * (2 * N);
                *(__nv_bfloat162*)&C3[r0 + col]     = hi2(v0, v1);
                *(__nv_bfloat162*)&C3[r0 + N + col] = lo2(v0, v1);
                *(__nv_bfloat162*)&C3[r1 + col]     = hi2(v2, v3);
                *(__nv_bfloat162*)&C3[r1 + N + col] = lo2(v2, v3);
            } else {
                *(float2*)&C[(size_t)row0 * N + col]       = make_float2(v0, v1);
                *(float2*)&C[(size_t)(row0 + 8) * N + col] = make_float2(v2, v3);
            }
        }
    }
}

// =====================================================================
// Flash attention v2: register-resident softmax + P.
// 128 q-rows/CTA, warp owns 16 rows x 64 keys. No S/P smem.
// Q smem [128][hi64|lo64] pitch 272; K [64][hi|lo] pitch 272;
// V [Vh rows 0-63 | Vl rows 64-127][64e] pitch 144.
// =====================================================================
#define FQ 0
#define FK 34816
#define FV 52224
#define FMSK 70656
#define FLASH_SMEM 70912

__global__ __launch_bounds__(256, 2) void flash_mma(
    const float* __restrict__ QKV, const unsigned char* __restrict__ mask,
    bf16* __restrict__ AO2)
{
    extern __shared__ char sm[];
    const uint32_t sb = smem_u32(sm);
    float* mskf = (float*)(sm + FMSK);
    const int tid = threadIdx.x;
    const int w = tid >> 5, lane = tid & 31;
    const int t4 = lane >> 2, qq = lane & 3;
    const int bh = blockIdx.y, b = bh >> 3, h = bh & 7;
    const int q0 = blockIdx.x * 128;
    const size_t basebl = (size_t)b * cL;

    // Q load + split (once)
    for (int idx = tid; idx < 2048; idx += 256){
        const int row = idx >> 4, c4 = idx & 15;
        F4U qv; qv.f4 = *(const float4*)&QKV[(basebl + q0 + row) * 1536 + h * 64 + c4 * 4];
        char* p = sm + FQ + row * 272 + c4 * 8;
        *(__nv_bfloat162*)(p)       = hi2(qv.f[0], qv.f[1]);
        *(__nv_bfloat162*)(p + 4)   = hi2(qv.f[2], qv.f[3]);
        *(__nv_bfloat162*)(p + 128) = lo2(qv.f[0], qv.f[1]);
        *(__nv_bfloat162*)(p + 132) = lo2(qv.f[2], qv.f[3]);
    }

    float m0 = -1e30f, m1 = -1e30f, l0 = 0.f, l1 = 0.f;
    float o[8][4];
#pragma unroll
    for (int nt = 0; nt < 8; nt++)
#pragma unroll
        for (int e = 0; e < 4; e++) o[nt][e] = 0.f;

    for (int jt = 0; jt < cL / 64; jt++){
        __syncthreads();
        for (int idx = tid; idx < 1024; idx += 256){
            const int row = idx >> 4, c4 = idx & 15;
            const size_t gr = (basebl + jt * 64 + row) * 1536 + h * 64 + c4 * 4;
            F4U kv; kv.f4 = *(const float4*)&QKV[gr + 512];
            F4U vv; vv.f4 = *(const float4*)&QKV[gr + 1024];
            char* pk = sm + FK + row * 272 + c4 * 8;
            *(__nv_bfloat162*)(pk)       = hi2(kv.f[0], kv.f[1]);
            *(__nv_bfloat162*)(pk + 4)   = hi2(kv.f[2], kv.f[3]);
            *(__nv_bfloat162*)(pk + 128) = lo2(kv.f[0], kv.f[1]);
            *(__nv_bfloat162*)(pk + 132) = lo2(kv.f[2], kv.f[3]);
            char* ph = sm + FV + row * 144 + c4 * 8;
            *(__nv_bfloat162*)(ph)     = hi2(vv.f[0], vv.f[1]);
            *(__nv_bfloat162*)(ph + 4) = hi2(vv.f[2], vv.f[3]);
            char* pl = sm + FV + (64 + row) * 144 + c4 * 8;
            *(__nv_bfloat162*)(pl)     = lo2(vv.f[0], vv.f[1]);
            *(__nv_bfloat162*)(pl + 4) = lo2(vv.f[2], vv.f[3]);
        }
        if (tid < 64) mskf[tid] = mask[b * cL + jt * 64 + tid] ? -1e30f : 0.0f;
        __syncthreads();

        // ---- QK^T: warp rows w*16..+15, all 64 keys ----
        float sacc[8][4];
#pragma unroll
        for (int nt = 0; nt < 8; nt++)
#pragma unroll
            for (int e = 0; e < 4; e++) sacc[nt][e] = 0.f;

#pragma unroll
        for (int s = 0; s < 12; s++){
            const int ab = (s < 4) ? s * 32 : (s < 8) ? 128 + (s - 4) * 32 : (s - 8) * 32;
            const int bb = (s < 8) ? (s & 3) * 32 : 128 + (s - 8) * 32;
            uint32_t a0, a1, a2, a3;
            ldsm4(a0, a1, a2, a3, sb + FQ + (w * 16 + (lane & 15)) * 272 + ab + (lane >> 4) * 16);
#pragma unroll
            for (int kc = 0; kc < 4; kc++){
                uint32_t b0, b1, b2, b3;
                ldsm4(b0, b1, b2, b3,
                      sb + FK + (kc * 16 + (lane & 7) + ((lane & 16) ? 8 : 0)) * 272 + bb + ((lane >> 3) & 1) * 16);
                mma16816(sacc[2 * kc],     a0, a1, a2, a3, b0, b1);
                mma16816(sacc[2 * kc + 1], a0, a1, a2, a3, b2, b3);
            }
        }

        // ---- in-register softmax (rows t4, t4+8 of warp's 16) ----
        float mx0 = -1e30f, mx1 = -1e30f;
#pragma unroll
        for (int nt = 0; nt < 8; nt++){
            const float2 mk = *(const float2*)&mskf[nt * 8 + qq * 2];
            sacc[nt][0] = sacc[nt][0] * 0.125f + mk.x;
            sacc[nt][1] = sacc[nt][1] * 0.125f + mk.y;
            sacc[nt][2] = sacc[nt][2] * 0.125f + mk.x;
            sacc[nt][3] = sacc[nt][3] * 0.125f + mk.y;
            mx0 = fmaxf(mx0, fmaxf(sacc[nt][0], sacc[nt][1]));
            mx1 = fmaxf(mx1, fmaxf(sacc[nt][2], sacc[nt][3]));
        }
        mx0 = fmaxf(mx0, __shfl_xor_sync(0xffffffffu, mx0, 1));
        mx0 = fmaxf(mx0, __shfl_xor_sync(0xffffffffu, mx0, 2));
        mx1 = fmaxf(mx1, __shfl_xor_sync(0xffffffffu, mx1, 1));
        mx1 = fmaxf(mx1, __shfl_xor_sync(0xffffffffu, mx1, 2));
        const float mn0 = fmaxf(m0, mx0), mn1 = fmaxf(m1, mx1);
        const float fac0 = __expf(m0 - mn0), fac1 = __expf(m1 - mn1);
        m0 = mn0; m1 = mn1;
        float sum0 = 0.f, sum1 = 0.f;
#pragma unroll
        for (int nt = 0; nt < 8; nt++){
            sacc[nt][0] = __expf(sacc[nt][0] - mn0);
            sacc[nt][1] = __expf(sacc[nt][1] - mn0);
            sacc[nt][2] = __expf(sacc[nt][2] - mn1);
            sacc[nt][3] = __expf(sacc[nt][3] - mn1);
            sum0 += sacc[nt][0] + sacc[nt][1];
            sum1 += sacc[nt][2] + sacc[nt][3];
        }
        sum0 += __shfl_xor_sync(0xffffffffu, sum0, 1);
        sum0 += __shfl_xor_sync(0xffffffffu, sum0, 2);
        sum1 += __shfl_xor_sync(0xffffffffu, sum1, 1);
        sum1 += __shfl_xor_sync(0xffffffffu, sum1, 2);
        l0 = l0 * fac0 + sum0;
        l1 = l1 * fac1 + sum1;
#pragma unroll
        for (int nt = 0; nt < 8; nt++){
            o[nt][0] *= fac0; o[nt][1] *= fac0;
            o[nt][2] *= fac1; o[nt][3] *= fac1;
        }

        // ---- P C-frags -> A-frags in registers (hi/lo split) ----
        uint32_t Ph[4][4], Pl[4][4];
#pragma unroll
        for (int kk = 0; kk < 4; kk++){
            Ph[kk][0] = hi2u(sacc[2*kk][0],   sacc[2*kk][1]);
            Ph[kk][1] = hi2u(sacc[2*kk][2],   sacc[2*kk][3]);
            Ph[kk][2] = hi2u(sacc[2*kk+1][0], sacc[2*kk+1][1]);
            Ph[kk][3] = hi2u(sacc[2*kk+1][2], sacc[2*kk+1][3]);
            Pl[kk][0] = lo2u(sacc[2*kk][0],   sacc[2*kk][1]);
            Pl[kk][1] = lo2u(sacc[2*kk][2],   sacc[2*kk][3]);
            Pl[kk][2] = lo2u(sacc[2*kk+1][0], sacc[2*kk+1][1]);
            Pl[kk][3] = lo2u(sacc[2*kk+1][2], sacc[2*kk+1][3]);
        }

        // ---- P*V: A = [Ph, Pl, Ph], V rows = [Vh, Vh, Vl] ----
#pragma unroll
        for (int s = 0; s < 12; s++){
            const uint32_t* af = (s < 4) ? Ph[s] : (s < 8) ? Pl[s - 4] : Ph[s - 8];
            const int vr = (s < 8) ? (s & 3) * 16 : 64 + (s - 8) * 16;
#pragma unroll
            for (int nb = 0; nb < 4; nb++){
                uint32_t v0, v1, v2, v3;
                ldsm4t(v0, v1, v2, v3,
                       sb + FV + (vr + (lane & 15)) * 144 + (nb * 16 + ((lane & 16) ? 8 : 0)) * 2);
                mma16816(o[2 * nb],     af[0], af[1], af[2], af[3], v0, v1);
                mma16816(o[2 * nb + 1], af[0], af[1], af[2], af[3], v2, v3);
            }
        }
    }

    // ---- epilogue: normalize + write [hi|lo] (pitch 1024) ----
    const float i0 = 1.0f / l0, i1 = 1.0f / l1;
    const size_t gA = (basebl + q0 + w * 16 + t4) * 1024;
    const size_t gB = gA + 8 * 1024;
#pragma unroll
    for (int nt = 0; nt < 8; nt++){
        const float a0 = o[nt][0] * i0, a1 = o[nt][1] * i0;
        const float a2 = o[nt][2] * i1, a3 = o[nt][3] * i1;
        const int col = h * 64 + nt * 8 + qq * 2;
        *(__nv_bfloat162*)&AO2[gA + col]       = hi2(a0, a1);
        *(__nv_bfloat162*)&AO2[gA + 512 + col] = lo2(a0, a1);
        *(__nv_bfloat162*)&AO2[gB + col]       = hi2(a2, a3);
        *(__nv_bfloat162*)&AO2[gB + 512 + col] = lo2(a2, a3);
    }
}

// =====================================================================
// Depthwise causal conv (KC=4) + SiLU; float4; writes u + u2 [hi|lo]
// =====================================================================
__global__ __launch_bounds__(256) void conv_silu(
    const float* __restrict__ xz, const float* __restrict__ cw,
    const float* __restrict__ cb, float* __restrict__ u, bf16* __restrict__ u2)
{
    const long idx = (long)blockIdx.x * 256 + threadIdx.x;
    const int c = (int)(idx & 255) * 4;
    const int m = (int)(idx >> 8);
    const int b = m / cL, l = m % cL;
    F4U acc; acc.f4 = *(const float4*)&cb[c];
    F4U w0, w1, w2, w3;
    w0.f4 = *(const float4*)&cw[c * 4];
    w1.f4 = *(const float4*)&cw[(c + 1) * 4];
    w2.f4 = *(const float4*)&cw[(c + 2) * 4];
    w3.f4 = *(const float4*)&cw[(c + 3) * 4];
#pragma unroll
    for (int k = 0; k < 4; k++){
        const int ls = l + k - 3;
        if (ls >= 0){
            F4U xv; xv.f4 = *(const float4*)&xz[(size_t)(b * cL + ls) * (2 * cDI) + c];
            acc.f[0] += xv.f[0] * w0.f[k];
            acc.f[1] += xv.f[1] * w1.f[k];
            acc.f[2] += xv.f[2] * w2.f[k];
            acc.f[3] += xv.f[3] * w3.f[k];
        }
    }
#pragma unroll
    for (int e = 0; e < 4; e++) acc.f[e] = acc.f[e] / (1.0f + __expf(-acc.f[e]));
    *(float4*)&u[(size_t)m * cDI + c] = acc.f4;
    const size_t r2 = (size_t)m * 2048;
    __nv_bfloat162 hh[2] = { hi2(acc.f[0], acc.f[1]), hi2(acc.f[2], acc.f[3]) };
    __nv_bfloat162 ll[2] = { lo2(acc.f[0], acc.f[1]), lo2(acc.f[2], acc.f[3]) };
    *(uint2*)&u2[r2 + c]        = *(uint2*)hh;
    *(uint2*)&u2[r2 + 1024 + c] = *(uint2*)ll;
}

// =====================================================================
// Selective scan: warp per (b, d); writes y2 [hi|lo]
// =====================================================================
__global__ __launch_bounds__(256) void mamba_scan(
    const float* __restrict__ delta, const float* __restrict__ u,
    const float* __restrict__ xdbc, const float* __restrict__ xz,
    const float* __restrict__ A_log, const float* __restrict__ Dssm,
    bf16* __restrict__ y2)
{
    const int warp = threadIdx.x >> 5, lane = threadIdx.x & 31;
    const int d = blockIdx.x * 8 + warp;
    const int b = blockIdx.y;
    const float a0 = -__expf(A_log[d * cS + 2 * lane]);
    const float a1 = -__expf(A_log[d * cS + 2 * lane + 1]);
    const float Dd = Dssm[d];
    float h0 = 0.f, h1 = 0.f;
    const size_t base = (size_t)b * cL;

    for (int t = 0; t < cL; t++){
        const size_t m = base + t;
        const float dt = __ldg(&delta[m * cDI + d]);
        const float uu = __ldg(&u[m * cDI + d]);
        const float2 Bv = *(const float2*)&xdbc[m * 160 + 32 + 2 * lane];
        const float2 Cv = *(const float2*)&xdbc[m * 160 + 96 + 2 * lane];
        const float du = dt * uu;
        h0 = h0 * __expf(dt * a0) + du * Bv.x;
        h1 = h1 * __expf(dt * a1) + du * Bv.y;
        float p = h0 * Cv.x + h1 * Cv.y;
        p += __shfl_xor_sync(0xffffffffu, p, 16);
        p += __shfl_xor_sync(0xffffffffu, p, 8);
        p += __shfl_xor_sync(0xffffffffu, p, 4);
        p += __shfl_xor_sync(0xffffffffu, p, 2);
        p += __shfl_xor_sync(0xffffffffu, p, 1);
        if (lane == 0){
            const float z = xz[m * (2 * cDI) + cDI + d];
            float yv = p + uu * Dd;
            yv *= z / (1.0f + __expf(-z));
            const size_t r2 = m * 2048;
            y2[r2 + d]        = hi_bf(yv);
            y2[r2 + 1024 + d] = lo_bf(yv);
        }
    }
}

// =====================================================================
// Fused residual + LN1 + LN2; writes h (fp32) and hn2 [hi|lo]
// =====================================================================
__device__ __forceinline__ float blockSum256(float v, float* red){
#pragma unroll
    for (int off = 16; off > 0; off >>= 1) v += __shfl_xor_sync(0xffffffffu, v, off);
    if ((threadIdx.x & 31) == 0) red[threadIdx.x >> 5] = v;
    __syncthreads();
    const float s = red[0]+red[1]+red[2]+red[3]+red[4]+red[5]+red[6]+red[7];
    __syncthreads();
    return s;
}

__global__ __launch_bounds__(256) void ln_fuse(
    const float* __restrict__ xf, const float* __restrict__ attn, const float* __restrict__ mamba,
    const float* __restrict__ g1, const float* __restrict__ b1,
    const float* __restrict__ g2, const float* __restrict__ b2,
    float* __restrict__ h, bf16* __restrict__ hn2)
{
    __shared__ float red[8];
    const size_t m = blockIdx.x;
    const int t = threadIdx.x * 2;
    const size_t r = m * cD;
    const float2 xv = *(const float2*)&xf[r + t];
    const float2 av = *(const float2*)&attn[r + t];
    const float2 mv = *(const float2*)&mamba[r + t];
    float v0 = xv.x + av.x + mv.x;
    float v1 = xv.y + av.y + mv.y;

    const float mean = blockSum256(v0 + v1, red) * (1.0f / cD);
    const float d0 = v0 - mean, d1 = v1 - mean;
    const float var = blockSum256(d0 * d0 + d1 * d1, red) * (1.0f / cD);
    const float inv = rsqrtf(var + 1e-5f);
    const float2 g1v = *(const float2*)&g1[t];
    const float2 b1v = *(const float2*)&b1[t];
    const float h0 = d0 * inv * g1v.x + b1v.x;
    const float h1 = d1 * inv * g1v.y + b1v.y;
    *(float2*)&h[r + t] = make_float2(h0, h1);

    const float mean2 = blockSum256(h0 + h1, red) * (1.0f / cD);
    const float e0 = h0 - mean2, e1 = h1 - mean2;
    const float var2 = blockSum256(e0 * e0 + e1 * e1, red) * (1.0f / cD);
    const float inv2 = rsqrtf(var2 + 1e-6f);
    const float2 g2v = *(const float2*)&g2[t];
    const float2 b2v = *(const float2*)&b2[t];
    const float n0 = e0 * inv2 * g2v.x + b2v.x;
    const float n1 = e1 * inv2 * g2v.y + b2v.y;
    const size_t r2 = m * 1024;
    *(__nv_bfloat162*)&hn2[r2 + t]       = hi2(n0, n1);
    *(__nv_bfloat162*)&hn2[r2 + 512 + t] = lo2(n0, n1);
}

// =====================================================================
// Launch
// =====================================================================
static inline int sgrid2(long rows, int K){
    return (int)((rows * (K >> 2) + 255) / 256);
}

extern "C" void kernel_launch(void* const* d_in, const int* in_sizes, int n_in,
                              void* d_out, int out_size)
{
    (void)in_sizes; (void)n_in; (void)out_size;
    const float* x      = (const float*)d_in[0];
    const unsigned char* mask = (const unsigned char*)d_in[1];
    const float* Wq = (const float*)d_in[2];  const float* bq = (const float*)d_in[3];
    const float* Wk = (const float*)d_in[4];  const float* bk = (const float*)d_in[5];
    const float* Wv = (const float*)d_in[6];  const float* bv = (const float*)d_in[7];
    const float* Wo = (const float*)d_in[8];  const float* bo = (const float*)d_in[9];
    const float* in_w   = (const float*)d_in[10];
    const float* conv_w = (const float*)d_in[11];
    const float* conv_b = (const float*)d_in[12];
    const float* xproj_w= (const float*)d_in[13];
    const float* dt_w   = (const float*)d_in[14];
    const float* dt_b   = (const float*)d_in[15];
    const float* A_log  = (const float*)d_in[16];
    const float* Dssm   = (const float*)d_in[17];
    const float* outp_w = (const float*)d_in[18];
    const float* ln1g   = (const float*)d_in[19];
    const float* ln1b   = (const float*)d_in[20];
    const float* fw1    = (const float*)d_in[21];
    const float* fb1    = (const float*)d_in[22];
    const float* fw2    = (const float*)d_in[23];
    const float* fb2    = (const float*)d_in[24];
    const float* ln2g   = (const float*)d_in[25];
    const float* ln2b   = (const float*)d_in[26];
    float* out = (float*)d_out;

    float *qkv,*attn,*xz,*u,*xdbc,*dlt,*mmb,*h;
    cudaGetSymbolAddress((void**)&qkv,  g_qkv);
    cudaGetSymbolAddress((void**)&attn, g_attn);
    cudaGetSymbolAddress((void**)&xz,   g_xz);
    cudaGetSymbolAddress((void**)&u,    g_u);
    cudaGetSymbolAddress((void**)&xdbc, g_xdbc);
    cudaGetSymbolAddress((void**)&dlt,  g_dlt);
    cudaGetSymbolAddress((void**)&mmb,  g_mmb);
    cudaGetSymbolAddress((void**)&h,    g_h);

    bf16 *px2,*pao2,*pu2,*pxdbc2,*py2,*phn2,*pff12;
    bf16 *pwqkv,*pwo,*pwin,*pwxp,*pwdt,*pwout,*pwf1,*pwf2;
    cudaGetSymbolAddress((void**)&px2,   gx2);
    cudaGetSymbolAddress((void**)&pao2,  gao2);
    cudaGetSymbolAddress((void**)&pu2,   gu2);
    cudaGetSymbolAddress((void**)&pxdbc2,gxdbc2);
    cudaGetSymbolAddress((void**)&py2,   gy2);
    cudaGetSymbolAddress((void**)&phn2,  ghn2);
    cudaGetSymbolAddress((void**)&pff12, gff12);
    cudaGetSymbolAddress((void**)&pwqkv, wqkv2);
    cudaGetSymbolAddress((void**)&pwo,   wo2);
    cudaGetSymbolAddress((void**)&pwin,  win2);
    cudaGetSymbolAddress((void**)&pwxp,  wxp2);
    cudaGetSymbolAddress((void**)&pwdt,  wdt2);
    cudaGetSymbolAddress((void**)&pwout, wout2);
    cudaGetSymbolAddress((void**)&pwf1,  wff12);
    cudaGetSymbolAddress((void**)&pwf2,  wff22);

    cudaFuncSetAttribute(flash_mma, cudaFuncAttributeMaxDynamicSharedMemorySize, FLASH_SMEM);
    cudaFuncSetAttribute(hmma_gemm<0,false>, cudaFuncAttributeMaxDynamicSharedMemorySize, GEMM_SMEM);
    cudaFuncSetAttribute(hmma_gemm<1,false>, cudaFuncAttributeMaxDynamicSharedMemorySize, GEMM_SMEM);
    cudaFuncSetAttribute(hmma_gemm<2,false>, cudaFuncAttributeMaxDynamicSharedMemorySize, GEMM_SMEM);
    cudaFuncSetAttribute(hmma_gemm<3,true>,  cudaFuncAttributeMaxDynamicSharedMemorySize, GEMM_SMEM);
    cudaFuncSetAttribute(hmma_gemm<4,false>, cudaFuncAttributeMaxDynamicSharedMemorySize, GEMM_SMEM);
    cudaFuncSetAttribute(hmma_gemm<5,false>, cudaFuncAttributeMaxDynamicSharedMemorySize, GEMM_SMEM);

    // ---- fused weight-split table ----
    WTab tab;
    long base = 0;
    auto add = [&](int i, const float* src, bf16* dst, int K, long rows){
        tab.e[i] = {src, dst, K, rows, base};
        base += rows * (K >> 2);
    };
    add(0, Wq,      pwqkv,               512,  512);
    add(1, Wk,      pwqkv + 512 * 1024,  512,  512);
    add(2, Wv,      pwqkv + 1024 * 1024, 512,  512);
    add(3, Wo,      pwo,                 512,  512);
    add(4, in_w,    pwin,                512,  2048);
    add(5, xproj_w, pwxp,                1024, 160);
    add(6, dt_w,    pwdt,                32,   1024);
    add(7, outp_w,  pwout,               1024, 512);
    add(8, fw1,     pwf1,                512,  2048);
    add(9, fw2,     pwf2,                2048, 512);
    const int wgrid = (int)((base + 255) / 256);

    cudaStream_t s0 = 0, sB = g_sh.sB;

    // slot 0, 1
    split2_wgt_all<<<wgrid, 256, 0, s0>>>(tab);
    split2<<<sgrid2(cM, 512), 256, 0, s0>>>(x, 512, 512, px2, cM);

    cudaEventRecord(g_sh.evRoot, s0);
    cudaStreamWaitEvent(sB, g_sh.evRoot, 0);

    // slot 2: fused QKV GEMM (tri-bias)
    hmma_gemm<5,false><<<dim3(12, 72), 512, GEMM_SMEM, s0>>>(px2, pwqkv, 512, bq, bk, bv, nullptr, qkv, nullptr, 1536);
    // slot 3: flash v2 (ncu target)
    flash_mma<<<dim3(cL / 128, cB * 8), 256, FLASH_SMEM, s0>>>(qkv, mask, pao2);
    hmma_gemm<1,false><<<dim3(4, 72), 512, GEMM_SMEM, s0>>>(pao2, pwo, 512, bo, nullptr, nullptr, nullptr, attn, nullptr, 512);

    // mamba branch on sB
    hmma_gemm<0,false><<<dim3(16, 72), 512, GEMM_SMEM, sB>>>(px2, pwin, 512, nullptr, nullptr, nullptr, nullptr, xz, nullptr, 2048);
    conv_silu<<<(cM * 256) / 256, 256, 0, sB>>>(xz, conv_w, conv_b, u, pu2);
    hmma_gemm<0,false><<<dim3(2, 72), 512, GEMM_SMEM, sB>>>(pu2, pwxp, 1024, nullptr, nullptr, nullptr, nullptr, xdbc, nullptr, 160);
    split2<<<sgrid2(cM, 32), 256, 0, sB>>>(xdbc, 160, 32, pxdbc2, cM);
    hmma_gemm<2,false><<<dim3(8, 72), 512, GEMM_SMEM, sB>>>(pxdbc2, pwdt, 32, dt_b, nullptr, nullptr, nullptr, dlt, nullptr, 1024);
    mamba_scan<<<dim3(cDI / 8, cB), 256, 0, sB>>>(dlt, u, xdbc, xz, A_log, Dssm, py2);
    hmma_gemm<0,false><<<dim3(4, 72), 512, GEMM_SMEM, sB>>>(py2, pwout, 1024, nullptr, nullptr, nullptr, nullptr, mmb, nullptr, 512);
    cudaEventRecord(g_sh.evB, sB);

    cudaStreamWaitEvent(s0, g_sh.evB, 0);
    ln_fuse<<<cM, 256, 0, s0>>>(x, attn, mmb, ln1g, ln1b, ln2g, ln2b, h, phn2);
    hmma_gemm<3,true><<<dim3(16, 72), 512, GEMM_SMEM, s0>>>(phn2, pwf1, 512, fb1, nullptr, nullptr, nullptr, nullptr, pff12, 2048);
    hmma_gemm<4,false><<<dim3(4, 72), 512, GEMM_SMEM, s0>>>(pff12, pwf2, 2048, fb2, nullptr, nullptr, h, out, nullptr, 512);
}

// round 11
// speedup vs baseline: 2.2450x; 1.4286x over previous
#include <cuda_runtime.h>
#include <cuda_bf16.h>
#include <cstdint>
#include <math.h>

typedef __nv_bfloat16 bf16;

// ---------------- dims ----------------
static const int cB  = 8;
static const int cL  = 1152;      // T*W
static const int cD  = 512;
static const int cDI = 1024;
static const int cS  = 64;
static const int cDFF= 2048;
static const int cM  = 9216;      // B*L

// ---------------- fp32 workspaces ----------------
__device__ float g_qkv [cM*1536];
__device__ float g_attn[cM*cD];
__device__ float g_xz  [cM*2*cDI];
__device__ float g_u   [cM*cDI];
__device__ float g_xdbc[cM*160];
__device__ float g_dlt [cM*cDI];
__device__ float g_mmb [cM*cD];
__device__ float g_h   [cM*cD];

// ---------------- bf16 split-2 storage [hi|lo] ----------------
__device__ bf16 gx2   [cM*1024];
__device__ bf16 gao2  [cM*1024];
__device__ bf16 gu2   [cM*2048];
__device__ bf16 gxdbc2[cM*64];
__device__ bf16 gy2   [cM*2048];
__device__ bf16 ghn2  [cM*1024];
__device__ bf16 gff12 [cM*4096];

__device__ bf16 wqkv2[1536*1024];
__device__ bf16 wo2  [512*1024];
__device__ bf16 win2 [2048*1024];
__device__ bf16 wxp2 [160*2048];
__device__ bf16 wdt2 [1024*64];
__device__ bf16 wout2[512*2048];
__device__ bf16 wff12[2048*1024];
__device__ bf16 wff22[512*4096];

// ---------------- streams ----------------
struct StreamHolder {
    cudaStream_t sB;
    cudaEvent_t evRoot, evB;
    StreamHolder(){
        cudaStreamCreateWithFlags(&sB, cudaStreamNonBlocking);
        cudaEventCreateWithFlags(&evRoot, cudaEventDisableTiming);
        cudaEventCreateWithFlags(&evB,   cudaEventDisableTiming);
    }
};
static StreamHolder g_sh;

// ---------------- helpers ----------------
union F4U { float4 f4; unsigned long long l[2]; float f[4]; };
union BU  { __nv_bfloat162 b; uint32_t u; };

__device__ __forceinline__ float softplus_f(float v){
    return fmaxf(v, 0.0f) + log1pf(__expf(-fabsf(v)));
}
__device__ __forceinline__ float gelu_f(float v){
    return 0.5f * v * (1.0f + erff(v * 0.70710678118654752f));
}
__device__ __forceinline__ bf16 hi_bf(float a){ return __float2bfloat16(a); }
__device__ __forceinline__ bf16 lo_bf(float a){
    bf16 h = __float2bfloat16(a);
    return __float2bfloat16(a - __bfloat162float(h));
}
__device__ __forceinline__ __nv_bfloat162 hi2(float a, float b){
    return __floats2bfloat162_rn(a, b);
}
__device__ __forceinline__ __nv_bfloat162 lo2(float a, float b){
    __nv_bfloat162 h = __floats2bfloat162_rn(a, b);
    return __floats2bfloat162_rn(a - __bfloat162float(h.x), b - __bfloat162float(h.y));
}
__device__ __forceinline__ uint32_t hi2u(float a, float b){ BU t; t.b = hi2(a, b); return t.u; }
__device__ __forceinline__ uint32_t lo2u(float a, float b){ BU t; t.b = lo2(a, b); return t.u; }

__device__ __forceinline__ uint32_t smem_u32(const void* p){
    uint32_t a;
    asm("{ .reg .u64 t; cvta.to.shared.u64 t, %1; cvt.u32.u64 %0, t; }" : "=r"(a) : "l"(p));
    return a;
}
__device__ __forceinline__ void cp16(uint32_t dst, const void* src){
    asm volatile("cp.async.cg.shared.global [%0], [%1], 16;" :: "r"(dst), "l"(src));
}
__device__ __forceinline__ void ldsm4(uint32_t &r0, uint32_t &r1, uint32_t &r2, uint32_t &r3, uint32_t addr){
    asm volatile("ldmatrix.sync.aligned.m8n8.x4.shared.b16 {%0,%1,%2,%3}, [%4];"
        : "=r"(r0), "=r"(r1), "=r"(r2), "=r"(r3) : "r"(addr));
}
__device__ __forceinline__ void ldsm4t(uint32_t &r0, uint32_t &r1, uint32_t &r2, uint32_t &r3, uint32_t addr){
    asm volatile("ldmatrix.sync.aligned.m8n8.x4.trans.shared.b16 {%0,%1,%2,%3}, [%4];"
        : "=r"(r0), "=r"(r1), "=r"(r2), "=r"(r3) : "r"(addr));
}
__device__ __forceinline__ void mma16816(float* c, uint32_t a0, uint32_t a1, uint32_t a2, uint32_t a3,
                                         uint32_t b0, uint32_t b1){
    asm volatile("mma.sync.aligned.m16n8k16.row.col.f32.bf16.bf16.f32 "
        "{%0,%1,%2,%3}, {%4,%5,%6,%7}, {%8,%9}, {%0,%1,%2,%3};"
        : "+f"(c[0]), "+f"(c[1]), "+f"(c[2]), "+f"(c[3])
        : "r"(a0), "r"(a1), "r"(a2), "r"(a3), "r"(b0), "r"(b1));
}

// =====================================================================
// split2: fp32 [rows x K] -> bf16 [rows x 2K] = [hi | lo]
// =====================================================================
__global__ __launch_bounds__(256) void split2(
    const float* __restrict__ in, int lda, int K,
    bf16* __restrict__ out, long rows)
{
    const int chunks = K >> 2;
    const long idx = (long)blockIdx.x * 256 + threadIdx.x;
    if (idx >= rows * chunks) return;
    const int row = (int)(idx / chunks);
    const int kc = (int)(idx - (long)row * chunks);
    const int blk = (kc * 8) / K;
    const int within = kc * 8 - blk * K;
    const float* src = in + (size_t)row * lda + within;
    F4U s0, s1; s0.f4 = *(const float4*)src; s1.f4 = *(const float4*)(src + 4);
    __nv_bfloat162 o[4];
    if (blk == 1){
        o[0] = lo2(s0.f[0], s0.f[1]); o[1] = lo2(s0.f[2], s0.f[3]);
        o[2] = lo2(s1.f[0], s1.f[1]); o[3] = lo2(s1.f[2], s1.f[3]);
    } else {
        o[0] = hi2(s0.f[0], s0.f[1]); o[1] = hi2(s0.f[2], s0.f[3]);
        o[2] = hi2(s1.f[0], s1.f[1]); o[3] = hi2(s1.f[2], s1.f[3]);
    }
    *(uint4*)&out[(size_t)row * (2 * K) + kc * 8] = *(uint4*)o;
}

struct WSpec { const float* src; bf16* dst; int K; long rows; long base; };
struct WTab  { WSpec e[10]; };

__global__ __launch_bounds__(256) void split2_wgt_all(WTab tab)
{
    const long idx = (long)blockIdx.x * 256 + threadIdx.x;
    int i = 0;
#pragma unroll
    for (int j = 1; j < 10; j++) if (idx >= tab.e[j].base) i = j;
    const WSpec w = tab.e[i];
    const long local = idx - w.base;
    const int chunks = w.K >> 2;
    if (local >= w.rows * chunks) return;
    const int row = (int)(local / chunks);
    const int kc = (int)(local - (long)row * chunks);
    const int blk = (kc * 8) / w.K;
    const int within = kc * 8 - blk * w.K;
    const float* src = w.src + (size_t)row * w.K + within;
    F4U s0, s1; s0.f4 = *(const float4*)src; s1.f4 = *(const float4*)(src + 4);
    __nv_bfloat162 o[4];
    if (blk == 1){
        o[0] = lo2(s0.f[0], s0.f[1]); o[1] = lo2(s0.f[2], s0.f[3]);
        o[2] = lo2(s1.f[0], s1.f[1]); o[3] = lo2(s1.f[2], s1.f[3]);
    } else {
        o[0] = hi2(s0.f[0], s0.f[1]); o[1] = hi2(s0.f[2], s0.f[3]);
        o[2] = hi2(s1.f[0], s1.f[1]); o[3] = hi2(s1.f[2], s1.f[3]);
    }
    *(uint4*)&w.dst[(size_t)row * (2 * w.K) + kc * 8] = *(uint4*)o;
}

// =====================================================================
// HMMA GEMM: logical K3=3*Ka over [hi|lo|hi]A x [hi|hi|lo]W, stored 2K.
// 512 threads, 16 warps (4x4 of 32x32), CTA 128x128, BK templated.
// =====================================================================
template<int EPI, bool OUT3, int BK>
__global__ __launch_bounds__(512, 2) void hmma_gemm(
    const bf16* __restrict__ A2, const bf16* __restrict__ W2, int Ka,
    const float* __restrict__ bias, const float* __restrict__ bias_b,
    const float* __restrict__ bias_c, const float* __restrict__ res,
    float* __restrict__ C, bf16* __restrict__ C3, int N)
{
    const int PITCH = 2 * BK + 16;
    const int TB = 256 * PITCH;
    extern __shared__ char smem[];
    const uint32_t sb = smem_u32(smem);
    const int tid = threadIdx.x;
    const int wid = tid >> 5, lane = tid & 31;
    const int bm = blockIdx.y * 128;
    const int bn = blockIdx.x * 128;
    const int wm = wid & 3, wn = wid >> 2;
    const int gpitch = 2 * Ka;

    float acc[2][4][4];
#pragma unroll
    for (int i = 0; i < 2; i++)
#pragma unroll
        for (int j = 0; j < 4; j++)
#pragma unroll
            for (int e = 0; e < 4; e++) acc[i][j][e] = 0.f;

    const int NC = (3 * Ka) / BK;
    const int CPR = BK / 8;               // 16B chunks per row
    const int NCHUNK = 256 * CPR;         // total per tile
    const int ACH = 128 * CPR;

    auto load_tile = [&](int ci, uint32_t sbase){
        const int lcbase = ci * BK;
        int acol = lcbase; if (acol >= 2 * Ka) acol -= 2 * Ka;
        int wcol = lcbase; if (wcol >= Ka) wcol -= Ka;
#pragma unroll
        for (int cc = 0; cc < NCHUNK / 512; cc++){
            const int c = tid + cc * 512;
            if (c < ACH){
                const int row = c / CPR, ch = c % CPR;
                cp16(sbase + row * PITCH + ch * 16,
                     &A2[(size_t)(bm + row) * gpitch + acol + ch * 8]);
            } else {
                const int c2 = c - ACH;
                const int row = c2 / CPR, ch = c2 % CPR;
                int br = bn + row; if (br >= N) br = N - 1;
                cp16(sbase + 128 * PITCH + row * PITCH + ch * 16,
                     &W2[(size_t)br * gpitch + wcol + ch * 8]);
            }
        }
        asm volatile("cp.async.commit_group;" ::: "memory");
    };

    load_tile(0, sb);
    if (NC > 1) load_tile(1, sb + TB);

    const uint32_t aOff = (uint32_t)((wm * 32 + (lane & 15)) * PITCH + (lane >> 4) * 16);
    const uint32_t bOff = (uint32_t)(128 * PITCH +
                          (wn * 32 + (lane & 7) + ((lane & 16) ? 8 : 0)) * PITCH +
                          ((lane >> 3) & 1) * 16);

    for (int ci = 0; ci < NC; ci++){
        if (ci + 1 < NC) asm volatile("cp.async.wait_group 1;" ::: "memory");
        else             asm volatile("cp.async.wait_group 0;" ::: "memory");
        __syncthreads();
        if (ci + 2 < NC){
            const int nb = (ci + 2) % 3;
            load_tile(ci + 2, sb + (uint32_t)nb * TB);
        }
        const uint32_t cur = sb + (uint32_t)(ci % 3) * TB;

#pragma unroll
        for (int s = 0; s < BK / 16; s++){
            uint32_t a[2][4];
#pragma unroll
            for (int i = 0; i < 2; i++)
                ldsm4(a[i][0], a[i][1], a[i][2], a[i][3], cur + aOff + i * (16 * PITCH) + s * 32);
            uint32_t b0, b1, b2, b3, b4, b5, b6, b7;
            ldsm4(b0, b1, b2, b3, cur + bOff + s * 32);
            ldsm4(b4, b5, b6, b7, cur + bOff + 16 * PITCH + s * 32);
#pragma unroll
            for (int i = 0; i < 2; i++){
                mma16816(acc[i][0], a[i][0], a[i][1], a[i][2], a[i][3], b0, b1);
                mma16816(acc[i][1], a[i][0], a[i][1], a[i][2], a[i][3], b2, b3);
                mma16816(acc[i][2], a[i][0], a[i][1], a[i][2], a[i][3], b4, b5);
                mma16816(acc[i][3], a[i][0], a[i][1], a[i][2], a[i][3], b6, b7);
            }
        }
    }

    const int t4 = lane >> 2, tp = (lane & 3) * 2;
#pragma unroll
    for (int i = 0; i < 2; i++){
#pragma unroll
        for (int j = 0; j < 4; j++){
            const int col = bn + wn * 32 + j * 8 + tp;
            if (col >= N) continue;
            const int row0 = bm + wm * 32 + i * 16 + t4;
            float v0 = acc[i][j][0], v1 = acc[i][j][1];
            float v2 = acc[i][j][2], v3 = acc[i][j][3];
            if (EPI >= 1 && EPI <= 4){
                const float bb0 = bias[col], bb1 = bias[col + 1];
                v0 += bb0; v1 += bb1; v2 += bb0; v3 += bb1;
            }
            if (EPI == 5){
                const float* bp = (col < 512) ? bias : (col < 1024) ? (bias_b - 512) : (bias_c - 1024);
                const float bb0 = bp[col], bb1 = bp[col + 1];
                v0 += bb0; v1 += bb1; v2 += bb0; v3 += bb1;
            }
            if (EPI == 2){ v0 = softplus_f(v0); v1 = softplus_f(v1); v2 = softplus_f(v2); v3 = softplus_f(v3); }
            if (EPI == 3){ v0 = gelu_f(v0); v1 = gelu_f(v1); v2 = gelu_f(v2); v3 = gelu_f(v3); }
            if (EPI == 4){
                v0 += res[(size_t)row0 * N + col];
                v1 += res[(size_t)row0 * N + col + 1];
                v2 += res[(size_t)(row0 + 8) * N + col];
                v3 += res[(size_t)(row0 + 8) * N + col + 1];
            }
            if (OUT3){
                const size_t r0 = (size_t)row0 * (2 * N), r1 = (size_t)(row0 + 8) * (2 * N);
                *(__nv_bfloat162*)&C3[r0 + col]     = hi2(v0, v1);
                *(__nv_bfloat162*)&C3[r0 + N + col] = lo2(v0, v1);
                *(__nv_bfloat162*)&C3[r1 + col]     = hi2(v2, v3);
                *(__nv_bfloat162*)&C3[r1 + N + col] = lo2(v2, v3);
            } else {
                *(float2*)&C[(size_t)row0 * N + col]       = make_float2(v0, v1);
                *(float2*)&C[(size_t)(row0 + 8) * N + col] = make_float2(v2, v3);
            }
        }
    }
}
#define GEMM_SMEM32 (3 * 256 * 80)
#define GEMM_SMEM64 (3 * 256 * 144)

// =====================================================================
// Flash attention v2 (unchanged from R10)
// =====================================================================
#define FQ 0
#define FK 34816
#define FV 52224
#define FMSK 70656
#define FLASH_SMEM 70912

__global__ __launch_bounds__(256, 2) void flash_mma(
    const float* __restrict__ QKV, const unsigned char* __restrict__ mask,
    bf16* __restrict__ AO2)
{
    extern __shared__ char sm[];
    const uint32_t sb = smem_u32(sm);
    float* mskf = (float*)(sm + FMSK);
    const int tid = threadIdx.x;
    const int w = tid >> 5, lane = tid & 31;
    const int t4 = lane >> 2, qq = lane & 3;
    const int bh = blockIdx.y, b = bh >> 3, h = bh & 7;
    const int q0 = blockIdx.x * 128;
    const size_t basebl = (size_t)b * cL;

    for (int idx = tid; idx < 2048; idx += 256){
        const int row = idx >> 4, c4 = idx & 15;
        F4U qv; qv.f4 = *(const float4*)&QKV[(basebl + q0 + row) * 1536 + h * 64 + c4 * 4];
        char* p = sm + FQ + row * 272 + c4 * 8;
        *(__nv_bfloat162*)(p)       = hi2(qv.f[0], qv.f[1]);
        *(__nv_bfloat162*)(p + 4)   = hi2(qv.f[2], qv.f[3]);
        *(__nv_bfloat162*)(p + 128) = lo2(qv.f[0], qv.f[1]);
        *(__nv_bfloat162*)(p + 132) = lo2(qv.f[2], qv.f[3]);
    }

    float m0 = -1e30f, m1 = -1e30f, l0 = 0.f, l1 = 0.f;
    float o[8][4];
#pragma unroll
    for (int nt = 0; nt < 8; nt++)
#pragma unroll
        for (int e = 0; e < 4; e++) o[nt][e] = 0.f;

    for (int jt = 0; jt < cL / 64; jt++){
        __syncthreads();
        for (int idx = tid; idx < 1024; idx += 256){
            const int row = idx >> 4, c4 = idx & 15;
            const size_t gr = (basebl + jt * 64 + row) * 1536 + h * 64 + c4 * 4;
            F4U kv; kv.f4 = *(const float4*)&QKV[gr + 512];
            F4U vv; vv.f4 = *(const float4*)&QKV[gr + 1024];
            char* pk = sm + FK + row * 272 + c4 * 8;
            *(__nv_bfloat162*)(pk)       = hi2(kv.f[0], kv.f[1]);
            *(__nv_bfloat162*)(pk + 4)   = hi2(kv.f[2], kv.f[3]);
            *(__nv_bfloat162*)(pk + 128) = lo2(kv.f[0], kv.f[1]);
            *(__nv_bfloat162*)(pk + 132) = lo2(kv.f[2], kv.f[3]);
            char* ph = sm + FV + row * 144 + c4 * 8;
            *(__nv_bfloat162*)(ph)     = hi2(vv.f[0], vv.f[1]);
            *(__nv_bfloat162*)(ph + 4) = hi2(vv.f[2], vv.f[3]);
            char* pl = sm + FV + (64 + row) * 144 + c4 * 8;
            *(__nv_bfloat162*)(pl)     = lo2(vv.f[0], vv.f[1]);
            *(__nv_bfloat162*)(pl + 4) = lo2(vv.f[2], vv.f[3]);
        }
        if (tid < 64) mskf[tid] = mask[b * cL + jt * 64 + tid] ? -1e30f : 0.0f;
        __syncthreads();

        float sacc[8][4];
#pragma unroll
        for (int nt = 0; nt < 8; nt++)
#pragma unroll
            for (int e = 0; e < 4; e++) sacc[nt][e] = 0.f;

#pragma unroll
        for (int s = 0; s < 12; s++){
            const int ab = (s < 4) ? s * 32 : (s < 8) ? 128 + (s - 4) * 32 : (s - 8) * 32;
            const int bb = (s < 8) ? (s & 3) * 32 : 128 + (s - 8) * 32;
            uint32_t a0, a1, a2, a3;
            ldsm4(a0, a1, a2, a3, sb + FQ + (w * 16 + (lane & 15)) * 272 + ab + (lane >> 4) * 16);
#pragma unroll
            for (int kc = 0; kc < 4; kc++){
                uint32_t b0, b1, b2, b3;
                ldsm4(b0, b1, b2, b3,
                      sb + FK + (kc * 16 + (lane & 7) + ((lane & 16) ? 8 : 0)) * 272 + bb + ((lane >> 3) & 1) * 16);
                mma16816(sacc[2 * kc],     a0, a1, a2, a3, b0, b1);
                mma16816(sacc[2 * kc + 1], a0, a1, a2, a3, b2, b3);
            }
        }

        float mx0 = -1e30f, mx1 = -1e30f;
#pragma unroll
        for (int nt = 0; nt < 8; nt++){
            const float2 mk = *(const float2*)&mskf[nt * 8 + qq * 2];
            sacc[nt][0] = sacc[nt][0] * 0.125f + mk.x;
            sacc[nt][1] = sacc[nt][1] * 0.125f + mk.y;
            sacc[nt][2] = sacc[nt][2] * 0.125f + mk.x;
            sacc[nt][3] = sacc[nt][3] * 0.125f + mk.y;
            mx0 = fmaxf(mx0, fmaxf(sacc[nt][0], sacc[nt][1]));
            mx1 = fmaxf(mx1, fmaxf(sacc[nt][2], sacc[nt][3]));
        }
        mx0 = fmaxf(mx0, __shfl_xor_sync(0xffffffffu, mx0, 1));
        mx0 = fmaxf(mx0, __shfl_xor_sync(0xffffffffu, mx0, 2));
        mx1 = fmaxf(mx1, __shfl_xor_sync(0xffffffffu, mx1, 1));
        mx1 = fmaxf(mx1, __shfl_xor_sync(0xffffffffu, mx1, 2));
        const float mn0 = fmaxf(m0, mx0), mn1 = fmaxf(m1, mx1);
        const float fac0 = __expf(m0 - mn0), fac1 = __expf(m1 - mn1);
        m0 = mn0; m1 = mn1;
        float sum0 = 0.f, sum1 = 0.f;
#pragma unroll
        for (int nt = 0; nt < 8; nt++){
            sacc[nt][0] = __expf(sacc[nt][0] - mn0);
            sacc[nt][1] = __expf(sacc[nt][1] - mn0);
            sacc[nt][2] = __expf(sacc[nt][2] - mn1);
            sacc[nt][3] = __expf(sacc[nt][3] - mn1);
            sum0 += sacc[nt][0] + sacc[nt][1];
            sum1 += sacc[nt][2] + sacc[nt][3];
        }
        sum0 += __shfl_xor_sync(0xffffffffu, sum0, 1);
        sum0 += __shfl_xor_sync(0xffffffffu, sum0, 2);
        sum1 += __shfl_xor_sync(0xffffffffu, sum1, 1);
        sum1 += __shfl_xor_sync(0xffffffffu, sum1, 2);
        l0 = l0 * fac0 + sum0;
        l1 = l1 * fac1 + sum1;
#pragma unroll
        for (int nt = 0; nt < 8; nt++){
            o[nt][0] *= fac0; o[nt][1] *= fac0;
            o[nt][2] *= fac1; o[nt][3] *= fac1;
        }

        uint32_t Ph[4][4], Pl[4][4];
#pragma unroll
        for (int kk = 0; kk < 4; kk++){
            Ph[kk][0] = hi2u(sacc[2*kk][0],   sacc[2*kk][1]);
            Ph[kk][1] = hi2u(sacc[2*kk][2],   sacc[2*kk][3]);
            Ph[kk][2] = hi2u(sacc[2*kk+1][0], sacc[2*kk+1][1]);
            Ph[kk][3] = hi2u(sacc[2*kk+1][2], sacc[2*kk+1][3]);
            Pl[kk][0] = lo2u(sacc[2*kk][0],   sacc[2*kk][1]);
            Pl[kk][1] = lo2u(sacc[2*kk][2],   sacc[2*kk][3]);
            Pl[kk][2] = lo2u(sacc[2*kk+1][0], sacc[2*kk+1][1]);
            Pl[kk][3] = lo2u(sacc[2*kk+1][2], sacc[2*kk+1][3]);
        }

#pragma unroll
        for (int s = 0; s < 12; s++){
            const uint32_t* af = (s < 4) ? Ph[s] : (s < 8) ? Pl[s - 4] : Ph[s - 8];
            const int vr = (s < 8) ? (s & 3) * 16 : 64 + (s - 8) * 16;
#pragma unroll
            for (int nb = 0; nb < 4; nb++){
                uint32_t v0, v1, v2, v3;
                ldsm4t(v0, v1, v2, v3,
                       sb + FV + (vr + (lane & 15)) * 144 + (nb * 16 + ((lane & 16) ? 8 : 0)) * 2);
                mma16816(o[2 * nb],     af[0], af[1], af[2], af[3], v0, v1);
                mma16816(o[2 * nb + 1], af[0], af[1], af[2], af[3], v2, v3);
            }
        }
    }

    const float i0 = 1.0f / l0, i1 = 1.0f / l1;
    const size_t gA = (basebl + q0 + w * 16 + t4) * 1024;
    const size_t gB = gA + 8 * 1024;
#pragma unroll
    for (int nt = 0; nt < 8; nt++){
        const float a0 = o[nt][0] * i0, a1 = o[nt][1] * i0;
        const float a2 = o[nt][2] * i1, a3 = o[nt][3] * i1;
        const int col = h * 64 + nt * 8 + qq * 2;
        *(__nv_bfloat162*)&AO2[gA + col]       = hi2(a0, a1);
        *(__nv_bfloat162*)&AO2[gA + 512 + col] = lo2(a0, a1);
        *(__nv_bfloat162*)&AO2[gB + col]       = hi2(a2, a3);
        *(__nv_bfloat162*)&AO2[gB + 512 + col] = lo2(a2, a3);
    }
}

// =====================================================================
// Depthwise causal conv (KC=4) + SiLU; float4; writes u + u2 [hi|lo]
// =====================================================================
__global__ __launch_bounds__(256) void conv_silu(
    const float* __restrict__ xz, const float* __restrict__ cw,
    const float* __restrict__ cb, float* __restrict__ u, bf16* __restrict__ u2)
{
    const long idx = (long)blockIdx.x * 256 + threadIdx.x;
    const int c = (int)(idx & 255) * 4;
    const int m = (int)(idx >> 8);
    const int b = m / cL, l = m % cL;
    F4U acc; acc.f4 = *(const float4*)&cb[c];
    F4U w0, w1, w2, w3;
    w0.f4 = *(const float4*)&cw[c * 4];
    w1.f4 = *(const float4*)&cw[(c + 1) * 4];
    w2.f4 = *(const float4*)&cw[(c + 2) * 4];
    w3.f4 = *(const float4*)&cw[(c + 3) * 4];
#pragma unroll
    for (int k = 0; k < 4; k++){
        const int ls = l + k - 3;
        if (ls >= 0){
            F4U xv; xv.f4 = *(const float4*)&xz[(size_t)(b * cL + ls) * (2 * cDI) + c];
            acc.f[0] += xv.f[0] * w0.f[k];
            acc.f[1] += xv.f[1] * w1.f[k];
            acc.f[2] += xv.f[2] * w2.f[k];
            acc.f[3] += xv.f[3] * w3.f[k];
        }
    }
#pragma unroll
    for (int e = 0; e < 4; e++) acc.f[e] = acc.f[e] / (1.0f + __expf(-acc.f[e]));
    *(float4*)&u[(size_t)m * cDI + c] = acc.f4;
    const size_t r2 = (size_t)m * 2048;
    __nv_bfloat162 hh[2] = { hi2(acc.f[0], acc.f[1]), hi2(acc.f[2], acc.f[3]) };
    __nv_bfloat162 ll[2] = { lo2(acc.f[0], acc.f[1]), lo2(acc.f[2], acc.f[3]) };
    *(uint2*)&u2[r2 + c]        = *(uint2*)hh;
    *(uint2*)&u2[r2 + 1024 + c] = *(uint2*)ll;
}

// =====================================================================
// Selective scan: 2 d per warp (16 lanes x 4 states each); writes y2
// =====================================================================
__global__ __launch_bounds__(256) void mamba_scan(
    const float* __restrict__ delta, const float* __restrict__ u,
    const float* __restrict__ xdbc, const float* __restrict__ xz,
    const float* __restrict__ A_log, const float* __restrict__ Dssm,
    bf16* __restrict__ y2)
{
    const int warp = threadIdx.x >> 5, lane = threadIdx.x & 31;
    const int half = lane >> 4, sl = lane & 15;
    const int d = blockIdx.x * 16 + warp * 2 + half;
    const int b = blockIdx.y;
    float a[4], hh[4];
#pragma unroll
    for (int k = 0; k < 4; k++){
        a[k] = -__expf(A_log[d * cS + sl * 4 + k]);
        hh[k] = 0.f;
    }
    const float Dd = Dssm[d];
    const size_t base = (size_t)b * cL;

    for (int t = 0; t < cL; t++){
        const size_t m = base + t;
        const float dt = __ldg(&delta[m * cDI + d]);
        const float uu = __ldg(&u[m * cDI + d]);
        F4U Bv, Cv;
        Bv.f4 = *(const float4*)&xdbc[m * 160 + 32 + sl * 4];
        Cv.f4 = *(const float4*)&xdbc[m * 160 + 96 + sl * 4];
        const float du = dt * uu;
        float p = 0.f;
#pragma unroll
        for (int k = 0; k < 4; k++){
            hh[k] = hh[k] * __expf(dt * a[k]) + du * Bv.f[k];
            p += hh[k] * Cv.f[k];
        }
        p += __shfl_xor_sync(0xffffffffu, p, 8);
        p += __shfl_xor_sync(0xffffffffu, p, 4);
        p += __shfl_xor_sync(0xffffffffu, p, 2);
        p += __shfl_xor_sync(0xffffffffu, p, 1);
        if (sl == 0){
            const float z = xz[m * (2 * cDI) + cDI + d];
            float yv = p + uu * Dd;
            yv *= z / (1.0f + __expf(-z));
            const size_t r2 = m * 2048;
            y2[r2 + d]        = hi_bf(yv);
            y2[r2 + 1024 + d] = lo_bf(yv);
        }
    }
}

// =====================================================================
// Fused residual + LN1 + LN2; writes h (fp32) and hn2 [hi|lo]
// =====================================================================
__device__ __forceinline__ float blockSum256(float v, float* red){
#pragma unroll
    for (int off = 16; off > 0; off >>= 1) v += __shfl_xor_sync(0xffffffffu, v, off);
    if ((threadIdx.x & 31) == 0) red[threadIdx.x >> 5] = v;
    __syncthreads();
    const float s = red[0]+red[1]+red[2]+red[3]+red[4]+red[5]+red[6]+red[7];
    __syncthreads();
    return s;
}

__global__ __launch_bounds__(256) void ln_fuse(
    const float* __restrict__ xf, const float* __restrict__ attn, const float* __restrict__ mamba,
    const float* __restrict__ g1, const float* __restrict__ b1,
    const float* __restrict__ g2, const float* __restrict__ b2,
    float* __restrict__ h, bf16* __restrict__ hn2)
{
    __shared__ float red[8];
    const size_t m = blockIdx.x;
    const int t = threadIdx.x * 2;
    const size_t r = m * cD;
    const float2 xv = *(const float2*)&xf[r + t];
    const float2 av = *(const float2*)&attn[r + t];
    const float2 mv = *(const float2*)&mamba[r + t];
    float v0 = xv.x + av.x + mv.x;
    float v1 = xv.y + av.y + mv.y;

    const float mean = blockSum256(v0 + v1, red) * (1.0f / cD);
    const float d0 = v0 - mean, d1 = v1 - mean;
    const float var = blockSum256(d0 * d0 + d1 * d1, red) * (1.0f / cD);
    const float inv = rsqrtf(var + 1e-5f);
    const float2 g1v = *(const float2*)&g1[t];
    const float2 b1v = *(const float2*)&b1[t];
    const float h0 = d0 * inv * g1v.x + b1v.x;
    const float h1 = d1 * inv * g1v.y + b1v.y;
    *(float2*)&h[r + t] = make_float2(h0, h1);

    const float mean2 = blockSum256(h0 + h1, red) * (1.0f / cD);
    const float e0 = h0 - mean2, e1 = h1 - mean2;
    const float var2 = blockSum256(e0 * e0 + e1 * e1, red) * (1.0f / cD);
    const float inv2 = rsqrtf(var2 + 1e-6f);
    const float2 g2v = *(const float2*)&g2[t];
    const float2 b2v = *(const float2*)&b2[t];
    const float n0 = e0 * inv2 * g2v.x + b2v.x;
    const float n1 = e1 * inv2 * g2v.y + b2v.y;
    const size_t r2 = m * 1024;
    *(__nv_bfloat162*)&hn2[r2 + t]       = hi2(n0, n1);
    *(__nv_bfloat162*)&hn2[r2 + 512 + t] = lo2(n0, n1);
}

// =====================================================================
// Launch
// =====================================================================
static inline int sgrid2(long rows, int K){
    return (int)((rows * (K >> 2) + 255) / 256);
}

extern "C" void kernel_launch(void* const* d_in, const int* in_sizes, int n_in,
                              void* d_out, int out_size)
{
    (void)in_sizes; (void)n_in; (void)out_size;
    const float* x      = (const float*)d_in[0];
    const unsigned char* mask = (const unsigned char*)d_in[1];
    const float* Wq = (const float*)d_in[2];  const float* bq = (const float*)d_in[3];
    const float* Wk = (const float*)d_in[4];  const float* bk = (const float*)d_in[5];
    const float* Wv = (const float*)d_in[6];  const float* bv = (const float*)d_in[7];
    const float* Wo = (const float*)d_in[8];  const float* bo = (const float*)d_in[9];
    const float* in_w   = (const float*)d_in[10];
    const float* conv_w = (const float*)d_in[11];
    const float* conv_b = (const float*)d_in[12];
    const float* xproj_w= (const float*)d_in[13];
    const float* dt_w   = (const float*)d_in[14];
    const float* dt_b   = (const float*)d_in[15];
    const float* A_log  = (const float*)d_in[16];
    const float* Dssm   = (const float*)d_in[17];
    const float* outp_w = (const float*)d_in[18];
    const float* ln1g   = (const float*)d_in[19];
    const float* ln1b   = (const float*)d_in[20];
    const float* fw1    = (const float*)d_in[21];
    const float* fb1    = (const float*)d_in[22];
    const float* fw2    = (const float*)d_in[23];
    const float* fb2    = (const float*)d_in[24];
    const float* ln2g   = (const float*)d_in[25];
    const float* ln2b   = (const float*)d_in[26];
    float* out = (float*)d_out;

    float *qkv,*attn,*xz,*u,*xdbc,*dlt,*mmb,*h;
    cudaGetSymbolAddress((void**)&qkv,  g_qkv);
    cudaGetSymbolAddress((void**)&attn, g_attn);
    cudaGetSymbolAddress((void**)&xz,   g_xz);
    cudaGetSymbolAddress((void**)&u,    g_u);
    cudaGetSymbolAddress((void**)&xdbc, g_xdbc);
    cudaGetSymbolAddress((void**)&dlt,  g_dlt);
    cudaGetSymbolAddress((void**)&mmb,  g_mmb);
    cudaGetSymbolAddress((void**)&h,    g_h);

    bf16 *px2,*pao2,*pu2,*pxdbc2,*py2,*phn2,*pff12;
    bf16 *pwqkv,*pwo,*pwin,*pwxp,*pwdt,*pwout,*pwf1,*pwf2;
    cudaGetSymbolAddress((void**)&px2,   gx2);
    cudaGetSymbolAddress((void**)&pao2,  gao2);
    cudaGetSymbolAddress((void**)&pu2,   gu2);
    cudaGetSymbolAddress((void**)&pxdbc2,gxdbc2);
    cudaGetSymbolAddress((void**)&py2,   gy2);
    cudaGetSymbolAddress((void**)&phn2,  ghn2);
    cudaGetSymbolAddress((void**)&pff12, gff12);
    cudaGetSymbolAddress((void**)&pwqkv, wqkv2);
    cudaGetSymbolAddress((void**)&pwo,   wo2);
    cudaGetSymbolAddress((void**)&pwin,  win2);
    cudaGetSymbolAddress((void**)&pwxp,  wxp2);
    cudaGetSymbolAddress((void**)&pwdt,  wdt2);
    cudaGetSymbolAddress((void**)&pwout, wout2);
    cudaGetSymbolAddress((void**)&pwf1,  wff12);
    cudaGetSymbolAddress((void**)&pwf2,  wff22);

    cudaFuncSetAttribute(flash_mma, cudaFuncAttributeMaxDynamicSharedMemorySize, FLASH_SMEM);
    cudaFuncSetAttribute(hmma_gemm<0,false,64>, cudaFuncAttributeMaxDynamicSharedMemorySize, GEMM_SMEM64);
    cudaFuncSetAttribute(hmma_gemm<1,false,64>, cudaFuncAttributeMaxDynamicSharedMemorySize, GEMM_SMEM64);
    cudaFuncSetAttribute(hmma_gemm<3,true,64>,  cudaFuncAttributeMaxDynamicSharedMemorySize, GEMM_SMEM64);
    cudaFuncSetAttribute(hmma_gemm<4,false,64>, cudaFuncAttributeMaxDynamicSharedMemorySize, GEMM_SMEM64);
    cudaFuncSetAttribute(hmma_gemm<5,false,64>, cudaFuncAttributeMaxDynamicSharedMemorySize, GEMM_SMEM64);
    cudaFuncSetAttribute(hmma_gemm<2,false,32>, cudaFuncAttributeMaxDynamicSharedMemorySize, GEMM_SMEM32);

    // ---- fused weight-split table ----
    WTab tab;
    long base = 0;
    auto add = [&](int i, const float* src, bf16* dst, int K, long rows){
        tab.e[i] = {src, dst, K, rows, base};
        base += rows * (K >> 2);
    };
    add(0, Wq,      pwqkv,               512,  512);
    add(1, Wk,      pwqkv + 512 * 1024,  512,  512);
    add(2, Wv,      pwqkv + 1024 * 1024, 512,  512);
    add(3, Wo,      pwo,                 512,  512);
    add(4, in_w,    pwin,                512,  2048);
    add(5, xproj_w, pwxp,                1024, 160);
    add(6, dt_w,    pwdt,                32,   1024);
    add(7, outp_w,  pwout,               1024, 512);
    add(8, fw1,     pwf1,                512,  2048);
    add(9, fw2,     pwf2,                2048, 512);
    const int wgrid = (int)((base + 255) / 256);

    cudaStream_t s0 = 0, sB = g_sh.sB;

    // slot 0, 1
    split2_wgt_all<<<wgrid, 256, 0, s0>>>(tab);
    split2<<<sgrid2(cM, 512), 256, 0, s0>>>(x, 512, 512, px2, cM);

    cudaEventRecord(g_sh.evRoot, s0);
    cudaStreamWaitEvent(sB, g_sh.evRoot, 0);

    // slot 2: fused QKV GEMM (tri-bias)
    hmma_gemm<5,false,64><<<dim3(12, 72), 512, GEMM_SMEM64, s0>>>(px2, pwqkv, 512, bq, bk, bv, nullptr, qkv, nullptr, 1536);
    // slot 3: in_proj GEMM (ncu target, BK=64)
    hmma_gemm<0,false,64><<<dim3(16, 72), 512, GEMM_SMEM64, sB>>>(px2, pwin, 512, nullptr, nullptr, nullptr, nullptr, xz, nullptr, 2048);
    // flash attention on s0
    flash_mma<<<dim3(cL / 128, cB * 8), 256, FLASH_SMEM, s0>>>(qkv, mask, pao2);
    conv_silu<<<(cM * 256) / 256, 256, 0, sB>>>(xz, conv_w, conv_b, u, pu2);
    hmma_gemm<1,false,64><<<dim3(4, 72), 512, GEMM_SMEM64, s0>>>(pao2, pwo, 512, bo, nullptr, nullptr, nullptr, attn, nullptr, 512);
    hmma_gemm<0,false,64><<<dim3(2, 72), 512, GEMM_SMEM64, sB>>>(pu2, pwxp, 1024, nullptr, nullptr, nullptr, nullptr, xdbc, nullptr, 160);
    split2<<<sgrid2(cM, 32), 256, 0, sB>>>(xdbc, 160, 32, pxdbc2, cM);
    hmma_gemm<2,false,32><<<dim3(8, 72), 512, GEMM_SMEM32, sB>>>(pxdbc2, pwdt, 32, dt_b, nullptr, nullptr, nullptr, dlt, nullptr, 1024);
    mamba_scan<<<dim3(cDI / 16, cB), 256, 0, sB>>>(dlt, u, xdbc, xz, A_log, Dssm, py2);
    hmma_gemm<0,false,64><<<dim3(4, 72), 512, GEMM_SMEM64, sB>>>(py2, pwout, 1024, nullptr, nullptr, nullptr, nullptr, mmb, nullptr, 512);
    cudaEventRecord(g_sh.evB, sB);

    cudaStreamWaitEvent(s0, g_sh.evB, 0);
    ln_fuse<<<cM, 256, 0, s0>>>(x, attn, mmb, ln1g, ln1b, ln2g, ln2b, h, phn2);
    hmma_gemm<3,true,64><<<dim3(16, 72), 512, GEMM_SMEM64, s0>>>(phn2, pwf1, 512, fb1, nullptr, nullptr, nullptr, nullptr, pff12, 2048);
    hmma_gemm<4,false,64><<<dim3(4, 72), 512, GEMM_SMEM64, s0>>>(pff12, pwf2, 2048, fb2, nullptr, nullptr, h, out, nullptr, 512);
}